// round 12
// baseline (speedup 1.0000x reference)
#include <cuda_runtime.h>
#include <cuda_bf16.h>
#include <math.h>
#include <stdint.h>

#define N_ 4096
#define C_ 512
#define H_ 128
#define T_ 64
#define D_ 20
#define G3 384

typedef unsigned long long u64;

// ------------------------- f32x2 helpers -------------------------
__device__ __forceinline__ u64 pack2_(float x) {
    u64 r; asm("mov.b64 %0, {%1, %2};" : "=l"(r) : "f"(x), "f"(x)); return r;
}
__device__ __forceinline__ void fma2_(u64& d, u64 a, u64 b) {
    asm("fma.rn.f32x2 %0, %1, %2, %0;" : "+l"(d) : "l"(a), "l"(b));
}
__device__ __forceinline__ void unpack2_(u64 v, float& lo, float& hi) {
    asm("mov.b64 {%0, %1}, %2;" : "=f"(lo), "=f"(hi) : "l"(v));
}

// fast activations
__device__ __forceinline__ float fsig_(float x) {
    float e, r;
    asm("ex2.approx.f32 %0, %1;" : "=f"(e) : "f"(-1.4426950408889634f * x));
    asm("rcp.approx.f32 %0, %1;" : "=f"(r) : "f"(1.f + e));
    return r;
}
__device__ __forceinline__ float ftanh_(float x) {
    float e, r;
    asm("ex2.approx.f32 %0, %1;" : "=f"(e) : "f"(2.8853900817779268f * x));
    asm("rcp.approx.f32 %0, %1;" : "=f"(r) : "f"(1.f + e));
    return fmaf(-2.f, r, 1.f);
}

// ------------------------- mma.sync helpers -------------------------
__device__ __forceinline__ uint32_t smem_u32_(const void* p) {
    uint32_t a;
    asm("{ .reg .u64 t; cvta.to.shared.u64 t, %1; cvt.u32.u64 %0, t; }" : "=r"(a) : "l"(p));
    return a;
}
__device__ __forceinline__ void ldsm4_(uint32_t* r, uint32_t a) {
    asm volatile("ldmatrix.sync.aligned.m8n8.x4.shared.b16 {%0,%1,%2,%3}, [%4];"
                 : "=r"(r[0]), "=r"(r[1]), "=r"(r[2]), "=r"(r[3]) : "r"(a));
}
__device__ __forceinline__ void ldsm2_(uint32_t* r, uint32_t a) {
    asm volatile("ldmatrix.sync.aligned.m8n8.x2.shared.b16 {%0,%1}, [%2];"
                 : "=r"(r[0]), "=r"(r[1]) : "r"(a));
}
__device__ __forceinline__ void mma_bf16_(float* d, const uint32_t* a, const uint32_t* b) {
    asm volatile(
        "mma.sync.aligned.m16n8k16.row.col.f32.bf16.bf16.f32 "
        "{%0,%1,%2,%3}, {%4,%5,%6,%7}, {%8,%9}, {%0,%1,%2,%3};"
        : "+f"(d[0]), "+f"(d[1]), "+f"(d[2]), "+f"(d[3])
        : "r"(a[0]), "r"(a[1]), "r"(a[2]), "r"(a[3]), "r"(b[0]), "r"(b[1]));
}

// ------------------------- scratch (device globals) -------------------------
__device__ float g_gx[(size_t)T_ * N_ * G3];
__device__ __nv_bfloat16 g_out0hi[(size_t)T_ * N_ * H_];
__device__ __nv_bfloat16 g_out0lo[(size_t)T_ * N_ * H_];
__device__ float g_xh[N_ * H_];
__device__ float g_den[C_];
__device__ float g_s2c[(size_t)N_ * C_];
__device__ float g_hidC[C_ * H_];
__device__ float g_v1[C_];
__device__ float g_logits[(size_t)C_ * N_];
__device__ float g_hid2[C_ * H_];
__device__ float g_nx[N_];
__device__ float g_ny[C_];
__device__ float g_c2s[(size_t)N_ * C_];
__device__ float g_tmp[N_ * H_];
__device__ float g_ps[N_ * H_];
__device__ float g_hsh[N_ * H_];
__device__ float g_outps[N_ * H_];
__device__ float g_nh[N_];
__device__ float g_diag[N_];
__device__ float g_big[(size_t)N_ * N_];
__device__ float g_part[32 * N_];
__device__ float g_kpart[(size_t)32 * 4096 * H_];
__device__ int   g_colcnt[N_];
__device__ int   g_kidx[N_ * 10];
__device__ float g_kval[N_ * 10];
__device__ long long g_hacc[N_ * H_];
__device__ float g_hidH[N_ * H_];
__device__ float g_v2[N_];
__device__ float g_nhh[N_];
__device__ float g_hsi[N_ * H_];
__device__ float g_indi[N_ * H_];
__device__ float g_ouths[N_ * H_];
__device__ float g_outindi[N_ * H_];

// ==================== HMMA GRU layer (1024 thr, 32 warps) ====================
// Warp wp: mg = wp>>4 selects row half (0-15 / 16-31); jb = (wp&15)*8 selects
// 8 hidden cols (same for all 3 gates). Per warp per step: 72 MMAs.
#define GRU_W_BYTES 98304
#define GRU_HB_STRIDE 136
#define GRU_HB_BYTES (32 * GRU_HB_STRIDE * 2)
#define GRU_SMEM (2 * GRU_W_BYTES + 4 * GRU_HB_BYTES)

__global__ __launch_bounds__(1024, 1) void gru_mma(
    const float* __restrict__ gx, const float* __restrict__ whh,
    const float* __restrict__ bhh, float* __restrict__ outF,
    __nv_bfloat16* __restrict__ outHi, __nv_bfloat16* __restrict__ outLo,
    int write_all)
{
    extern __shared__ __align__(16) char gsm[];
    char* Wlo = gsm + GRU_W_BYTES;
    char* Hbase = gsm + 2 * GRU_W_BYTES;
    const int tid = threadIdx.x, lane = tid & 31, wp = tid >> 5;
    const int n0 = blockIdx.x * 32;
    const int mg = wp >> 4;
    const int jb = (wp & 15) * 8;

    for (int idx = tid; idx < 384 * 16; idx += 1024) {
        int n = idx >> 4, g8 = idx & 15;
        const float* src = whh + n * 128 + g8 * 8;
        float4 v0 = *(const float4*)src;
        float4 v1 = *(const float4*)(src + 4);
        float f[8] = {v0.x, v0.y, v0.z, v0.w, v1.x, v1.y, v1.z, v1.w};
        uint32_t hw[4], lw[4];
#pragma unroll
        for (int q = 0; q < 4; ++q) {
            __nv_bfloat16 h0 = __float2bfloat16(f[2 * q]);
            __nv_bfloat16 h1 = __float2bfloat16(f[2 * q + 1]);
            __nv_bfloat162 hp = __halves2bfloat162(h0, h1);
            __nv_bfloat162 lp = __halves2bfloat162(
                __float2bfloat16(f[2 * q] - __bfloat162float(h0)),
                __float2bfloat16(f[2 * q + 1] - __bfloat162float(h1)));
            hw[q] = *(uint32_t*)&hp;
            lw[q] = *(uint32_t*)&lp;
        }
        int off = n * 256 + ((g8 ^ (n & 7)) << 4);
        *(uint4*)(gsm + off) = make_uint4(hw[0], hw[1], hw[2], hw[3]);
        *(uint4*)(Wlo + off) = make_uint4(lw[0], lw[1], lw[2], lw[3]);
    }
    for (int idx = tid; idx < (4 * GRU_HB_BYTES) / 4; idx += 1024)
        ((uint32_t*)Hbase)[idx] = 0;

    const int col0 = jb + 2 * (lane & 3);
    const int rbase = lane >> 2;
    float bR0 = bhh[col0], bR1 = bhh[col0 + 1];
    float bZ0 = bhh[128 + col0], bZ1 = bhh[128 + col0 + 1];
    float bN0 = bhh[256 + col0], bN1 = bhh[256 + col0 + 1];

    const uint32_t sb = smem_u32_(gsm);
    const uint32_t hB = sb + 2 * GRU_W_BYTES;
    const uint32_t aoff = (uint32_t)((lane & 15) * (GRU_HB_STRIDE * 2) + (lane >> 4) * 16
                                     + mg * 16 * (GRU_HB_STRIDE * 2));
    const int nRZ = ((lane >> 4) ? 128 + jb : jb) + (lane & 7);
    const uint32_t bRZ_base = sb + nRZ * 256;
    const uint32_t nlowRZ = (uint32_t)(nRZ & 7);
    const int nN = 256 + jb + (lane & 7);
    const uint32_t bN_base = sb + nN * 256;
    const uint32_t nlowN = (uint32_t)(nN & 7);
    const uint32_t ghalf = (uint32_t)((lane >> 3) & 1);

    float hold[2][2];
    hold[0][0] = hold[0][1] = hold[1][0] = hold[1][1] = 0.f;

    __syncthreads();

    for (int t = 0; t < T_; ++t) {
        const int rb = t & 1;
        const uint32_t aHi = hB + (uint32_t)(rb * 2 * GRU_HB_BYTES);
        const uint32_t aLo = aHi + GRU_HB_BYTES;
        __nv_bfloat16* Whi_w = (__nv_bfloat16*)(Hbase + (rb ^ 1) * 2 * GRU_HB_BYTES);
        __nv_bfloat16* Wlo_w = (__nv_bfloat16*)((char*)Whi_w + GRU_HB_BYTES);

        const float* gbase = gx + ((size_t)t * N_ + n0) * G3;
        float2 gR[2], gZ[2], gN[2];
#pragma unroll
        for (int r8 = 0; r8 < 2; ++r8) {
            int row = mg * 16 + r8 * 8 + rbase;
            const float* gp = gbase + row * G3 + col0;
            gR[r8] = *(const float2*)(gp);
            gZ[r8] = *(const float2*)(gp + 128);
            gN[r8] = *(const float2*)(gp + 256);
        }

        float acc[3][4];
#pragma unroll
        for (int g = 0; g < 3; ++g)
#pragma unroll
            for (int q = 0; q < 4; ++q) acc[g][q] = 0.f;

#pragma unroll 2
        for (int kc = 0; kc < 8; ++kc) {
            uint32_t gsw = (uint32_t)(kc * 2);
            uint32_t addrRZ = bRZ_base + (((gsw + ghalf) ^ nlowRZ) << 4);
            uint32_t addrN = bN_base + (((gsw + ghalf) ^ nlowN) << 4);
            uint32_t bhiRZ[4], bloRZ[4], bhiN[2], bloN[2];
            ldsm4_(bhiRZ, addrRZ);
            ldsm4_(bloRZ, addrRZ + GRU_W_BYTES);
            ldsm2_(bhiN, addrN);
            ldsm2_(bloN, addrN + GRU_W_BYTES);
            uint32_t ahi[4], alo[4];
            uint32_t aa = aoff + (uint32_t)(kc * 32);
            ldsm4_(ahi, aHi + aa);
            ldsm4_(alo, aLo + aa);
            mma_bf16_(acc[0], ahi, bhiRZ);
            mma_bf16_(acc[0], alo, bhiRZ);
            mma_bf16_(acc[0], ahi, bloRZ);
            mma_bf16_(acc[1], ahi, bhiRZ + 2);
            mma_bf16_(acc[1], alo, bhiRZ + 2);
            mma_bf16_(acc[1], ahi, bloRZ + 2);
            mma_bf16_(acc[2], ahi, bhiN);
            mma_bf16_(acc[2], alo, bhiN);
            mma_bf16_(acc[2], ahi, bloN);
        }

#pragma unroll
        for (int r8 = 0; r8 < 2; ++r8) {
            int q0 = r8 * 2;
            int row = mg * 16 + r8 * 8 + rbase;
            float rr0 = fsig_(gR[r8].x + acc[0][q0] + bR0);
            float rr1 = fsig_(gR[r8].y + acc[0][q0 + 1] + bR1);
            float zz0 = fsig_(gZ[r8].x + acc[1][q0] + bZ0);
            float zz1 = fsig_(gZ[r8].y + acc[1][q0 + 1] + bZ1);
            float nc0 = ftanh_(gN[r8].x + rr0 * (acc[2][q0] + bN0));
            float nc1 = ftanh_(gN[r8].y + rr1 * (acc[2][q0 + 1] + bN1));
            float h0 = (1.f - zz0) * nc0 + zz0 * hold[r8][0];
            float h1 = (1.f - zz1) * nc1 + zz1 * hold[r8][1];
            hold[r8][0] = h0; hold[r8][1] = h1;
            __nv_bfloat16 hh0 = __float2bfloat16(h0);
            __nv_bfloat16 hh1 = __float2bfloat16(h1);
            __nv_bfloat162 hp = __halves2bfloat162(hh0, hh1);
            __nv_bfloat162 lp = __halves2bfloat162(
                __float2bfloat16(h0 - __bfloat162float(hh0)),
                __float2bfloat16(h1 - __bfloat162float(hh1)));
            *(__nv_bfloat162*)&Whi_w[row * GRU_HB_STRIDE + col0] = hp;
            *(__nv_bfloat162*)&Wlo_w[row * GRU_HB_STRIDE + col0] = lp;
            if (write_all) {
                size_t gb = ((size_t)t * N_ + n0 + row) * H_ + col0;
                *(__nv_bfloat162*)&outHi[gb] = hp;
                *(__nv_bfloat162*)&outLo[gb] = lp;
            }
        }
        __syncthreads();
    }
    if (!write_all) {
#pragma unroll
        for (int r8 = 0; r8 < 2; ++r8) {
            int row = mg * 16 + r8 * 8 + rbase;
            *(float2*)&outF[(size_t)(n0 + row) * H_ + col0] =
                make_float2(hold[r8][0], hold[r8][1]);
        }
    }
}

// ==================== mma.sync bf16-split NT GEMM (K=128), 128x128 tile ====================
#define MM_PAD 136
#define MM_TILE_BYTES (128 * MM_PAD * 2)
#define MM_SMEM (4 * MM_TILE_BYTES)

__device__ __forceinline__ void cvt_split_(float4 v, uint2& hw, uint2& lw) {
    __nv_bfloat16 h0 = __float2bfloat16(v.x), h1 = __float2bfloat16(v.y);
    __nv_bfloat16 h2 = __float2bfloat16(v.z), h3 = __float2bfloat16(v.w);
    __nv_bfloat162 hp0 = __halves2bfloat162(h0, h1);
    __nv_bfloat162 hp1 = __halves2bfloat162(h2, h3);
    __nv_bfloat162 lp0 = __halves2bfloat162(
        __float2bfloat16(v.x - __bfloat162float(h0)),
        __float2bfloat16(v.y - __bfloat162float(h1)));
    __nv_bfloat162 lp1 = __halves2bfloat162(
        __float2bfloat16(v.z - __bfloat162float(h2)),
        __float2bfloat16(v.w - __bfloat162float(h3)));
    hw.x = *(uint32_t*)&hp0; hw.y = *(uint32_t*)&hp1;
    lw.x = *(uint32_t*)&lp0; lw.y = *(uint32_t*)&lp1;
}

template <int EPI>
__device__ __forceinline__ float mepi_(float v, int row, int col,
                                       const float* e1, const float* e2)
{
    if (EPI == 1) v += e1[col];
    if (EPI == 4) {
        v = v / fmaxf(e1[row] * e2[col], 1e-12f);
        if (row == col) v = 0.f;
    }
    return v;
}

// shared mainloop+epilogue (A/B tiles already staged in smem)
template <int EPI>
__device__ __forceinline__ void mm_core_(char* msm, float* __restrict__ Cm,
                                         int bm, int bn, int Nn,
                                         const float* e1, const float* e2)
{
    const int tid = threadIdx.x, lane = tid & 31, wid = tid >> 5;
    const uint32_t sb = smem_u32_(msm);
    const int m0 = (wid >> 2) * 64, n0 = (wid & 3) * 32;
    const uint32_t aRow = (uint32_t)((m0 + (lane & 15)) * MM_PAD * 2 + (lane >> 4) * 16);
    const uint32_t bRow = (uint32_t)((n0 + (lane & 7)) * MM_PAD * 2 + ((lane >> 3) & 1) * 16);

    float acc[4][4][4];
#pragma unroll
    for (int i = 0; i < 4; ++i)
#pragma unroll
        for (int j = 0; j < 4; ++j)
#pragma unroll
            for (int q = 0; q < 4; ++q) acc[i][j][q] = 0.f;

#pragma unroll
    for (int p = 0; p < 3; ++p) {
        const uint32_t aB = sb + (p == 1 ? MM_TILE_BYTES : 0) + aRow;
        const uint32_t bB = sb + 2 * MM_TILE_BYTES + (p == 2 ? MM_TILE_BYTES : 0) + bRow;
#pragma unroll
        for (int k0 = 0; k0 < 128; k0 += 16) {
            uint32_t af[4][4], bf[4][2];
#pragma unroll
            for (int i = 0; i < 4; ++i) ldsm4_(af[i], aB + i * 16 * MM_PAD * 2 + k0 * 2);
#pragma unroll
            for (int j = 0; j < 4; ++j) ldsm2_(bf[j], bB + j * 8 * MM_PAD * 2 + k0 * 2);
#pragma unroll
            for (int i = 0; i < 4; ++i)
#pragma unroll
                for (int j = 0; j < 4; ++j) mma_bf16_(acc[i][j], af[i], bf[j]);
        }
    }

    const int tr = lane >> 2, tc = (lane & 3) * 2;
#pragma unroll
    for (int i = 0; i < 4; ++i) {
#pragma unroll
        for (int j = 0; j < 4; ++j) {
            int row = bm + m0 + i * 16 + tr;
            int col = bn + n0 + j * 8 + tc;
            float2 v0, v1;
            v0.x = mepi_<EPI>(acc[i][j][0], row, col, e1, e2);
            v0.y = mepi_<EPI>(acc[i][j][1], row, col + 1, e1, e2);
            v1.x = mepi_<EPI>(acc[i][j][2], row + 8, col, e1, e2);
            v1.y = mepi_<EPI>(acc[i][j][3], row + 8, col + 1, e1, e2);
            *(float2*)&Cm[(size_t)row * Nn + col] = v0;
            *(float2*)&Cm[(size_t)(row + 8) * Nn + col] = v1;
        }
    }
}

template <int EPI>
__global__ __launch_bounds__(256, 1) void mmagemm(
    const float* __restrict__ A, const float* __restrict__ B, float* __restrict__ Cm,
    int M, int Nn, const float* __restrict__ e1, const float* __restrict__ e2)
{
    extern __shared__ __align__(16) char msm[];
    __nv_bfloat16* Ah = (__nv_bfloat16*)msm;
    __nv_bfloat16* Al = (__nv_bfloat16*)(msm + MM_TILE_BYTES);
    __nv_bfloat16* Bh = (__nv_bfloat16*)(msm + 2 * MM_TILE_BYTES);
    __nv_bfloat16* Bl = (__nv_bfloat16*)(msm + 3 * MM_TILE_BYTES);
    const int tid = threadIdx.x;
    const int bm = blockIdx.y * 128, bn = blockIdx.x * 128;

    {
        const float* Ab = A + (size_t)bm * 128;
        const float* Bb = B + (size_t)bn * 128;
        for (int idx = tid; idx < 128 * 32; idx += 256) {
            int row = idx >> 5, q = (idx & 31) << 2;
            uint2 hw, lw;
            cvt_split_(*(const float4*)&Ab[row * 128 + q], hw, lw);
            *(uint2*)&Ah[row * MM_PAD + q] = hw;
            *(uint2*)&Al[row * MM_PAD + q] = lw;
            cvt_split_(*(const float4*)&Bb[row * 128 + q], hw, lw);
            *(uint2*)&Bh[row * MM_PAD + q] = hw;
            *(uint2*)&Bl[row * MM_PAD + q] = lw;
        }
    }
    __syncthreads();
    mm_core_<EPI>(msm, Cm, bm, bn, Nn, e1, e2);
}

// variant: A pre-split (bf16 hi/lo planes), B fp32
__global__ __launch_bounds__(256, 1) void mmagemm_pre(
    const __nv_bfloat16* __restrict__ Ahi_g, const __nv_bfloat16* __restrict__ Alo_g,
    const float* __restrict__ B, float* __restrict__ Cm,
    int M, int Nn, const float* __restrict__ e1)
{
    extern __shared__ __align__(16) char msm[];
    __nv_bfloat16* Ah = (__nv_bfloat16*)msm;
    __nv_bfloat16* Al = (__nv_bfloat16*)(msm + MM_TILE_BYTES);
    __nv_bfloat16* Bh = (__nv_bfloat16*)(msm + 2 * MM_TILE_BYTES);
    __nv_bfloat16* Bl = (__nv_bfloat16*)(msm + 3 * MM_TILE_BYTES);
    const int tid = threadIdx.x;
    const int bm = blockIdx.y * 128, bn = blockIdx.x * 128;

    // copy pre-split A (128 rows x 16 uint4)
    for (int idx = tid; idx < 128 * 16; idx += 256) {
        int row = idx >> 4, q = (idx & 15) << 3;
        *(uint4*)&Ah[row * MM_PAD + q] = *(const uint4*)&Ahi_g[((size_t)bm + row) * 128 + q];
        *(uint4*)&Al[row * MM_PAD + q] = *(const uint4*)&Alo_g[((size_t)bm + row) * 128 + q];
    }
    // convert B
    {
        const float* Bb = B + (size_t)bn * 128;
        for (int idx = tid; idx < 128 * 32; idx += 256) {
            int row = idx >> 5, q = (idx & 31) << 2;
            uint2 hw, lw;
            cvt_split_(*(const float4*)&Bb[row * 128 + q], hw, lw);
            *(uint2*)&Bh[row * MM_PAD + q] = hw;
            *(uint2*)&Bl[row * MM_PAD + q] = lw;
        }
    }
    __syncthreads();
    mm_core_<1>(msm, Cm, bm, bn, Nn, e1, nullptr);
}

// ------------------------- gx0 -------------------------
__global__ void gx0_kernel(const float* __restrict__ x, const float* __restrict__ wih,
                           const float* __restrict__ bih, float* __restrict__ gx)
{
    __shared__ float xs[32 * D_];
    const int t = blockIdx.x;
    const int n0 = blockIdx.y * 32;
    const int g = threadIdx.x;
    for (int idx = g; idx < 32 * D_; idx += G3) {
        int r = idx / D_, d = idx - r * D_;
        xs[idx] = x[(size_t)(n0 + r) * (D_ * T_) + d * T_ + t];
    }
    float wr[D_];
#pragma unroll
    for (int d = 0; d < D_; ++d) wr[d] = wih[g * D_ + d];
    const float b = bih[g];
    __syncthreads();
    for (int r = 0; r < 32; ++r) {
        const float4* xp = (const float4*)&xs[r * D_];
        float acc = b;
#pragma unroll
        for (int q = 0; q < 5; ++q) {
            float4 v = xp[q];
            acc += v.x * wr[q * 4 + 0] + v.y * wr[q * 4 + 1] +
                   v.z * wr[q * 4 + 2] + v.w * wr[q * 4 + 3];
        }
        gx[((size_t)t * N_ + n0 + r) * G3 + g] = acc;
    }
}

// ------------------------- 128x128 f32x2 SGEMM with split-K -------------------------
template <int EPI>
__device__ __forceinline__ float epi_apply(float v, int row, int col, int Nn,
                                           const float* e1, const float* e2)
{
    if (EPI == 1) v += e1[col];
    if (EPI == 2) { v += e1[col]; v = v > 0.f ? v : 0.01f * v; }
    if (EPI == 3) { v += e1[col]; v = e2[(size_t)row * Nn + col] - v; }
    return v;
}

template <int TR, int EPI>
__global__ __launch_bounds__(256, 2) void sgemm128(
    const float* __restrict__ A, const float* __restrict__ B, float* __restrict__ Cm,
    int M, int Nn, int K, int Ksplit,
    const float* __restrict__ e1, const float* __restrict__ e2,
    float* __restrict__ part)
{
    __shared__ __align__(16) float As[16][136];
    __shared__ __align__(16) float Bs[16][136];
    const int bm = blockIdx.y * 128, bn = blockIdx.x * 128;
    const int z = blockIdx.z;
    const int kb = z * Ksplit, ke = kb + Ksplit;
    const int tid = threadIdx.x;
    const int tx = tid & 15, ty = tid >> 4;
    u64 acc[4][8];
#pragma unroll
    for (int i = 0; i < 4; ++i)
#pragma unroll
        for (int j = 0; j < 8; ++j) acc[i][j] = 0ull;

    for (int k0 = kb; k0 < ke; k0 += 16) {
        if (TR == 2) {
            int k = tid >> 4, m = (tid & 15) << 3;
            const float* src = &A[(size_t)(k0 + k) * M + bm + m];
            *(float4*)&As[k][m]     = *(const float4*)(src);
            *(float4*)&As[k][m + 4] = *(const float4*)(src + 4);
        } else {
            int m = tid >> 1, kq = (tid & 1) << 3;
            const float* src = &A[(size_t)(bm + m) * K + k0 + kq];
            float4 v0 = *(const float4*)(src);
            float4 v1 = *(const float4*)(src + 4);
            As[kq + 0][m] = v0.x; As[kq + 1][m] = v0.y;
            As[kq + 2][m] = v0.z; As[kq + 3][m] = v0.w;
            As[kq + 4][m] = v1.x; As[kq + 5][m] = v1.y;
            As[kq + 6][m] = v1.z; As[kq + 7][m] = v1.w;
        }
        if (TR == 1) {
            int n = tid >> 1, kq = (tid & 1) << 3;
            const float* src = &B[(size_t)(bn + n) * K + k0 + kq];
            float4 v0 = *(const float4*)(src);
            float4 v1 = *(const float4*)(src + 4);
            Bs[kq + 0][n] = v0.x; Bs[kq + 1][n] = v0.y;
            Bs[kq + 2][n] = v0.z; Bs[kq + 3][n] = v0.w;
            Bs[kq + 4][n] = v1.x; Bs[kq + 5][n] = v1.y;
            Bs[kq + 6][n] = v1.z; Bs[kq + 7][n] = v1.w;
        } else {
            int k = tid >> 4, n = (tid & 15) << 3;
            const float* src = &B[(size_t)(k0 + k) * Nn + bn + n];
            *(float4*)&Bs[k][n]     = *(const float4*)(src);
            *(float4*)&Bs[k][n + 4] = *(const float4*)(src + 4);
        }
        __syncthreads();
#pragma unroll
        for (int kk = 0; kk < 16; ++kk) {
            ulonglong2 a01 = *(const ulonglong2*)&As[kk][ty << 3];
            ulonglong2 a23 = *(const ulonglong2*)&As[kk][(ty << 3) + 4];
            float4 b0 = *(const float4*)&Bs[kk][tx << 2];
            float4 b1 = *(const float4*)&Bs[kk][64 + (tx << 2)];
            u64 ar[4] = {a01.x, a01.y, a23.x, a23.y};
            u64 bd[8];
            bd[0] = pack2_(b0.x); bd[1] = pack2_(b0.y);
            bd[2] = pack2_(b0.z); bd[3] = pack2_(b0.w);
            bd[4] = pack2_(b1.x); bd[5] = pack2_(b1.y);
            bd[6] = pack2_(b1.z); bd[7] = pack2_(b1.w);
#pragma unroll
            for (int rp = 0; rp < 4; ++rp)
#pragma unroll
                for (int c = 0; c < 8; ++c) fma2_(acc[rp][c], ar[rp], bd[c]);
        }
        __syncthreads();
    }

    const bool partial = (gridDim.z > 1);
    float* obase = partial ? part + (size_t)z * M * Nn : Cm;
#pragma unroll
    for (int rp = 0; rp < 4; ++rp) {
        float lo[8], hi[8];
#pragma unroll
        for (int c = 0; c < 8; ++c) unpack2_(acc[rp][c], lo[c], hi[c]);
        int row0 = bm + (ty << 3) + rp * 2;
#pragma unroll
        for (int h = 0; h < 2; ++h) {
            int row = row0 + h;
            float* vv = h ? hi : lo;
            int colA = bn + (tx << 2);
            int colB = bn + 64 + (tx << 2);
            float4 oA, oB;
            if (!partial) {
                oA.x = epi_apply<EPI>(vv[0], row, colA + 0, Nn, e1, e2);
                oA.y = epi_apply<EPI>(vv[1], row, colA + 1, Nn, e1, e2);
                oA.z = epi_apply<EPI>(vv[2], row, colA + 2, Nn, e1, e2);
                oA.w = epi_apply<EPI>(vv[3], row, colA + 3, Nn, e1, e2);
                oB.x = epi_apply<EPI>(vv[4], row, colB + 0, Nn, e1, e2);
                oB.y = epi_apply<EPI>(vv[5], row, colB + 1, Nn, e1, e2);
                oB.z = epi_apply<EPI>(vv[6], row, colB + 2, Nn, e1, e2);
                oB.w = epi_apply<EPI>(vv[7], row, colB + 3, Nn, e1, e2);
            } else {
                oA = make_float4(vv[0], vv[1], vv[2], vv[3]);
                oB = make_float4(vv[4], vv[5], vv[6], vv[7]);
            }
            *(float4*)&obase[(size_t)row * Nn + colA] = oA;
            *(float4*)&obase[(size_t)row * Nn + colB] = oB;
        }
    }
}

__global__ void kreduce(const float* __restrict__ part, int S, size_t MN,
                        float* __restrict__ out)
{
    size_t i4 = ((size_t)blockIdx.x * 256 + threadIdx.x) * 4;
    if (i4 >= MN) return;
    float4 s = *(const float4*)&part[i4];
    for (int z = 1; z < S; ++z) {
        float4 v = *(const float4*)&part[(size_t)z * MN + i4];
        s.x += v.x; s.y += v.y; s.z += v.z; s.w += v.w;
    }
    *(float4*)&out[i4] = s;
}

// ------------------------- reductions / elementwise -------------------------
__global__ void colsum_part(const float* __restrict__ m, const float* __restrict__ w,
                            int rows, int cols, float* __restrict__ part)
{
    int c = blockIdx.x * 256 + threadIdx.x;
    int chunk = rows / gridDim.y;
    int r0 = blockIdx.y * chunk;
    float acc = 0.f;
    for (int r = r0; r < r0 + chunk; ++r)
        acc += m[(size_t)r * cols + c] * (w ? w[r] : 1.f);
    part[(size_t)blockIdx.y * cols + c] = acc;
}
__global__ void colsum_reduce(const float* __restrict__ part, int nb, int cols,
                              float* __restrict__ out)
{
    int c = blockIdx.x * 256 + threadIdx.x;
    float a = 0.f;
    for (int b = 0; b < nb; ++b) a += part[(size_t)b * cols + c];
    out[c] = a;
}

__global__ void s2c_kernel(const float* __restrict__ cm, const float* __restrict__ mv,
                           const float* __restrict__ den, float* __restrict__ s2c)
{
    int e = blockIdx.x * 256 + threadIdx.x;
    if (e >= N_ * C_) return;
    int i = e >> 9, c = e & (C_ - 1);
    float cv = cm[e];
    s2c[e] = cv * mv[i] / (den[c] * cv + 1.f);
}

__global__ void rownorm(const float* __restrict__ x, int cols,
                        float* __restrict__ nrm, float* __restrict__ vflag,
                        float* __restrict__ dg)
{
    int row = blockIdx.x * 8 + (threadIdx.x >> 5);
    int lane = threadIdx.x & 31;
    const float* p = x + (size_t)row * cols;
    float s = 0.f, q = 0.f;
    for (int c = lane; c < cols; c += 32) { float v = p[c]; s += v; q += v * v; }
#pragma unroll
    for (int o = 16; o; o >>= 1) {
        s += __shfl_xor_sync(0xffffffffu, s, o);
        q += __shfl_xor_sync(0xffffffffu, q, o);
    }
    if (lane == 0) {
        if (nrm) nrm[row] = sqrtf(q);
        if (vflag) vflag[row] = (s != 0.f) ? 1.f : 0.f;
        if (dg) { float d = sqrtf(q) * sqrtf(q); dg[row] = q / fmaxf(d, 1e-12f); }
    }
}

// 512-thread row softmax
__global__ __launch_bounds__(512, 1) void row_softmax(
    float* __restrict__ m, int width,
    const float* __restrict__ rs, const float* __restrict__ cs,
    const float* __restrict__ vm)
{
    extern __shared__ float sv[];
    __shared__ float red[16];
    __shared__ float smx, ssum;
    const int tid = threadIdx.x, lane = tid & 31, wid = tid >> 5;
    const size_t base = (size_t)blockIdx.x * width;
    const float rsv = rs ? rs[blockIdx.x] : 0.f;
    float lmax = -3.0e38f;
    for (int j = tid; j < width; j += 512) {
        float v = m[base + j];
        if (rs) v = v / fmaxf(rsv * cs[j], 1e-12f);
        if (vm && vm[j] == 0.f) v = -3.0e38f;
        sv[j] = v;
        lmax = fmaxf(lmax, v);
    }
#pragma unroll
    for (int o = 16; o; o >>= 1) lmax = fmaxf(lmax, __shfl_xor_sync(0xffffffffu, lmax, o));
    if (lane == 0) red[wid] = lmax;
    __syncthreads();
    if (tid == 0) {
        float v = red[0];
        for (int w = 1; w < 16; ++w) v = fmaxf(v, red[w]);
        smx = v;
    }
    __syncthreads();
    const float mx = smx;
    float lsum = 0.f;
    for (int j = tid; j < width; j += 512) {
        float e = __expf(sv[j] - mx);
        sv[j] = e;
        lsum += e;
    }
#pragma unroll
    for (int o = 16; o; o >>= 1) lsum += __shfl_xor_sync(0xffffffffu, lsum, o);
    if (lane == 0) red[wid] = lsum;
    __syncthreads();
    if (tid == 0) {
        float v = 0.f;
        for (int w = 0; w < 16; ++w) v += red[w];
        ssum = v;
    }
    __syncthreads();
    const float inv = 1.f / ssum;
    for (int j = tid; j < width; j += 512) {
        float o = sv[j] * inv;
        if (vm) o = (vm[j] != 0.f) ? o : 0.f;
        m[base + j] = o;
    }
}

// ------------------------- top-10 store -------------------------
__global__ __launch_bounds__(512, 1) void topk_store(
    const float* __restrict__ m, int* __restrict__ colcnt,
    int* __restrict__ kidx, float* __restrict__ kval)
{
    __shared__ float vals[N_];
    __shared__ float cval[160];
    __shared__ int cidx[160];
    __shared__ int keep[10];
    __shared__ float keepv[10];
    const int tid = threadIdx.x, lane = tid & 31, wid = tid >> 5;
    const size_t base = (size_t)blockIdx.x * N_;

    for (int j = tid; j < N_; j += 512) vals[j] = m[base + j];
    __syncthreads();

    {
        const int cbase = wid * 256 + lane * 8;
        float v[8];
#pragma unroll
        for (int i = 0; i < 8; ++i) v[i] = vals[cbase + i];
        for (int s = 0; s < 10; ++s) {
            float bv = v[0]; int bs = 0;
#pragma unroll
            for (int i = 1; i < 8; ++i)
                if (v[i] > bv) { bv = v[i]; bs = i; }
            int bi = cbase + bs;
#pragma unroll
            for (int o = 16; o; o >>= 1) {
                float ov = __shfl_down_sync(0xffffffffu, bv, o);
                int oi = __shfl_down_sync(0xffffffffu, bi, o);
                if (ov > bv || (ov == bv && oi < bi)) { bv = ov; bi = oi; }
            }
            bv = __shfl_sync(0xffffffffu, bv, 0);
            bi = __shfl_sync(0xffffffffu, bi, 0);
            if (lane == 0) { cval[wid * 10 + s] = bv; cidx[wid * 10 + s] = bi; }
            if (bi >= cbase && bi < cbase + 8) v[bi - cbase] = -3.0e38f;
        }
    }
    __syncthreads();

    if (wid == 0) {
        float v[5]; int gi[5];
#pragma unroll
        for (int i = 0; i < 5; ++i) {
            v[i] = cval[lane * 5 + i];
            gi[i] = cidx[lane * 5 + i];
        }
        for (int s = 0; s < 10; ++s) {
            float bv = v[0]; int bi = gi[0], bs = 0;
#pragma unroll
            for (int i = 1; i < 5; ++i)
                if (v[i] > bv || (v[i] == bv && gi[i] < bi)) { bv = v[i]; bi = gi[i]; bs = i; }
            int slot = lane * 5 + bs;
#pragma unroll
            for (int o = 16; o; o >>= 1) {
                float ov = __shfl_down_sync(0xffffffffu, bv, o);
                int oi = __shfl_down_sync(0xffffffffu, bi, o);
                int os = __shfl_down_sync(0xffffffffu, slot, o);
                if (ov > bv || (ov == bv && oi < bi)) { bv = ov; bi = oi; slot = os; }
            }
            bv = __shfl_sync(0xffffffffu, bv, 0);
            bi = __shfl_sync(0xffffffffu, bi, 0);
            slot = __shfl_sync(0xffffffffu, slot, 0);
            if (lane == 0) { keep[s] = bi; keepv[s] = bv; }
            if (slot >= lane * 5 && slot < lane * 5 + 5) v[slot - lane * 5] = -3.0e38f;
        }
        if (lane < 10) {
            atomicAdd(&colcnt[keep[lane]], 1);
            kidx[blockIdx.x * 10 + lane] = keep[lane];
            kval[blockIdx.x * 10 + lane] = keepv[lane];
        }
    }
}

// ------------------------- sparse hidden_h -------------------------
#define FXSCALE 1099511627776.f
#define FXINV   (1.0 / 1099511627776.0)

__global__ void scatter_hidh(const int* __restrict__ kidx, const float* __restrict__ kval,
                             const float* __restrict__ hsh, long long* __restrict__ hacc)
{
    int gid = blockIdx.x * 256 + threadIdx.x;
    if (gid >= N_ * 10 * H_) return;
    int e = gid >> 7, h = gid & 127;
    int row = e / 10;
    int col = kidx[e];
    float prod = kval[e] * hsh[row * H_ + h];
    long long q = llrintf(prod * FXSCALE);
    atomicAdd((unsigned long long*)&hacc[(size_t)col * H_ + h], (unsigned long long)q);
}

__global__ void convert_hidh(const long long* __restrict__ hacc,
                             const int* __restrict__ cnt, const float* __restrict__ dg,
                             const float* __restrict__ hsh, float* __restrict__ hidH)
{
    int i = blockIdx.x * 256 + threadIdx.x;
    if (i >= N_ * H_) return;
    int c = i >> 7;
    float v = (float)((double)hacc[i] * FXINV);
    if (cnt[c] > 0) v += dg[c] * hsh[i];
    hidH[i] = v;
}

__global__ void final_head(const float* __restrict__ a, const float* __restrict__ b,
                           const float* __restrict__ c, const float* __restrict__ w,
                           const float* __restrict__ bo, float* __restrict__ out)
{
    int row = blockIdx.x * 8 + (threadIdx.x >> 5);
    int lane = threadIdx.x & 31;
    size_t base = (size_t)row * H_;
    float acc = 0.f;
    for (int h = lane; h < H_; h += 32)
        acc += (a[base + h] + b[base + h] + c[base + h]) * w[h];
#pragma unroll
    for (int o = 16; o; o >>= 1) acc += __shfl_xor_sync(0xffffffffu, acc, o);
    if (lane == 0) out[row] = acc + bo[0];
}

// ------------------------- host side -------------------------
static float* g_kpart_ptr;

static void gemm(int TR, int EPI, const float* A, const float* B, float* Cm,
                 int M, int Nn, int K, int S, const float* e1, const float* e2)
{
    dim3 g(Nn / 128, M / 128, S), blk(256);
    int Ks = K / S;
    if (S > 1) {
        if (TR == 0) sgemm128<0, 0><<<g, blk>>>(A, B, Cm, M, Nn, K, Ks, e1, e2, g_kpart_ptr);
        else if (TR == 1) sgemm128<1, 0><<<g, blk>>>(A, B, Cm, M, Nn, K, Ks, e1, e2, g_kpart_ptr);
        else sgemm128<2, 0><<<g, blk>>>(A, B, Cm, M, Nn, K, Ks, e1, e2, g_kpart_ptr);
        size_t MN = (size_t)M * Nn;
        kreduce<<<(int)((MN / 4 + 255) / 256), 256>>>(g_kpart_ptr, S, MN, Cm);
        return;
    }
    if (TR == 0) sgemm128<0, 0><<<g, blk>>>(A, B, Cm, M, Nn, K, Ks, e1, e2, nullptr);
    else if (TR == 2) sgemm128<2, 0><<<g, blk>>>(A, B, Cm, M, Nn, K, Ks, e1, e2, nullptr);
    else if (EPI == 0) sgemm128<1, 0><<<g, blk>>>(A, B, Cm, M, Nn, K, Ks, e1, e2, nullptr);
    else if (EPI == 1) sgemm128<1, 1><<<g, blk>>>(A, B, Cm, M, Nn, K, Ks, e1, e2, nullptr);
    else if (EPI == 2) sgemm128<1, 2><<<g, blk>>>(A, B, Cm, M, Nn, K, Ks, e1, e2, nullptr);
    else sgemm128<1, 3><<<g, blk>>>(A, B, Cm, M, Nn, K, Ks, e1, e2, nullptr);
}

static void mm_go(int EPI, const float* A, const float* B, float* Cm,
                  int M, int Nn, const float* e1, const float* e2)
{
    dim3 g(Nn / 128, M / 128);
    if (EPI == 0) mmagemm<0><<<g, 256, MM_SMEM>>>(A, B, Cm, M, Nn, e1, e2);
    else if (EPI == 1) mmagemm<1><<<g, 256, MM_SMEM>>>(A, B, Cm, M, Nn, e1, e2);
    else mmagemm<4><<<g, 256, MM_SMEM>>>(A, B, Cm, M, Nn, e1, e2);
}

template <typename Tp>
static float* symaddr(Tp& sym)
{
    void* p = nullptr;
    cudaGetSymbolAddress(&p, sym);
    return (float*)p;
}

extern "C" void kernel_launch(void* const* d_in, const int* in_sizes, int n_in,
                              void* d_out, int out_size)
{
    const float* x = (const float*)d_in[0];
    const float* cm = (const float*)d_in[1];
    const float* mv = (const float*)d_in[2];
    const float* wih0 = (const float*)d_in[3];
    const float* whh0 = (const float*)d_in[4];
    const float* bih0 = (const float*)d_in[5];
    const float* bhh0 = (const float*)d_in[6];
    const float* wih1 = (const float*)d_in[7];
    const float* whh1 = (const float*)d_in[8];
    const float* bih1 = (const float*)d_in[9];
    const float* bhh1 = (const float*)d_in[10];
    const float* w_ps = (const float*)d_in[11];
    const float* b_ps = (const float*)d_in[12];
    const float* w_hs = (const float*)d_in[13];
    const float* b_hs = (const float*)d_in[14];
    const float* w_ps_fore = (const float*)d_in[15];
    const float* b_ps_fore = (const float*)d_in[16];
    const float* w_hs_fore = (const float*)d_in[17];
    const float* b_hs_fore = (const float*)d_in[18];
    const float* w_ps_back = (const float*)d_in[19];
    const float* b_ps_back = (const float*)d_in[20];
    const float* w_hs_back = (const float*)d_in[21];
    const float* b_hs_back = (const float*)d_in[22];
    const float* w_indi = (const float*)d_in[23];
    const float* b_indi = (const float*)d_in[24];
    const float* w_out = (const float*)d_in[25];
    const float* b_out = (const float*)d_in[26];
    float* out = (float*)d_out;

    float* gx = symaddr(g_gx);
    __nv_bfloat16* out0hi = (__nv_bfloat16*)symaddr(g_out0hi);
    __nv_bfloat16* out0lo = (__nv_bfloat16*)symaddr(g_out0lo);
    float* xh = symaddr(g_xh);
    float* den = symaddr(g_den);
    float* s2c = symaddr(g_s2c);
    float* hidC = symaddr(g_hidC);
    float* v1 = symaddr(g_v1);
    float* logits = symaddr(g_logits);
    float* hid2 = symaddr(g_hid2);
    float* nx = symaddr(g_nx);
    float* ny = symaddr(g_ny);
    float* c2s = symaddr(g_c2s);
    float* tmp = symaddr(g_tmp);
    float* ps = symaddr(g_ps);
    float* hsh = symaddr(g_hsh);
    float* outps = symaddr(g_outps);
    float* nh = symaddr(g_nh);
    float* dg = symaddr(g_diag);
    float* big = symaddr(g_big);
    float* part = symaddr(g_part);
    int* colcnt = (int*)symaddr(g_colcnt);
    int* kidx = (int*)symaddr(g_kidx);
    float* kval = symaddr(g_kval);
    long long* hacc = (long long*)symaddr(g_hacc);
    float* hidH = symaddr(g_hidH);
    float* v2 = symaddr(g_v2);
    float* nhh = symaddr(g_nhh);
    float* hsi = symaddr(g_hsi);
    float* indi = symaddr(g_indi);
    float* ouths = symaddr(g_ouths);
    float* outindi = symaddr(g_outindi);
    g_kpart_ptr = symaddr(g_kpart);

    cudaFuncSetAttribute(gru_mma, cudaFuncAttributeMaxDynamicSharedMemorySize, GRU_SMEM);
    cudaFuncSetAttribute(mmagemm<0>, cudaFuncAttributeMaxDynamicSharedMemorySize, MM_SMEM);
    cudaFuncSetAttribute(mmagemm<1>, cudaFuncAttributeMaxDynamicSharedMemorySize, MM_SMEM);
    cudaFuncSetAttribute(mmagemm<4>, cudaFuncAttributeMaxDynamicSharedMemorySize, MM_SMEM);
    cudaFuncSetAttribute(mmagemm_pre, cudaFuncAttributeMaxDynamicSharedMemorySize, MM_SMEM);

    // ---- GRU ----
    gx0_kernel<<<dim3(T_, N_ / 32), G3>>>(x, wih0, bih0, gx);
    gru_mma<<<N_ / 32, 1024, GRU_SMEM>>>(gx, whh0, bhh0, nullptr, out0hi, out0lo, 1);
    {
        dim3 g(G3 / 128, (T_ * N_) / 128);
        mmagemm_pre<<<g, 256, MM_SMEM>>>(out0hi, out0lo, wih1, gx, T_ * N_, G3, bih1);
    }
    gru_mma<<<N_ / 32, 1024, GRU_SMEM>>>(gx, whh1, bhh1, xh, nullptr, nullptr, 0);

    // ---- predefined-concept branch ----
    colsum_part<<<dim3(C_ / 256, 32), 256>>>(cm, mv, N_, C_, part);
    colsum_reduce<<<C_ / 256, 256>>>(part, 32, C_, den);
    s2c_kernel<<<(N_ * C_) / 256, 256>>>(cm, mv, den, s2c);
    gemm(2, 0, s2c, xh, hidC, C_, H_, N_, 32, nullptr, nullptr);
    rownorm<<<C_ / 8, 256>>>(hidC, H_, nullptr, v1, nullptr);
    mm_go(0, hidC, xh, logits, C_, N_, nullptr, nullptr);
    row_softmax<<<C_, 512, N_ * 4>>>(logits, N_, nullptr, nullptr, nullptr);
    gemm(0, 0, logits, xh, hid2, C_, H_, N_, 32, nullptr, nullptr);
    rownorm<<<N_ / 8, 256>>>(xh, H_, nx, nullptr, nullptr);
    rownorm<<<C_ / 8, 256>>>(hid2, H_, ny, nullptr, nullptr);
    mm_go(0, xh, hid2, c2s, N_, C_, nullptr, nullptr);
    row_softmax<<<N_, 512, C_ * 4>>>(c2s, C_, nx, ny, v1);
    gemm(0, 0, c2s, hid2, tmp, N_, H_, C_, 8, nullptr, nullptr);
    gemm(1, 1, tmp, w_ps, ps, N_, H_, H_, 1, b_ps, nullptr);
    gemm(1, 3, ps, w_ps_back, hsh, N_, H_, H_, 1, b_ps_back, xh);
    gemm(1, 2, ps, w_ps_fore, outps, N_, H_, H_, 1, b_ps_fore, nullptr);

    // ---- hidden-concept branch ----
    rownorm<<<N_ / 8, 256>>>(hsh, H_, nh, nullptr, dg);
    mm_go(4, hsh, hsh, big, N_, N_, nh, nh);
    cudaMemsetAsync(colcnt, 0, N_ * sizeof(int));
    cudaMemsetAsync(hacc, 0, (size_t)N_ * H_ * sizeof(long long));
    topk_store<<<N_, 512>>>(big, colcnt, kidx, kval);
    scatter_hidh<<<(N_ * 10 * H_) / 256, 256>>>(kidx, kval, hsh, hacc);
    convert_hidh<<<(N_ * H_) / 256, 256>>>(hacc, colcnt, dg, hsh, hidH);
    rownorm<<<N_ / 8, 256>>>(hidH, H_, nhh, v2, nullptr);
    mm_go(0, hsh, hidH, big, N_, N_, nullptr, nullptr);
    row_softmax<<<N_, 512, N_ * 4>>>(big, N_, nh, nhh, v2);
    gemm(0, 0, big, hidH, tmp, N_, H_, N_, 16, nullptr, nullptr);
    gemm(1, 1, tmp, w_hs, hsi, N_, H_, H_, 1, b_hs, nullptr);
    gemm(1, 3, hsi, w_hs_back, indi, N_, H_, H_, 1, b_hs_back, hsh);
    gemm(1, 2, hsi, w_hs_fore, ouths, N_, H_, H_, 1, b_hs_fore, nullptr);
    gemm(1, 2, indi, w_indi, outindi, N_, H_, H_, 1, b_indi, nullptr);

    // ---- head ----
    final_head<<<N_ / 8, 256>>>(outps, ouths, outindi, w_out, b_out, out);
}

// round 13
// speedup vs baseline: 1.0100x; 1.0100x over previous
#include <cuda_runtime.h>
#include <cuda_bf16.h>
#include <math.h>
#include <stdint.h>

#define N_ 4096
#define C_ 512
#define H_ 128
#define T_ 64
#define D_ 20
#define G3 384

typedef unsigned long long u64;

// ------------------------- f32x2 helpers -------------------------
__device__ __forceinline__ u64 pack2_(float x) {
    u64 r; asm("mov.b64 %0, {%1, %2};" : "=l"(r) : "f"(x), "f"(x)); return r;
}
__device__ __forceinline__ void fma2_(u64& d, u64 a, u64 b) {
    asm("fma.rn.f32x2 %0, %1, %2, %0;" : "+l"(d) : "l"(a), "l"(b));
}
__device__ __forceinline__ void unpack2_(u64 v, float& lo, float& hi) {
    asm("mov.b64 {%0, %1}, %2;" : "=f"(lo), "=f"(hi) : "l"(v));
}

// fast activations
__device__ __forceinline__ float fsig_(float x) {
    float e, r;
    asm("ex2.approx.f32 %0, %1;" : "=f"(e) : "f"(-1.4426950408889634f * x));
    asm("rcp.approx.f32 %0, %1;" : "=f"(r) : "f"(1.f + e));
    return r;
}
__device__ __forceinline__ float ftanh_(float x) {
    float e, r;
    asm("ex2.approx.f32 %0, %1;" : "=f"(e) : "f"(2.8853900817779268f * x));
    asm("rcp.approx.f32 %0, %1;" : "=f"(r) : "f"(1.f + e));
    return fmaf(-2.f, r, 1.f);
}

// ------------------------- mma.sync helpers -------------------------
__device__ __forceinline__ uint32_t smem_u32_(const void* p) {
    uint32_t a;
    asm("{ .reg .u64 t; cvta.to.shared.u64 t, %1; cvt.u32.u64 %0, t; }" : "=r"(a) : "l"(p));
    return a;
}
__device__ __forceinline__ void ldsm4_(uint32_t* r, uint32_t a) {
    asm volatile("ldmatrix.sync.aligned.m8n8.x4.shared.b16 {%0,%1,%2,%3}, [%4];"
                 : "=r"(r[0]), "=r"(r[1]), "=r"(r[2]), "=r"(r[3]) : "r"(a));
}
__device__ __forceinline__ void ldsm2_(uint32_t* r, uint32_t a) {
    asm volatile("ldmatrix.sync.aligned.m8n8.x2.shared.b16 {%0,%1}, [%2];"
                 : "=r"(r[0]), "=r"(r[1]) : "r"(a));
}
__device__ __forceinline__ void mma_bf16_(float* d, const uint32_t* a, const uint32_t* b) {
    asm volatile(
        "mma.sync.aligned.m16n8k16.row.col.f32.bf16.bf16.f32 "
        "{%0,%1,%2,%3}, {%4,%5,%6,%7}, {%8,%9}, {%0,%1,%2,%3};"
        : "+f"(d[0]), "+f"(d[1]), "+f"(d[2]), "+f"(d[3])
        : "r"(a[0]), "r"(a[1]), "r"(a[2]), "r"(a[3]), "r"(b[0]), "r"(b[1]));
}

// ------------------------- scratch (device globals) -------------------------
__device__ float g_gx[(size_t)T_ * N_ * G3];
__device__ __nv_bfloat16 g_out0hi[(size_t)T_ * N_ * H_];
__device__ __nv_bfloat16 g_out0lo[(size_t)T_ * N_ * H_];
__device__ float g_xh[N_ * H_];
__device__ float g_den[C_];
__device__ float g_s2c[(size_t)N_ * C_];
__device__ float g_hidC[C_ * H_];
__device__ float g_v1[C_];
__device__ float g_logits[(size_t)C_ * N_];
__device__ float g_hid2[C_ * H_];
__device__ float g_nx[N_];
__device__ float g_ny[C_];
__device__ float g_c2s[(size_t)N_ * C_];
__device__ float g_tmp[N_ * H_];
__device__ float g_ps[N_ * H_];
__device__ float g_hsh[N_ * H_];
__device__ float g_outps[N_ * H_];
__device__ float g_nh[N_];
__device__ float g_diag[N_];
__device__ float g_big[(size_t)N_ * N_];
__device__ float g_part[32 * N_];
__device__ float g_kpart[(size_t)32 * 4096 * H_];
__device__ int   g_colcnt[N_];
__device__ int   g_kidx[N_ * 10];
__device__ float g_kval[N_ * 10];
__device__ long long g_hacc[N_ * H_];
__device__ float g_hidH[N_ * H_];
__device__ float g_v2[N_];
__device__ float g_nhh[N_];
__device__ float g_hsi[N_ * H_];
__device__ float g_indi[N_ * H_];
__device__ float g_ouths[N_ * H_];
__device__ float g_outindi[N_ * H_];

// ==================== HMMA GRU layer (512 thr / 16 warps, double-buffered h) ====
#define GRU_W_BYTES 98304
#define GRU_HB_STRIDE 136
#define GRU_HB_BYTES (32 * GRU_HB_STRIDE * 2)
#define GRU_SMEM (2 * GRU_W_BYTES + 4 * GRU_HB_BYTES)

__global__ __launch_bounds__(512, 1) void gru_mma(
    const float* __restrict__ gx, const float* __restrict__ whh,
    const float* __restrict__ bhh, float* __restrict__ outF,
    __nv_bfloat16* __restrict__ outHi, __nv_bfloat16* __restrict__ outLo,
    int write_all)
{
    extern __shared__ __align__(16) char gsm[];
    char* Wlo = gsm + GRU_W_BYTES;
    char* Hbase = gsm + 2 * GRU_W_BYTES;
    const int tid = threadIdx.x, lane = tid & 31, wp = tid >> 5;
    const int n0 = blockIdx.x * 32;
    const int jb = wp * 8;

    for (int idx = tid; idx < 384 * 16; idx += 512) {
        int n = idx >> 4, g8 = idx & 15;
        const float* src = whh + n * 128 + g8 * 8;
        float4 v0 = *(const float4*)src;
        float4 v1 = *(const float4*)(src + 4);
        float f[8] = {v0.x, v0.y, v0.z, v0.w, v1.x, v1.y, v1.z, v1.w};
        uint32_t hw[4], lw[4];
#pragma unroll
        for (int q = 0; q < 4; ++q) {
            __nv_bfloat16 h0 = __float2bfloat16(f[2 * q]);
            __nv_bfloat16 h1 = __float2bfloat16(f[2 * q + 1]);
            __nv_bfloat162 hp = __halves2bfloat162(h0, h1);
            __nv_bfloat162 lp = __halves2bfloat162(
                __float2bfloat16(f[2 * q] - __bfloat162float(h0)),
                __float2bfloat16(f[2 * q + 1] - __bfloat162float(h1)));
            hw[q] = *(uint32_t*)&hp;
            lw[q] = *(uint32_t*)&lp;
        }
        int off = n * 256 + ((g8 ^ (n & 7)) << 4);
        *(uint4*)(gsm + off) = make_uint4(hw[0], hw[1], hw[2], hw[3]);
        *(uint4*)(Wlo + off) = make_uint4(lw[0], lw[1], lw[2], lw[3]);
    }
    for (int idx = tid; idx < (4 * GRU_HB_BYTES) / 4; idx += 512)
        ((uint32_t*)Hbase)[idx] = 0;

    const int col0 = jb + 2 * (lane & 3);
    const int rbase = lane >> 2;
    float bR0 = bhh[col0], bR1 = bhh[col0 + 1];
    float bZ0 = bhh[128 + col0], bZ1 = bhh[128 + col0 + 1];
    float bN0 = bhh[256 + col0], bN1 = bhh[256 + col0 + 1];

    const uint32_t sb = smem_u32_(gsm);
    const uint32_t hB = sb + 2 * GRU_W_BYTES;
    const uint32_t aoff = (uint32_t)((lane & 15) * (GRU_HB_STRIDE * 2) + (lane >> 4) * 16);
    const int nRZ = ((lane >> 4) ? 128 + jb : jb) + (lane & 7);
    const uint32_t bRZ_base = sb + nRZ * 256;
    const uint32_t nlowRZ = (uint32_t)(nRZ & 7);
    const int nN = 256 + jb + (lane & 7);
    const uint32_t bN_base = sb + nN * 256;
    const uint32_t nlowN = (uint32_t)(nN & 7);
    const uint32_t ghalf = (uint32_t)((lane >> 3) & 1);

    float hold[4][2];
#pragma unroll
    for (int i = 0; i < 4; ++i) { hold[i][0] = 0.f; hold[i][1] = 0.f; }

    __syncthreads();

    for (int t = 0; t < T_; ++t) {
        const int rb = t & 1;
        const uint32_t aHi = hB + (uint32_t)(rb * 2 * GRU_HB_BYTES);
        const uint32_t aLo = aHi + GRU_HB_BYTES;
        __nv_bfloat16* Whi_w = (__nv_bfloat16*)(Hbase + (rb ^ 1) * 2 * GRU_HB_BYTES);
        __nv_bfloat16* Wlo_w = (__nv_bfloat16*)((char*)Whi_w + GRU_HB_BYTES);

        const float* gbase = gx + ((size_t)t * N_ + n0) * G3;
        float2 gR[4], gZ[4], gN[4];
#pragma unroll
        for (int ridx = 0; ridx < 4; ++ridx) {
            int row = (ridx >> 1) * 16 + (ridx & 1) * 8 + rbase;
            const float* gp = gbase + row * G3 + col0;
            gR[ridx] = *(const float2*)(gp);
            gZ[ridx] = *(const float2*)(gp + 128);
            gN[ridx] = *(const float2*)(gp + 256);
        }

        float acc[2][3][4];
#pragma unroll
        for (int i = 0; i < 2; ++i)
#pragma unroll
            for (int g = 0; g < 3; ++g)
#pragma unroll
                for (int q = 0; q < 4; ++q) acc[i][g][q] = 0.f;

#pragma unroll 2
        for (int kc = 0; kc < 8; ++kc) {
            uint32_t gsw = (uint32_t)(kc * 2);
            uint32_t addrRZ = bRZ_base + (((gsw + ghalf) ^ nlowRZ) << 4);
            uint32_t addrN = bN_base + (((gsw + ghalf) ^ nlowN) << 4);
            uint32_t bhiRZ[4], bloRZ[4], bhiN[2], bloN[2];
            ldsm4_(bhiRZ, addrRZ);
            ldsm4_(bloRZ, addrRZ + GRU_W_BYTES);
            ldsm2_(bhiN, addrN);
            ldsm2_(bloN, addrN + GRU_W_BYTES);
            uint32_t ahi[2][4], alo[2][4];
#pragma unroll
            for (int i = 0; i < 2; ++i) {
                uint32_t aa = aoff + (uint32_t)(i * 16 * GRU_HB_STRIDE * 2 + kc * 32);
                ldsm4_(ahi[i], aHi + aa);
                ldsm4_(alo[i], aLo + aa);
            }
#pragma unroll
            for (int i = 0; i < 2; ++i) {
                mma_bf16_(acc[i][0], ahi[i], bhiRZ);
                mma_bf16_(acc[i][0], alo[i], bhiRZ);
                mma_bf16_(acc[i][0], ahi[i], bloRZ);
                mma_bf16_(acc[i][1], ahi[i], bhiRZ + 2);
                mma_bf16_(acc[i][1], alo[i], bhiRZ + 2);
                mma_bf16_(acc[i][1], ahi[i], bloRZ + 2);
                mma_bf16_(acc[i][2], ahi[i], bhiN);
                mma_bf16_(acc[i][2], alo[i], bhiN);
                mma_bf16_(acc[i][2], ahi[i], bloN);
            }
        }

#pragma unroll
        for (int ridx = 0; ridx < 4; ++ridx) {
            int i = ridx >> 1, q0 = (ridx & 1) * 2;
            int row = (ridx >> 1) * 16 + (ridx & 1) * 8 + rbase;
            float rr0 = fsig_(gR[ridx].x + acc[i][0][q0] + bR0);
            float rr1 = fsig_(gR[ridx].y + acc[i][0][q0 + 1] + bR1);
            float zz0 = fsig_(gZ[ridx].x + acc[i][1][q0] + bZ0);
            float zz1 = fsig_(gZ[ridx].y + acc[i][1][q0 + 1] + bZ1);
            float nc0 = ftanh_(gN[ridx].x + rr0 * (acc[i][2][q0] + bN0));
            float nc1 = ftanh_(gN[ridx].y + rr1 * (acc[i][2][q0 + 1] + bN1));
            float h0 = (1.f - zz0) * nc0 + zz0 * hold[ridx][0];
            float h1 = (1.f - zz1) * nc1 + zz1 * hold[ridx][1];
            hold[ridx][0] = h0; hold[ridx][1] = h1;
            __nv_bfloat16 hh0 = __float2bfloat16(h0);
            __nv_bfloat16 hh1 = __float2bfloat16(h1);
            __nv_bfloat162 hp = __halves2bfloat162(hh0, hh1);
            __nv_bfloat162 lp = __halves2bfloat162(
                __float2bfloat16(h0 - __bfloat162float(hh0)),
                __float2bfloat16(h1 - __bfloat162float(hh1)));
            *(__nv_bfloat162*)&Whi_w[row * GRU_HB_STRIDE + col0] = hp;
            *(__nv_bfloat162*)&Wlo_w[row * GRU_HB_STRIDE + col0] = lp;
            if (write_all) {
                size_t gb = ((size_t)t * N_ + n0 + row) * H_ + col0;
                *(__nv_bfloat162*)&outHi[gb] = hp;
                *(__nv_bfloat162*)&outLo[gb] = lp;
            }
        }
        __syncthreads();
    }
    if (!write_all) {
#pragma unroll
        for (int ridx = 0; ridx < 4; ++ridx) {
            int row = (ridx >> 1) * 16 + (ridx & 1) * 8 + rbase;
            *(float2*)&outF[(size_t)(n0 + row) * H_ + col0] =
                make_float2(hold[ridx][0], hold[ridx][1]);
        }
    }
}

// ==================== mma.sync bf16-split NT GEMM (K=128), 128x128 tile ====================
#define MM_PAD 136
#define MM_TILE_BYTES (128 * MM_PAD * 2)
#define MM_SMEM (4 * MM_TILE_BYTES)

__device__ __forceinline__ void cvt_split_(float4 v, uint2& hw, uint2& lw) {
    __nv_bfloat16 h0 = __float2bfloat16(v.x), h1 = __float2bfloat16(v.y);
    __nv_bfloat16 h2 = __float2bfloat16(v.z), h3 = __float2bfloat16(v.w);
    __nv_bfloat162 hp0 = __halves2bfloat162(h0, h1);
    __nv_bfloat162 hp1 = __halves2bfloat162(h2, h3);
    __nv_bfloat162 lp0 = __halves2bfloat162(
        __float2bfloat16(v.x - __bfloat162float(h0)),
        __float2bfloat16(v.y - __bfloat162float(h1)));
    __nv_bfloat162 lp1 = __halves2bfloat162(
        __float2bfloat16(v.z - __bfloat162float(h2)),
        __float2bfloat16(v.w - __bfloat162float(h3)));
    hw.x = *(uint32_t*)&hp0; hw.y = *(uint32_t*)&hp1;
    lw.x = *(uint32_t*)&lp0; lw.y = *(uint32_t*)&lp1;
}

template <int EPI>
__device__ __forceinline__ float mepi_(float v, int row, int col,
                                       const float* e1, const float* e2)
{
    if (EPI == 1) v += e1[col];
    if (EPI == 4) {
        v = v / fmaxf(e1[row] * e2[col], 1e-12f);
        if (row == col) v = 0.f;
    }
    return v;
}

template <int EPI>
__device__ __forceinline__ void mm_core_(char* msm, float* __restrict__ Cm,
                                         int bm, int bn, int Nn,
                                         const float* e1, const float* e2)
{
    const int tid = threadIdx.x, lane = tid & 31, wid = tid >> 5;
    const uint32_t sb = smem_u32_(msm);
    const int m0 = (wid >> 2) * 64, n0 = (wid & 3) * 32;
    const uint32_t aRow = (uint32_t)((m0 + (lane & 15)) * MM_PAD * 2 + (lane >> 4) * 16);
    const uint32_t bRow = (uint32_t)((n0 + (lane & 7)) * MM_PAD * 2 + ((lane >> 3) & 1) * 16);

    float acc[4][4][4];
#pragma unroll
    for (int i = 0; i < 4; ++i)
#pragma unroll
        for (int j = 0; j < 4; ++j)
#pragma unroll
            for (int q = 0; q < 4; ++q) acc[i][j][q] = 0.f;

#pragma unroll
    for (int p = 0; p < 3; ++p) {
        const uint32_t aB = sb + (p == 1 ? MM_TILE_BYTES : 0) + aRow;
        const uint32_t bB = sb + 2 * MM_TILE_BYTES + (p == 2 ? MM_TILE_BYTES : 0) + bRow;
#pragma unroll
        for (int k0 = 0; k0 < 128; k0 += 16) {
            uint32_t af[4][4], bf[4][2];
#pragma unroll
            for (int i = 0; i < 4; ++i) ldsm4_(af[i], aB + i * 16 * MM_PAD * 2 + k0 * 2);
#pragma unroll
            for (int j = 0; j < 4; ++j) ldsm2_(bf[j], bB + j * 8 * MM_PAD * 2 + k0 * 2);
#pragma unroll
            for (int i = 0; i < 4; ++i)
#pragma unroll
                for (int j = 0; j < 4; ++j) mma_bf16_(acc[i][j], af[i], bf[j]);
        }
    }

    const int tr = lane >> 2, tc = (lane & 3) * 2;
#pragma unroll
    for (int i = 0; i < 4; ++i) {
#pragma unroll
        for (int j = 0; j < 4; ++j) {
            int row = bm + m0 + i * 16 + tr;
            int col = bn + n0 + j * 8 + tc;
            float2 v0, v1;
            v0.x = mepi_<EPI>(acc[i][j][0], row, col, e1, e2);
            v0.y = mepi_<EPI>(acc[i][j][1], row, col + 1, e1, e2);
            v1.x = mepi_<EPI>(acc[i][j][2], row + 8, col, e1, e2);
            v1.y = mepi_<EPI>(acc[i][j][3], row + 8, col + 1, e1, e2);
            *(float2*)&Cm[(size_t)row * Nn + col] = v0;
            *(float2*)&Cm[(size_t)(row + 8) * Nn + col] = v1;
        }
    }
}

template <int EPI>
__global__ __launch_bounds__(256, 1) void mmagemm(
    const float* __restrict__ A, const float* __restrict__ B, float* __restrict__ Cm,
    int M, int Nn, const float* __restrict__ e1, const float* __restrict__ e2)
{
    extern __shared__ __align__(16) char msm[];
    __nv_bfloat16* Ah = (__nv_bfloat16*)msm;
    __nv_bfloat16* Al = (__nv_bfloat16*)(msm + MM_TILE_BYTES);
    __nv_bfloat16* Bh = (__nv_bfloat16*)(msm + 2 * MM_TILE_BYTES);
    __nv_bfloat16* Bl = (__nv_bfloat16*)(msm + 3 * MM_TILE_BYTES);
    const int tid = threadIdx.x;
    const int bm = blockIdx.y * 128, bn = blockIdx.x * 128;

    {
        const float* Ab = A + (size_t)bm * 128;
        const float* Bb = B + (size_t)bn * 128;
        for (int idx = tid; idx < 128 * 32; idx += 256) {
            int row = idx >> 5, q = (idx & 31) << 2;
            uint2 hw, lw;
            cvt_split_(*(const float4*)&Ab[row * 128 + q], hw, lw);
            *(uint2*)&Ah[row * MM_PAD + q] = hw;
            *(uint2*)&Al[row * MM_PAD + q] = lw;
            cvt_split_(*(const float4*)&Bb[row * 128 + q], hw, lw);
            *(uint2*)&Bh[row * MM_PAD + q] = hw;
            *(uint2*)&Bl[row * MM_PAD + q] = lw;
        }
    }
    __syncthreads();
    mm_core_<EPI>(msm, Cm, bm, bn, Nn, e1, e2);
}

// variant: A pre-split (bf16 hi/lo planes), B fp32
__global__ __launch_bounds__(256, 1) void mmagemm_pre(
    const __nv_bfloat16* __restrict__ Ahi_g, const __nv_bfloat16* __restrict__ Alo_g,
    const float* __restrict__ B, float* __restrict__ Cm,
    int M, int Nn, const float* __restrict__ e1)
{
    extern __shared__ __align__(16) char msm[];
    __nv_bfloat16* Ah = (__nv_bfloat16*)msm;
    __nv_bfloat16* Al = (__nv_bfloat16*)(msm + MM_TILE_BYTES);
    __nv_bfloat16* Bh = (__nv_bfloat16*)(msm + 2 * MM_TILE_BYTES);
    __nv_bfloat16* Bl = (__nv_bfloat16*)(msm + 3 * MM_TILE_BYTES);
    const int tid = threadIdx.x;
    const int bm = blockIdx.y * 128, bn = blockIdx.x * 128;

    for (int idx = tid; idx < 128 * 16; idx += 256) {
        int row = idx >> 4, q = (idx & 15) << 3;
        *(uint4*)&Ah[row * MM_PAD + q] = *(const uint4*)&Ahi_g[((size_t)bm + row) * 128 + q];
        *(uint4*)&Al[row * MM_PAD + q] = *(const uint4*)&Alo_g[((size_t)bm + row) * 128 + q];
    }
    {
        const float* Bb = B + (size_t)bn * 128;
        for (int idx = tid; idx < 128 * 32; idx += 256) {
            int row = idx >> 5, q = (idx & 31) << 2;
            uint2 hw, lw;
            cvt_split_(*(const float4*)&Bb[row * 128 + q], hw, lw);
            *(uint2*)&Bh[row * MM_PAD + q] = hw;
            *(uint2*)&Bl[row * MM_PAD + q] = lw;
        }
    }
    __syncthreads();
    mm_core_<1>(msm, Cm, bm, bn, Nn, e1, nullptr);
}

// ------------------------- gx0 -------------------------
__global__ void gx0_kernel(const float* __restrict__ x, const float* __restrict__ wih,
                           const float* __restrict__ bih, float* __restrict__ gx)
{
    __shared__ float xs[32 * D_];
    const int t = blockIdx.x;
    const int n0 = blockIdx.y * 32;
    const int g = threadIdx.x;
    for (int idx = g; idx < 32 * D_; idx += G3) {
        int r = idx / D_, d = idx - r * D_;
        xs[idx] = x[(size_t)(n0 + r) * (D_ * T_) + d * T_ + t];
    }
    float wr[D_];
#pragma unroll
    for (int d = 0; d < D_; ++d) wr[d] = wih[g * D_ + d];
    const float b = bih[g];
    __syncthreads();
    for (int r = 0; r < 32; ++r) {
        const float4* xp = (const float4*)&xs[r * D_];
        float acc = b;
#pragma unroll
        for (int q = 0; q < 5; ++q) {
            float4 v = xp[q];
            acc += v.x * wr[q * 4 + 0] + v.y * wr[q * 4 + 1] +
                   v.z * wr[q * 4 + 2] + v.w * wr[q * 4 + 3];
        }
        gx[((size_t)t * N_ + n0 + r) * G3 + g] = acc;
    }
}

// ------------------------- 128x128 f32x2 SGEMM with split-K -------------------------
template <int EPI>
__device__ __forceinline__ float epi_apply(float v, int row, int col, int Nn,
                                           const float* e1, const float* e2)
{
    if (EPI == 1) v += e1[col];
    if (EPI == 2) { v += e1[col]; v = v > 0.f ? v : 0.01f * v; }
    if (EPI == 3) { v += e1[col]; v = e2[(size_t)row * Nn + col] - v; }
    return v;
}

template <int TR, int EPI>
__global__ __launch_bounds__(256, 2) void sgemm128(
    const float* __restrict__ A, const float* __restrict__ B, float* __restrict__ Cm,
    int M, int Nn, int K, int Ksplit,
    const float* __restrict__ e1, const float* __restrict__ e2,
    float* __restrict__ part)
{
    __shared__ __align__(16) float As[16][136];
    __shared__ __align__(16) float Bs[16][136];
    const int bm = blockIdx.y * 128, bn = blockIdx.x * 128;
    const int z = blockIdx.z;
    const int kb = z * Ksplit, ke = kb + Ksplit;
    const int tid = threadIdx.x;
    const int tx = tid & 15, ty = tid >> 4;
    u64 acc[4][8];
#pragma unroll
    for (int i = 0; i < 4; ++i)
#pragma unroll
        for (int j = 0; j < 8; ++j) acc[i][j] = 0ull;

    for (int k0 = kb; k0 < ke; k0 += 16) {
        if (TR == 2) {
            int k = tid >> 4, m = (tid & 15) << 3;
            const float* src = &A[(size_t)(k0 + k) * M + bm + m];
            *(float4*)&As[k][m]     = *(const float4*)(src);
            *(float4*)&As[k][m + 4] = *(const float4*)(src + 4);
        } else {
            int m = tid >> 1, kq = (tid & 1) << 3;
            const float* src = &A[(size_t)(bm + m) * K + k0 + kq];
            float4 v0 = *(const float4*)(src);
            float4 v1 = *(const float4*)(src + 4);
            As[kq + 0][m] = v0.x; As[kq + 1][m] = v0.y;
            As[kq + 2][m] = v0.z; As[kq + 3][m] = v0.w;
            As[kq + 4][m] = v1.x; As[kq + 5][m] = v1.y;
            As[kq + 6][m] = v1.z; As[kq + 7][m] = v1.w;
        }
        if (TR == 1) {
            int n = tid >> 1, kq = (tid & 1) << 3;
            const float* src = &B[(size_t)(bn + n) * K + k0 + kq];
            float4 v0 = *(const float4*)(src);
            float4 v1 = *(const float4*)(src + 4);
            Bs[kq + 0][n] = v0.x; Bs[kq + 1][n] = v0.y;
            Bs[kq + 2][n] = v0.z; Bs[kq + 3][n] = v0.w;
            Bs[kq + 4][n] = v1.x; Bs[kq + 5][n] = v1.y;
            Bs[kq + 6][n] = v1.z; Bs[kq + 7][n] = v1.w;
        } else {
            int k = tid >> 4, n = (tid & 15) << 3;
            const float* src = &B[(size_t)(k0 + k) * Nn + bn + n];
            *(float4*)&Bs[k][n]     = *(const float4*)(src);
            *(float4*)&Bs[k][n + 4] = *(const float4*)(src + 4);
        }
        __syncthreads();
#pragma unroll
        for (int kk = 0; kk < 16; ++kk) {
            ulonglong2 a01 = *(const ulonglong2*)&As[kk][ty << 3];
            ulonglong2 a23 = *(const ulonglong2*)&As[kk][(ty << 3) + 4];
            float4 b0 = *(const float4*)&Bs[kk][tx << 2];
            float4 b1 = *(const float4*)&Bs[kk][64 + (tx << 2)];
            u64 ar[4] = {a01.x, a01.y, a23.x, a23.y};
            u64 bd[8];
            bd[0] = pack2_(b0.x); bd[1] = pack2_(b0.y);
            bd[2] = pack2_(b0.z); bd[3] = pack2_(b0.w);
            bd[4] = pack2_(b1.x); bd[5] = pack2_(b1.y);
            bd[6] = pack2_(b1.z); bd[7] = pack2_(b1.w);
#pragma unroll
            for (int rp = 0; rp < 4; ++rp)
#pragma unroll
                for (int c = 0; c < 8; ++c) fma2_(acc[rp][c], ar[rp], bd[c]);
        }
        __syncthreads();
    }

    const bool partial = (gridDim.z > 1);
    float* obase = partial ? part + (size_t)z * M * Nn : Cm;
#pragma unroll
    for (int rp = 0; rp < 4; ++rp) {
        float lo[8], hi[8];
#pragma unroll
        for (int c = 0; c < 8; ++c) unpack2_(acc[rp][c], lo[c], hi[c]);
        int row0 = bm + (ty << 3) + rp * 2;
#pragma unroll
        for (int h = 0; h < 2; ++h) {
            int row = row0 + h;
            float* vv = h ? hi : lo;
            int colA = bn + (tx << 2);
            int colB = bn + 64 + (tx << 2);
            float4 oA, oB;
            if (!partial) {
                oA.x = epi_apply<EPI>(vv[0], row, colA + 0, Nn, e1, e2);
                oA.y = epi_apply<EPI>(vv[1], row, colA + 1, Nn, e1, e2);
                oA.z = epi_apply<EPI>(vv[2], row, colA + 2, Nn, e1, e2);
                oA.w = epi_apply<EPI>(vv[3], row, colA + 3, Nn, e1, e2);
                oB.x = epi_apply<EPI>(vv[4], row, colB + 0, Nn, e1, e2);
                oB.y = epi_apply<EPI>(vv[5], row, colB + 1, Nn, e1, e2);
                oB.z = epi_apply<EPI>(vv[6], row, colB + 2, Nn, e1, e2);
                oB.w = epi_apply<EPI>(vv[7], row, colB + 3, Nn, e1, e2);
            } else {
                oA = make_float4(vv[0], vv[1], vv[2], vv[3]);
                oB = make_float4(vv[4], vv[5], vv[6], vv[7]);
            }
            *(float4*)&obase[(size_t)row * Nn + colA] = oA;
            *(float4*)&obase[(size_t)row * Nn + colB] = oB;
        }
    }
}

__global__ void kreduce(const float* __restrict__ part, int S, size_t MN,
                        float* __restrict__ out)
{
    size_t i4 = ((size_t)blockIdx.x * 256 + threadIdx.x) * 4;
    if (i4 >= MN) return;
    float4 s = *(const float4*)&part[i4];
    for (int z = 1; z < S; ++z) {
        float4 v = *(const float4*)&part[(size_t)z * MN + i4];
        s.x += v.x; s.y += v.y; s.z += v.z; s.w += v.w;
    }
    *(float4*)&out[i4] = s;
}

// ------------------------- reductions / elementwise -------------------------
__global__ void colsum_part(const float* __restrict__ m, const float* __restrict__ w,
                            int rows, int cols, float* __restrict__ part)
{
    int c = blockIdx.x * 256 + threadIdx.x;
    int chunk = rows / gridDim.y;
    int r0 = blockIdx.y * chunk;
    float acc = 0.f;
    for (int r = r0; r < r0 + chunk; ++r)
        acc += m[(size_t)r * cols + c] * (w ? w[r] : 1.f);
    part[(size_t)blockIdx.y * cols + c] = acc;
}
__global__ void colsum_reduce(const float* __restrict__ part, int nb, int cols,
                              float* __restrict__ out)
{
    int c = blockIdx.x * 256 + threadIdx.x;
    float a = 0.f;
    for (int b = 0; b < nb; ++b) a += part[(size_t)b * cols + c];
    out[c] = a;
}

__global__ void s2c_kernel(const float* __restrict__ cm, const float* __restrict__ mv,
                           const float* __restrict__ den, float* __restrict__ s2c)
{
    int e = blockIdx.x * 256 + threadIdx.x;
    if (e >= N_ * C_) return;
    int i = e >> 9, c = e & (C_ - 1);
    float cv = cm[e];
    s2c[e] = cv * mv[i] / (den[c] * cv + 1.f);
}

__global__ void rownorm(const float* __restrict__ x, int cols,
                        float* __restrict__ nrm, float* __restrict__ vflag,
                        float* __restrict__ dg)
{
    int row = blockIdx.x * 8 + (threadIdx.x >> 5);
    int lane = threadIdx.x & 31;
    const float* p = x + (size_t)row * cols;
    float s = 0.f, q = 0.f;
    for (int c = lane; c < cols; c += 32) { float v = p[c]; s += v; q += v * v; }
#pragma unroll
    for (int o = 16; o; o >>= 1) {
        s += __shfl_xor_sync(0xffffffffu, s, o);
        q += __shfl_xor_sync(0xffffffffu, q, o);
    }
    if (lane == 0) {
        if (nrm) nrm[row] = sqrtf(q);
        if (vflag) vflag[row] = (s != 0.f) ? 1.f : 0.f;
        if (dg) { float d = sqrtf(q) * sqrtf(q); dg[row] = q / fmaxf(d, 1e-12f); }
    }
}

// 512-thread row softmax
__global__ __launch_bounds__(512, 1) void row_softmax(
    float* __restrict__ m, int width,
    const float* __restrict__ rs, const float* __restrict__ cs,
    const float* __restrict__ vm)
{
    extern __shared__ float sv[];
    __shared__ float red[16];
    __shared__ float smx, ssum;
    const int tid = threadIdx.x, lane = tid & 31, wid = tid >> 5;
    const size_t base = (size_t)blockIdx.x * width;
    const float rsv = rs ? rs[blockIdx.x] : 0.f;
    float lmax = -3.0e38f;
    for (int j = tid; j < width; j += 512) {
        float v = m[base + j];
        if (rs) v = v / fmaxf(rsv * cs[j], 1e-12f);
        if (vm && vm[j] == 0.f) v = -3.0e38f;
        sv[j] = v;
        lmax = fmaxf(lmax, v);
    }
#pragma unroll
    for (int o = 16; o; o >>= 1) lmax = fmaxf(lmax, __shfl_xor_sync(0xffffffffu, lmax, o));
    if (lane == 0) red[wid] = lmax;
    __syncthreads();
    if (tid == 0) {
        float v = red[0];
        for (int w = 1; w < 16; ++w) v = fmaxf(v, red[w]);
        smx = v;
    }
    __syncthreads();
    const float mx = smx;
    float lsum = 0.f;
    for (int j = tid; j < width; j += 512) {
        float e = __expf(sv[j] - mx);
        sv[j] = e;
        lsum += e;
    }
#pragma unroll
    for (int o = 16; o; o >>= 1) lsum += __shfl_xor_sync(0xffffffffu, lsum, o);
    if (lane == 0) red[wid] = lsum;
    __syncthreads();
    if (tid == 0) {
        float v = 0.f;
        for (int w = 0; w < 16; ++w) v += red[w];
        ssum = v;
    }
    __syncthreads();
    const float inv = 1.f / ssum;
    for (int j = tid; j < width; j += 512) {
        float o = sv[j] * inv;
        if (vm) o = (vm[j] != 0.f) ? o : 0.f;
        m[base + j] = o;
    }
}

// ------------------------- top-10 store -------------------------
__global__ __launch_bounds__(512, 1) void topk_store(
    const float* __restrict__ m, int* __restrict__ colcnt,
    int* __restrict__ kidx, float* __restrict__ kval)
{
    __shared__ float vals[N_];
    __shared__ float cval[160];
    __shared__ int cidx[160];
    __shared__ int keep[10];
    __shared__ float keepv[10];
    const int tid = threadIdx.x, lane = tid & 31, wid = tid >> 5;
    const size_t base = (size_t)blockIdx.x * N_;

    for (int j = tid; j < N_; j += 512) vals[j] = m[base + j];
    __syncthreads();

    {
        const int cbase = wid * 256 + lane * 8;
        float v[8];
#pragma unroll
        for (int i = 0; i < 8; ++i) v[i] = vals[cbase + i];
        for (int s = 0; s < 10; ++s) {
            float bv = v[0]; int bs = 0;
#pragma unroll
            for (int i = 1; i < 8; ++i)
                if (v[i] > bv) { bv = v[i]; bs = i; }
            int bi = cbase + bs;
#pragma unroll
            for (int o = 16; o; o >>= 1) {
                float ov = __shfl_down_sync(0xffffffffu, bv, o);
                int oi = __shfl_down_sync(0xffffffffu, bi, o);
                if (ov > bv || (ov == bv && oi < bi)) { bv = ov; bi = oi; }
            }
            bv = __shfl_sync(0xffffffffu, bv, 0);
            bi = __shfl_sync(0xffffffffu, bi, 0);
            if (lane == 0) { cval[wid * 10 + s] = bv; cidx[wid * 10 + s] = bi; }
            if (bi >= cbase && bi < cbase + 8) v[bi - cbase] = -3.0e38f;
        }
    }
    __syncthreads();

    if (wid == 0) {
        float v[5]; int gi[5];
#pragma unroll
        for (int i = 0; i < 5; ++i) {
            v[i] = cval[lane * 5 + i];
            gi[i] = cidx[lane * 5 + i];
        }
        for (int s = 0; s < 10; ++s) {
            float bv = v[0]; int bi = gi[0], bs = 0;
#pragma unroll
            for (int i = 1; i < 5; ++i)
                if (v[i] > bv || (v[i] == bv && gi[i] < bi)) { bv = v[i]; bi = gi[i]; bs = i; }
            int slot = lane * 5 + bs;
#pragma unroll
            for (int o = 16; o; o >>= 1) {
                float ov = __shfl_down_sync(0xffffffffu, bv, o);
                int oi = __shfl_down_sync(0xffffffffu, bi, o);
                int os = __shfl_down_sync(0xffffffffu, slot, o);
                if (ov > bv || (ov == bv && oi < bi)) { bv = ov; bi = oi; slot = os; }
            }
            bv = __shfl_sync(0xffffffffu, bv, 0);
            bi = __shfl_sync(0xffffffffu, bi, 0);
            slot = __shfl_sync(0xffffffffu, slot, 0);
            if (lane == 0) { keep[s] = bi; keepv[s] = bv; }
            if (slot >= lane * 5 && slot < lane * 5 + 5) v[slot - lane * 5] = -3.0e38f;
        }
        if (lane < 10) {
            atomicAdd(&colcnt[keep[lane]], 1);
            kidx[blockIdx.x * 10 + lane] = keep[lane];
            kval[blockIdx.x * 10 + lane] = keepv[lane];
        }
    }
}

// ------------------------- sparse hidden_h -------------------------
#define FXSCALE 1099511627776.f
#define FXINV   (1.0 / 1099511627776.0)

__global__ void scatter_hidh(const int* __restrict__ kidx, const float* __restrict__ kval,
                             const float* __restrict__ hsh, long long* __restrict__ hacc)
{
    int gid = blockIdx.x * 256 + threadIdx.x;
    if (gid >= N_ * 10 * H_) return;
    int e = gid >> 7, h = gid & 127;
    int row = e / 10;
    int col = kidx[e];
    float prod = kval[e] * hsh[row * H_ + h];
    long long q = llrintf(prod * FXSCALE);
    atomicAdd((unsigned long long*)&hacc[(size_t)col * H_ + h], (unsigned long long)q);
}

__global__ void convert_hidh(const long long* __restrict__ hacc,
                             const int* __restrict__ cnt, const float* __restrict__ dg,
                             const float* __restrict__ hsh, float* __restrict__ hidH)
{
    int i = blockIdx.x * 256 + threadIdx.x;
    if (i >= N_ * H_) return;
    int c = i >> 7;
    float v = (float)((double)hacc[i] * FXINV);
    if (cnt[c] > 0) v += dg[c] * hsh[i];
    hidH[i] = v;
}

__global__ void final_head(const float* __restrict__ a, const float* __restrict__ b,
                           const float* __restrict__ c, const float* __restrict__ w,
                           const float* __restrict__ bo, float* __restrict__ out)
{
    int row = blockIdx.x * 8 + (threadIdx.x >> 5);
    int lane = threadIdx.x & 31;
    size_t base = (size_t)row * H_;
    float acc = 0.f;
    for (int h = lane; h < H_; h += 32)
        acc += (a[base + h] + b[base + h] + c[base + h]) * w[h];
#pragma unroll
    for (int o = 16; o; o >>= 1) acc += __shfl_xor_sync(0xffffffffu, acc, o);
    if (lane == 0) out[row] = acc + bo[0];
}

// ------------------------- host side -------------------------
static float* g_kpart_ptr;

static void gemm(int TR, int EPI, const float* A, const float* B, float* Cm,
                 int M, int Nn, int K, int S, const float* e1, const float* e2)
{
    dim3 g(Nn / 128, M / 128, S), blk(256);
    int Ks = K / S;
    if (S > 1) {
        if (TR == 0) sgemm128<0, 0><<<g, blk>>>(A, B, Cm, M, Nn, K, Ks, e1, e2, g_kpart_ptr);
        else if (TR == 1) sgemm128<1, 0><<<g, blk>>>(A, B, Cm, M, Nn, K, Ks, e1, e2, g_kpart_ptr);
        else sgemm128<2, 0><<<g, blk>>>(A, B, Cm, M, Nn, K, Ks, e1, e2, g_kpart_ptr);
        size_t MN = (size_t)M * Nn;
        kreduce<<<(int)((MN / 4 + 255) / 256), 256>>>(g_kpart_ptr, S, MN, Cm);
        return;
    }
    if (TR == 0) sgemm128<0, 0><<<g, blk>>>(A, B, Cm, M, Nn, K, Ks, e1, e2, nullptr);
    else if (TR == 2) sgemm128<2, 0><<<g, blk>>>(A, B, Cm, M, Nn, K, Ks, e1, e2, nullptr);
    else if (EPI == 0) sgemm128<1, 0><<<g, blk>>>(A, B, Cm, M, Nn, K, Ks, e1, e2, nullptr);
    else if (EPI == 1) sgemm128<1, 1><<<g, blk>>>(A, B, Cm, M, Nn, K, Ks, e1, e2, nullptr);
    else if (EPI == 2) sgemm128<1, 2><<<g, blk>>>(A, B, Cm, M, Nn, K, Ks, e1, e2, nullptr);
    else sgemm128<1, 3><<<g, blk>>>(A, B, Cm, M, Nn, K, Ks, e1, e2, nullptr);
}

static void mm_go(int EPI, const float* A, const float* B, float* Cm,
                  int M, int Nn, const float* e1, const float* e2)
{
    dim3 g(Nn / 128, M / 128);
    if (EPI == 0) mmagemm<0><<<g, 256, MM_SMEM>>>(A, B, Cm, M, Nn, e1, e2);
    else if (EPI == 1) mmagemm<1><<<g, 256, MM_SMEM>>>(A, B, Cm, M, Nn, e1, e2);
    else mmagemm<4><<<g, 256, MM_SMEM>>>(A, B, Cm, M, Nn, e1, e2);
}

template <typename Tp>
static float* symaddr(Tp& sym)
{
    void* p = nullptr;
    cudaGetSymbolAddress(&p, sym);
    return (float*)p;
}

extern "C" void kernel_launch(void* const* d_in, const int* in_sizes, int n_in,
                              void* d_out, int out_size)
{
    const float* x = (const float*)d_in[0];
    const float* cm = (const float*)d_in[1];
    const float* mv = (const float*)d_in[2];
    const float* wih0 = (const float*)d_in[3];
    const float* whh0 = (const float*)d_in[4];
    const float* bih0 = (const float*)d_in[5];
    const float* bhh0 = (const float*)d_in[6];
    const float* wih1 = (const float*)d_in[7];
    const float* whh1 = (const float*)d_in[8];
    const float* bih1 = (const float*)d_in[9];
    const float* bhh1 = (const float*)d_in[10];
    const float* w_ps = (const float*)d_in[11];
    const float* b_ps = (const float*)d_in[12];
    const float* w_hs = (const float*)d_in[13];
    const float* b_hs = (const float*)d_in[14];
    const float* w_ps_fore = (const float*)d_in[15];
    const float* b_ps_fore = (const float*)d_in[16];
    const float* w_hs_fore = (const float*)d_in[17];
    const float* b_hs_fore = (const float*)d_in[18];
    const float* w_ps_back = (const float*)d_in[19];
    const float* b_ps_back = (const float*)d_in[20];
    const float* w_hs_back = (const float*)d_in[21];
    const float* b_hs_back = (const float*)d_in[22];
    const float* w_indi = (const float*)d_in[23];
    const float* b_indi = (const float*)d_in[24];
    const float* w_out = (const float*)d_in[25];
    const float* b_out = (const float*)d_in[26];
    float* out = (float*)d_out;

    float* gx = symaddr(g_gx);
    __nv_bfloat16* out0hi = (__nv_bfloat16*)symaddr(g_out0hi);
    __nv_bfloat16* out0lo = (__nv_bfloat16*)symaddr(g_out0lo);
    float* xh = symaddr(g_xh);
    float* den = symaddr(g_den);
    float* s2c = symaddr(g_s2c);
    float* hidC = symaddr(g_hidC);
    float* v1 = symaddr(g_v1);
    float* logits = symaddr(g_logits);
    float* hid2 = symaddr(g_hid2);
    float* nx = symaddr(g_nx);
    float* ny = symaddr(g_ny);
    float* c2s = symaddr(g_c2s);
    float* tmp = symaddr(g_tmp);
    float* ps = symaddr(g_ps);
    float* hsh = symaddr(g_hsh);
    float* outps = symaddr(g_outps);
    float* nh = symaddr(g_nh);
    float* dg = symaddr(g_diag);
    float* big = symaddr(g_big);
    float* part = symaddr(g_part);
    int* colcnt = (int*)symaddr(g_colcnt);
    int* kidx = (int*)symaddr(g_kidx);
    float* kval = symaddr(g_kval);
    long long* hacc = (long long*)symaddr(g_hacc);
    float* hidH = symaddr(g_hidH);
    float* v2 = symaddr(g_v2);
    float* nhh = symaddr(g_nhh);
    float* hsi = symaddr(g_hsi);
    float* indi = symaddr(g_indi);
    float* ouths = symaddr(g_ouths);
    float* outindi = symaddr(g_outindi);
    g_kpart_ptr = symaddr(g_kpart);

    cudaFuncSetAttribute(gru_mma, cudaFuncAttributeMaxDynamicSharedMemorySize, GRU_SMEM);
    cudaFuncSetAttribute(mmagemm<0>, cudaFuncAttributeMaxDynamicSharedMemorySize, MM_SMEM);
    cudaFuncSetAttribute(mmagemm<1>, cudaFuncAttributeMaxDynamicSharedMemorySize, MM_SMEM);
    cudaFuncSetAttribute(mmagemm<4>, cudaFuncAttributeMaxDynamicSharedMemorySize, MM_SMEM);
    cudaFuncSetAttribute(mmagemm_pre, cudaFuncAttributeMaxDynamicSharedMemorySize, MM_SMEM);

    // ---- GRU ----
    gx0_kernel<<<dim3(T_, N_ / 32), G3>>>(x, wih0, bih0, gx);
    gru_mma<<<N_ / 32, 512, GRU_SMEM>>>(gx, whh0, bhh0, nullptr, out0hi, out0lo, 1);
    {
        dim3 g(G3 / 128, (T_ * N_) / 128);
        mmagemm_pre<<<g, 256, MM_SMEM>>>(out0hi, out0lo, wih1, gx, T_ * N_, G3, bih1);
    }
    gru_mma<<<N_ / 32, 512, GRU_SMEM>>>(gx, whh1, bhh1, xh, nullptr, nullptr, 0);

    // ---- predefined-concept branch ----
    colsum_part<<<dim3(C_ / 256, 32), 256>>>(cm, mv, N_, C_, part);
    colsum_reduce<<<C_ / 256, 256>>>(part, 32, C_, den);
    s2c_kernel<<<(N_ * C_) / 256, 256>>>(cm, mv, den, s2c);
    gemm(2, 0, s2c, xh, hidC, C_, H_, N_, 32, nullptr, nullptr);
    rownorm<<<C_ / 8, 256>>>(hidC, H_, nullptr, v1, nullptr);
    mm_go(0, hidC, xh, logits, C_, N_, nullptr, nullptr);
    row_softmax<<<C_, 512, N_ * 4>>>(logits, N_, nullptr, nullptr, nullptr);
    gemm(0, 0, logits, xh, hid2, C_, H_, N_, 32, nullptr, nullptr);
    rownorm<<<N_ / 8, 256>>>(xh, H_, nx, nullptr, nullptr);
    rownorm<<<C_ / 8, 256>>>(hid2, H_, ny, nullptr, nullptr);
    mm_go(0, xh, hid2, c2s, N_, C_, nullptr, nullptr);
    row_softmax<<<N_, 512, C_ * 4>>>(c2s, C_, nx, ny, v1);
    gemm(0, 0, c2s, hid2, tmp, N_, H_, C_, 8, nullptr, nullptr);
    gemm(1, 1, tmp, w_ps, ps, N_, H_, H_, 1, b_ps, nullptr);
    gemm(1, 3, ps, w_ps_back, hsh, N_, H_, H_, 1, b_ps_back, xh);
    gemm(1, 2, ps, w_ps_fore, outps, N_, H_, H_, 1, b_ps_fore, nullptr);

    // ---- hidden-concept branch ----
    rownorm<<<N_ / 8, 256>>>(hsh, H_, nh, nullptr, dg);
    mm_go(4, hsh, hsh, big, N_, N_, nh, nh);
    cudaMemsetAsync(colcnt, 0, N_ * sizeof(int));
    cudaMemsetAsync(hacc, 0, (size_t)N_ * H_ * sizeof(long long));
    topk_store<<<N_, 512>>>(big, colcnt, kidx, kval);
    scatter_hidh<<<(N_ * 10 * H_) / 256, 256>>>(kidx, kval, hsh, hacc);
    convert_hidh<<<(N_ * H_) / 256, 256>>>(hacc, colcnt, dg, hsh, hidH);
    rownorm<<<N_ / 8, 256>>>(hidH, H_, nhh, v2, nullptr);
    mm_go(0, hsh, hidH, big, N_, N_, nullptr, nullptr);
    row_softmax<<<N_, 512, N_ * 4>>>(big, N_, nh, nhh, v2);
    gemm(0, 0, big, hidH, tmp, N_, H_, N_, 16, nullptr, nullptr);
    gemm(1, 1, tmp, w_hs, hsi, N_, H_, H_, 1, b_hs, nullptr);
    gemm(1, 3, hsi, w_hs_back, indi, N_, H_, H_, 1, b_hs_back, hsh);
    gemm(1, 2, hsi, w_hs_fore, ouths, N_, H_, H_, 1, b_hs_fore, nullptr);
    gemm(1, 2, indi, w_indi, outindi, N_, H_, H_, 1, b_indi, nullptr);

    // ---- head ----
    final_head<<<N_ / 8, 256>>>(outps, ouths, outindi, w_out, b_out, out);
}

// round 14
// speedup vs baseline: 1.0277x; 1.0175x over previous
#include <cuda_runtime.h>
#include <cuda_bf16.h>
#include <math.h>
#include <stdint.h>

#define N_ 4096
#define C_ 512
#define H_ 128
#define T_ 64
#define D_ 20
#define G3 384

typedef unsigned long long u64;

// ------------------------- f32x2 helpers -------------------------
__device__ __forceinline__ u64 pack2_(float x) {
    u64 r; asm("mov.b64 %0, {%1, %2};" : "=l"(r) : "f"(x), "f"(x)); return r;
}
__device__ __forceinline__ void fma2_(u64& d, u64 a, u64 b) {
    asm("fma.rn.f32x2 %0, %1, %2, %0;" : "+l"(d) : "l"(a), "l"(b));
}
__device__ __forceinline__ void unpack2_(u64 v, float& lo, float& hi) {
    asm("mov.b64 {%0, %1}, %2;" : "=f"(lo), "=f"(hi) : "l"(v));
}

// fast activations
__device__ __forceinline__ float fsig_(float x) {
    float e, r;
    asm("ex2.approx.f32 %0, %1;" : "=f"(e) : "f"(-1.4426950408889634f * x));
    asm("rcp.approx.f32 %0, %1;" : "=f"(r) : "f"(1.f + e));
    return r;
}
__device__ __forceinline__ float ftanh_(float x) {
    float e, r;
    asm("ex2.approx.f32 %0, %1;" : "=f"(e) : "f"(2.8853900817779268f * x));
    asm("rcp.approx.f32 %0, %1;" : "=f"(r) : "f"(1.f + e));
    return fmaf(-2.f, r, 1.f);
}

// ------------------------- mma.sync helpers -------------------------
__device__ __forceinline__ uint32_t smem_u32_(const void* p) {
    uint32_t a;
    asm("{ .reg .u64 t; cvta.to.shared.u64 t, %1; cvt.u32.u64 %0, t; }" : "=r"(a) : "l"(p));
    return a;
}
__device__ __forceinline__ void ldsm4_(uint32_t* r, uint32_t a) {
    asm volatile("ldmatrix.sync.aligned.m8n8.x4.shared.b16 {%0,%1,%2,%3}, [%4];"
                 : "=r"(r[0]), "=r"(r[1]), "=r"(r[2]), "=r"(r[3]) : "r"(a));
}
__device__ __forceinline__ void ldsm2_(uint32_t* r, uint32_t a) {
    asm volatile("ldmatrix.sync.aligned.m8n8.x2.shared.b16 {%0,%1}, [%2];"
                 : "=r"(r[0]), "=r"(r[1]) : "r"(a));
}
__device__ __forceinline__ void mma_bf16_(float* d, const uint32_t* a, const uint32_t* b) {
    asm volatile(
        "mma.sync.aligned.m16n8k16.row.col.f32.bf16.bf16.f32 "
        "{%0,%1,%2,%3}, {%4,%5,%6,%7}, {%8,%9}, {%0,%1,%2,%3};"
        : "+f"(d[0]), "+f"(d[1]), "+f"(d[2]), "+f"(d[3])
        : "r"(a[0]), "r"(a[1]), "r"(a[2]), "r"(a[3]), "r"(b[0]), "r"(b[1]));
}

// ------------------------- scratch (device globals) -------------------------
__device__ float g_gx[(size_t)T_ * N_ * G3];
__device__ __nv_bfloat16 g_out0hi[(size_t)T_ * N_ * H_];
__device__ __nv_bfloat16 g_out0lo[(size_t)T_ * N_ * H_];
__device__ float g_xh[N_ * H_];
__device__ float g_xhT[H_ * N_];
__device__ float g_den[C_];
__device__ float g_s2c[(size_t)N_ * C_];
__device__ float g_s2cT[(size_t)C_ * N_];
__device__ float g_hidC[C_ * H_];
__device__ float g_v1[C_];
__device__ float g_logits[(size_t)C_ * N_];
__device__ float g_hid2[C_ * H_];
__device__ float g_hid2T[H_ * C_];
__device__ float g_nx[N_];
__device__ float g_ny[C_];
__device__ float g_c2s[(size_t)N_ * C_];
__device__ float g_tmp[N_ * H_];
__device__ float g_ps[N_ * H_];
__device__ float g_hsh[N_ * H_];
__device__ float g_outps[N_ * H_];
__device__ float g_nh[N_];
__device__ float g_diag[N_];
__device__ float g_big[(size_t)N_ * N_];
__device__ float g_kpart[(size_t)32 * 4096 * H_];
__device__ int   g_colcnt[N_];
__device__ int   g_kidx[N_ * 10];
__device__ float g_kval[N_ * 10];
__device__ long long g_hacc[N_ * H_];
__device__ float g_hidH[N_ * H_];
__device__ float g_hidHT[H_ * N_];
__device__ float g_v2[N_];
__device__ float g_nhh[N_];
__device__ float g_hsi[N_ * H_];
__device__ float g_indi[N_ * H_];
__device__ float g_ouths[N_ * H_];
__device__ float g_outindi[N_ * H_];

// ==================== HMMA GRU layer (512 thr / 16 warps, double-buffered h) ====
#define GRU_W_BYTES 98304
#define GRU_HB_STRIDE 136
#define GRU_HB_BYTES (32 * GRU_HB_STRIDE * 2)
#define GRU_SMEM (2 * GRU_W_BYTES + 4 * GRU_HB_BYTES)

__global__ __launch_bounds__(512, 1) void gru_mma(
    const float* __restrict__ gx, const float* __restrict__ whh,
    const float* __restrict__ bhh, float* __restrict__ outF,
    __nv_bfloat16* __restrict__ outHi, __nv_bfloat16* __restrict__ outLo,
    int write_all)
{
    extern __shared__ __align__(16) char gsm[];
    char* Wlo = gsm + GRU_W_BYTES;
    char* Hbase = gsm + 2 * GRU_W_BYTES;
    const int tid = threadIdx.x, lane = tid & 31, wp = tid >> 5;
    const int n0 = blockIdx.x * 32;
    const int jb = wp * 8;

    for (int idx = tid; idx < 384 * 16; idx += 512) {
        int n = idx >> 4, g8 = idx & 15;
        const float* src = whh + n * 128 + g8 * 8;
        float4 v0 = *(const float4*)src;
        float4 v1 = *(const float4*)(src + 4);
        float f[8] = {v0.x, v0.y, v0.z, v0.w, v1.x, v1.y, v1.z, v1.w};
        uint32_t hw[4], lw[4];
#pragma unroll
        for (int q = 0; q < 4; ++q) {
            __nv_bfloat16 h0 = __float2bfloat16(f[2 * q]);
            __nv_bfloat16 h1 = __float2bfloat16(f[2 * q + 1]);
            __nv_bfloat162 hp = __halves2bfloat162(h0, h1);
            __nv_bfloat162 lp = __halves2bfloat162(
                __float2bfloat16(f[2 * q] - __bfloat162float(h0)),
                __float2bfloat16(f[2 * q + 1] - __bfloat162float(h1)));
            hw[q] = *(uint32_t*)&hp;
            lw[q] = *(uint32_t*)&lp;
        }
        int off = n * 256 + ((g8 ^ (n & 7)) << 4);
        *(uint4*)(gsm + off) = make_uint4(hw[0], hw[1], hw[2], hw[3]);
        *(uint4*)(Wlo + off) = make_uint4(lw[0], lw[1], lw[2], lw[3]);
    }
    for (int idx = tid; idx < (4 * GRU_HB_BYTES) / 4; idx += 512)
        ((uint32_t*)Hbase)[idx] = 0;

    const int col0 = jb + 2 * (lane & 3);
    const int rbase = lane >> 2;
    float bR0 = bhh[col0], bR1 = bhh[col0 + 1];
    float bZ0 = bhh[128 + col0], bZ1 = bhh[128 + col0 + 1];
    float bN0 = bhh[256 + col0], bN1 = bhh[256 + col0 + 1];

    const uint32_t sb = smem_u32_(gsm);
    const uint32_t hB = sb + 2 * GRU_W_BYTES;
    const uint32_t aoff = (uint32_t)((lane & 15) * (GRU_HB_STRIDE * 2) + (lane >> 4) * 16);
    const int nRZ = ((lane >> 4) ? 128 + jb : jb) + (lane & 7);
    const uint32_t bRZ_base = sb + nRZ * 256;
    const uint32_t nlowRZ = (uint32_t)(nRZ & 7);
    const int nN = 256 + jb + (lane & 7);
    const uint32_t bN_base = sb + nN * 256;
    const uint32_t nlowN = (uint32_t)(nN & 7);
    const uint32_t ghalf = (uint32_t)((lane >> 3) & 1);

    float hold[4][2];
#pragma unroll
    for (int i = 0; i < 4; ++i) { hold[i][0] = 0.f; hold[i][1] = 0.f; }

    __syncthreads();

    for (int t = 0; t < T_; ++t) {
        const int rb = t & 1;
        const uint32_t aHi = hB + (uint32_t)(rb * 2 * GRU_HB_BYTES);
        const uint32_t aLo = aHi + GRU_HB_BYTES;
        __nv_bfloat16* Whi_w = (__nv_bfloat16*)(Hbase + (rb ^ 1) * 2 * GRU_HB_BYTES);
        __nv_bfloat16* Wlo_w = (__nv_bfloat16*)((char*)Whi_w + GRU_HB_BYTES);

        const float* gbase = gx + ((size_t)t * N_ + n0) * G3;
        float2 gR[4], gZ[4], gN[4];
#pragma unroll
        for (int ridx = 0; ridx < 4; ++ridx) {
            int row = (ridx >> 1) * 16 + (ridx & 1) * 8 + rbase;
            const float* gp = gbase + row * G3 + col0;
            gR[ridx] = *(const float2*)(gp);
            gZ[ridx] = *(const float2*)(gp + 128);
            gN[ridx] = *(const float2*)(gp + 256);
        }

        float acc[2][3][4];
#pragma unroll
        for (int i = 0; i < 2; ++i)
#pragma unroll
            for (int g = 0; g < 3; ++g)
#pragma unroll
                for (int q = 0; q < 4; ++q) acc[i][g][q] = 0.f;

#pragma unroll 2
        for (int kc = 0; kc < 8; ++kc) {
            uint32_t gsw = (uint32_t)(kc * 2);
            uint32_t addrRZ = bRZ_base + (((gsw + ghalf) ^ nlowRZ) << 4);
            uint32_t addrN = bN_base + (((gsw + ghalf) ^ nlowN) << 4);
            uint32_t bhiRZ[4], bloRZ[4], bhiN[2], bloN[2];
            ldsm4_(bhiRZ, addrRZ);
            ldsm4_(bloRZ, addrRZ + GRU_W_BYTES);
            ldsm2_(bhiN, addrN);
            ldsm2_(bloN, addrN + GRU_W_BYTES);
            uint32_t ahi[2][4], alo[2][4];
#pragma unroll
            for (int i = 0; i < 2; ++i) {
                uint32_t aa = aoff + (uint32_t)(i * 16 * GRU_HB_STRIDE * 2 + kc * 32);
                ldsm4_(ahi[i], aHi + aa);
                ldsm4_(alo[i], aLo + aa);
            }
#pragma unroll
            for (int i = 0; i < 2; ++i) {
                mma_bf16_(acc[i][0], ahi[i], bhiRZ);
                mma_bf16_(acc[i][0], alo[i], bhiRZ);
                mma_bf16_(acc[i][0], ahi[i], bloRZ);
                mma_bf16_(acc[i][1], ahi[i], bhiRZ + 2);
                mma_bf16_(acc[i][1], alo[i], bhiRZ + 2);
                mma_bf16_(acc[i][1], ahi[i], bloRZ + 2);
                mma_bf16_(acc[i][2], ahi[i], bhiN);
                mma_bf16_(acc[i][2], alo[i], bhiN);
                mma_bf16_(acc[i][2], ahi[i], bloN);
            }
        }

#pragma unroll
        for (int ridx = 0; ridx < 4; ++ridx) {
            int i = ridx >> 1, q0 = (ridx & 1) * 2;
            int row = (ridx >> 1) * 16 + (ridx & 1) * 8 + rbase;
            float rr0 = fsig_(gR[ridx].x + acc[i][0][q0] + bR0);
            float rr1 = fsig_(gR[ridx].y + acc[i][0][q0 + 1] + bR1);
            float zz0 = fsig_(gZ[ridx].x + acc[i][1][q0] + bZ0);
            float zz1 = fsig_(gZ[ridx].y + acc[i][1][q0 + 1] + bZ1);
            float nc0 = ftanh_(gN[ridx].x + rr0 * (acc[i][2][q0] + bN0));
            float nc1 = ftanh_(gN[ridx].y + rr1 * (acc[i][2][q0 + 1] + bN1));
            float h0 = (1.f - zz0) * nc0 + zz0 * hold[ridx][0];
            float h1 = (1.f - zz1) * nc1 + zz1 * hold[ridx][1];
            hold[ridx][0] = h0; hold[ridx][1] = h1;
            __nv_bfloat16 hh0 = __float2bfloat16(h0);
            __nv_bfloat16 hh1 = __float2bfloat16(h1);
            __nv_bfloat162 hp = __halves2bfloat162(hh0, hh1);
            __nv_bfloat162 lp = __halves2bfloat162(
                __float2bfloat16(h0 - __bfloat162float(hh0)),
                __float2bfloat16(h1 - __bfloat162float(hh1)));
            *(__nv_bfloat162*)&Whi_w[row * GRU_HB_STRIDE + col0] = hp;
            *(__nv_bfloat162*)&Wlo_w[row * GRU_HB_STRIDE + col0] = lp;
            if (write_all) {
                size_t gb = ((size_t)t * N_ + n0 + row) * H_ + col0;
                *(__nv_bfloat162*)&outHi[gb] = hp;
                *(__nv_bfloat162*)&outLo[gb] = lp;
            }
        }
        __syncthreads();
    }
    if (!write_all) {
#pragma unroll
        for (int ridx = 0; ridx < 4; ++ridx) {
            int row = (ridx >> 1) * 16 + (ridx & 1) * 8 + rbase;
            *(float2*)&outF[(size_t)(n0 + row) * H_ + col0] =
                make_float2(hold[ridx][0], hold[ridx][1]);
        }
    }
}

// ==================== mma.sync bf16-split NT GEMMs ====================
#define MM_PAD 136
#define MM_TILE_BYTES (128 * MM_PAD * 2)
#define MM_SMEM (4 * MM_TILE_BYTES)

__device__ __forceinline__ void cvt_split_(float4 v, uint2& hw, uint2& lw) {
    __nv_bfloat16 h0 = __float2bfloat16(v.x), h1 = __float2bfloat16(v.y);
    __nv_bfloat16 h2 = __float2bfloat16(v.z), h3 = __float2bfloat16(v.w);
    __nv_bfloat162 hp0 = __halves2bfloat162(h0, h1);
    __nv_bfloat162 hp1 = __halves2bfloat162(h2, h3);
    __nv_bfloat162 lp0 = __halves2bfloat162(
        __float2bfloat16(v.x - __bfloat162float(h0)),
        __float2bfloat16(v.y - __bfloat162float(h1)));
    __nv_bfloat162 lp1 = __halves2bfloat162(
        __float2bfloat16(v.z - __bfloat162float(h2)),
        __float2bfloat16(v.w - __bfloat162float(h3)));
    hw.x = *(uint32_t*)&hp0; hw.y = *(uint32_t*)&hp1;
    lw.x = *(uint32_t*)&lp0; lw.y = *(uint32_t*)&lp1;
}

template <int EPI>
__device__ __forceinline__ float mepi_(float v, int row, int col,
                                       const float* e1, const float* e2)
{
    if (EPI == 1) v += e1[col];
    if (EPI == 4) {
        v = v / fmaxf(e1[row] * e2[col], 1e-12f);
        if (row == col) v = 0.f;
    }
    return v;
}

template <int EPI>
__device__ __forceinline__ void mm_core_(char* msm, float* __restrict__ Cm,
                                         int bm, int bn, int Nn,
                                         const float* e1, const float* e2)
{
    const int tid = threadIdx.x, lane = tid & 31, wid = tid >> 5;
    const uint32_t sb = smem_u32_(msm);
    const int m0 = (wid >> 2) * 64, n0 = (wid & 3) * 32;
    const uint32_t aRow = (uint32_t)((m0 + (lane & 15)) * MM_PAD * 2 + (lane >> 4) * 16);
    const uint32_t bRow = (uint32_t)((n0 + (lane & 7)) * MM_PAD * 2 + ((lane >> 3) & 1) * 16);

    float acc[4][4][4];
#pragma unroll
    for (int i = 0; i < 4; ++i)
#pragma unroll
        for (int j = 0; j < 4; ++j)
#pragma unroll
            for (int q = 0; q < 4; ++q) acc[i][j][q] = 0.f;

#pragma unroll
    for (int p = 0; p < 3; ++p) {
        const uint32_t aB = sb + (p == 1 ? MM_TILE_BYTES : 0) + aRow;
        const uint32_t bB = sb + 2 * MM_TILE_BYTES + (p == 2 ? MM_TILE_BYTES : 0) + bRow;
#pragma unroll
        for (int k0 = 0; k0 < 128; k0 += 16) {
            uint32_t af[4][4], bf[4][2];
#pragma unroll
            for (int i = 0; i < 4; ++i) ldsm4_(af[i], aB + i * 16 * MM_PAD * 2 + k0 * 2);
#pragma unroll
            for (int j = 0; j < 4; ++j) ldsm2_(bf[j], bB + j * 8 * MM_PAD * 2 + k0 * 2);
#pragma unroll
            for (int i = 0; i < 4; ++i)
#pragma unroll
                for (int j = 0; j < 4; ++j) mma_bf16_(acc[i][j], af[i], bf[j]);
        }
    }

    const int tr = lane >> 2, tc = (lane & 3) * 2;
#pragma unroll
    for (int i = 0; i < 4; ++i) {
#pragma unroll
        for (int j = 0; j < 4; ++j) {
            int row = bm + m0 + i * 16 + tr;
            int col = bn + n0 + j * 8 + tc;
            float2 v0, v1;
            v0.x = mepi_<EPI>(acc[i][j][0], row, col, e1, e2);
            v0.y = mepi_<EPI>(acc[i][j][1], row, col + 1, e1, e2);
            v1.x = mepi_<EPI>(acc[i][j][2], row + 8, col, e1, e2);
            v1.y = mepi_<EPI>(acc[i][j][3], row + 8, col + 1, e1, e2);
            *(float2*)&Cm[(size_t)row * Nn + col] = v0;
            *(float2*)&Cm[(size_t)(row + 8) * Nn + col] = v1;
        }
    }
}

template <int EPI>
__global__ __launch_bounds__(256, 1) void mmagemm(
    const float* __restrict__ A, const float* __restrict__ B, float* __restrict__ Cm,
    int M, int Nn, const float* __restrict__ e1, const float* __restrict__ e2)
{
    extern __shared__ __align__(16) char msm[];
    __nv_bfloat16* Ah = (__nv_bfloat16*)msm;
    __nv_bfloat16* Al = (__nv_bfloat16*)(msm + MM_TILE_BYTES);
    __nv_bfloat16* Bh = (__nv_bfloat16*)(msm + 2 * MM_TILE_BYTES);
    __nv_bfloat16* Bl = (__nv_bfloat16*)(msm + 3 * MM_TILE_BYTES);
    const int tid = threadIdx.x;
    const int bm = blockIdx.y * 128, bn = blockIdx.x * 128;

    {
        const float* Ab = A + (size_t)bm * 128;
        const float* Bb = B + (size_t)bn * 128;
        for (int idx = tid; idx < 128 * 32; idx += 256) {
            int row = idx >> 5, q = (idx & 31) << 2;
            uint2 hw, lw;
            cvt_split_(*(const float4*)&Ab[row * 128 + q], hw, lw);
            *(uint2*)&Ah[row * MM_PAD + q] = hw;
            *(uint2*)&Al[row * MM_PAD + q] = lw;
            cvt_split_(*(const float4*)&Bb[row * 128 + q], hw, lw);
            *(uint2*)&Bh[row * MM_PAD + q] = hw;
            *(uint2*)&Bl[row * MM_PAD + q] = lw;
        }
    }
    __syncthreads();
    mm_core_<EPI>(msm, Cm, bm, bn, Nn, e1, e2);
}

// variant: A pre-split (bf16 hi/lo planes), B fp32
__global__ __launch_bounds__(256, 1) void mmagemm_pre(
    const __nv_bfloat16* __restrict__ Ahi_g, const __nv_bfloat16* __restrict__ Alo_g,
    const float* __restrict__ B, float* __restrict__ Cm,
    int M, int Nn, const float* __restrict__ e1)
{
    extern __shared__ __align__(16) char msm[];
    __nv_bfloat16* Ah = (__nv_bfloat16*)msm;
    __nv_bfloat16* Al = (__nv_bfloat16*)(msm + MM_TILE_BYTES);
    __nv_bfloat16* Bh = (__nv_bfloat16*)(msm + 2 * MM_TILE_BYTES);
    __nv_bfloat16* Bl = (__nv_bfloat16*)(msm + 3 * MM_TILE_BYTES);
    const int tid = threadIdx.x;
    const int bm = blockIdx.y * 128, bn = blockIdx.x * 128;

    for (int idx = tid; idx < 128 * 16; idx += 256) {
        int row = idx >> 4, q = (idx & 15) << 3;
        *(uint4*)&Ah[row * MM_PAD + q] = *(const uint4*)&Ahi_g[((size_t)bm + row) * 128 + q];
        *(uint4*)&Al[row * MM_PAD + q] = *(const uint4*)&Alo_g[((size_t)bm + row) * 128 + q];
    }
    {
        const float* Bb = B + (size_t)bn * 128;
        for (int idx = tid; idx < 128 * 32; idx += 256) {
            int row = idx >> 5, q = (idx & 31) << 2;
            uint2 hw, lw;
            cvt_split_(*(const float4*)&Bb[row * 128 + q], hw, lw);
            *(uint2*)&Bh[row * MM_PAD + q] = hw;
            *(uint2*)&Bl[row * MM_PAD + q] = lw;
        }
    }
    __syncthreads();
    mm_core_<1>(msm, Cm, bm, bn, Nn, e1, nullptr);
}

// K-loop split-K HMMA NT GEMM: partials -> part[z]. A[M,K], B[N,K] row-major.
__global__ __launch_bounds__(256, 1) void mmagemm_k(
    const float* __restrict__ A, const float* __restrict__ B, float* __restrict__ part,
    int M, int Nn, int K, int Kchunk)
{
    extern __shared__ __align__(16) char msm[];
    __nv_bfloat16* Ah = (__nv_bfloat16*)msm;
    __nv_bfloat16* Al = (__nv_bfloat16*)(msm + MM_TILE_BYTES);
    __nv_bfloat16* Bh = (__nv_bfloat16*)(msm + 2 * MM_TILE_BYTES);
    __nv_bfloat16* Bl = (__nv_bfloat16*)(msm + 3 * MM_TILE_BYTES);
    const int tid = threadIdx.x, lane = tid & 31, wid = tid >> 5;
    const int bm = blockIdx.y * 128, bn = blockIdx.x * 128;
    const int kb = blockIdx.z * Kchunk;

    const uint32_t sb = smem_u32_(msm);
    const int m0 = (wid >> 2) * 64, n0 = (wid & 3) * 32;
    const uint32_t aRow = (uint32_t)((m0 + (lane & 15)) * MM_PAD * 2 + (lane >> 4) * 16);
    const uint32_t bRow = (uint32_t)((n0 + (lane & 7)) * MM_PAD * 2 + ((lane >> 3) & 1) * 16);

    float acc[4][4][4];
#pragma unroll
    for (int i = 0; i < 4; ++i)
#pragma unroll
        for (int j = 0; j < 4; ++j)
#pragma unroll
            for (int q = 0; q < 4; ++q) acc[i][j][q] = 0.f;

    for (int kc = kb; kc < kb + Kchunk; kc += 128) {
        for (int idx = tid; idx < 128 * 32; idx += 256) {
            int row = idx >> 5, q = (idx & 31) << 2;
            uint2 hw, lw;
            cvt_split_(*(const float4*)&A[(size_t)(bm + row) * K + kc + q], hw, lw);
            *(uint2*)&Ah[row * MM_PAD + q] = hw;
            *(uint2*)&Al[row * MM_PAD + q] = lw;
            cvt_split_(*(const float4*)&B[(size_t)(bn + row) * K + kc + q], hw, lw);
            *(uint2*)&Bh[row * MM_PAD + q] = hw;
            *(uint2*)&Bl[row * MM_PAD + q] = lw;
        }
        __syncthreads();
#pragma unroll
        for (int p = 0; p < 3; ++p) {
            const uint32_t aB = sb + (p == 1 ? MM_TILE_BYTES : 0) + aRow;
            const uint32_t bB = sb + 2 * MM_TILE_BYTES + (p == 2 ? MM_TILE_BYTES : 0) + bRow;
#pragma unroll
            for (int k0 = 0; k0 < 128; k0 += 16) {
                uint32_t af[4][4], bf[4][2];
#pragma unroll
                for (int i = 0; i < 4; ++i) ldsm4_(af[i], aB + i * 16 * MM_PAD * 2 + k0 * 2);
#pragma unroll
                for (int j = 0; j < 4; ++j) ldsm2_(bf[j], bB + j * 8 * MM_PAD * 2 + k0 * 2);
#pragma unroll
                for (int i = 0; i < 4; ++i)
#pragma unroll
                    for (int j = 0; j < 4; ++j) mma_bf16_(acc[i][j], af[i], bf[j]);
            }
        }
        __syncthreads();
    }

    float* obase = part + (size_t)blockIdx.z * M * Nn;
    const int tr = lane >> 2, tc = (lane & 3) * 2;
#pragma unroll
    for (int i = 0; i < 4; ++i) {
#pragma unroll
        for (int j = 0; j < 4; ++j) {
            int row = bm + m0 + i * 16 + tr;
            int col = bn + n0 + j * 8 + tc;
            *(float2*)&obase[(size_t)row * Nn + col] =
                make_float2(acc[i][j][0], acc[i][j][1]);
            *(float2*)&obase[(size_t)(row + 8) * Nn + col] =
                make_float2(acc[i][j][2], acc[i][j][3]);
        }
    }
}

__global__ void kreduce(const float* __restrict__ part, int S, size_t MN,
                        float* __restrict__ out)
{
    size_t i4 = ((size_t)blockIdx.x * 256 + threadIdx.x) * 4;
    if (i4 >= MN) return;
    float4 s = *(const float4*)&part[i4];
    for (int z = 1; z < S; ++z) {
        float4 v = *(const float4*)&part[(size_t)z * MN + i4];
        s.x += v.x; s.y += v.y; s.z += v.z; s.w += v.w;
    }
    *(float4*)&out[i4] = s;
}

// ------------------------- tiled transpose -------------------------
__global__ void transpose32(const float* __restrict__ in, float* __restrict__ out,
                            int rows, int cols)
{
    __shared__ float t[32][33];
    int c0 = blockIdx.x * 32, r0 = blockIdx.y * 32;
    int tx = threadIdx.x, ty = threadIdx.y;
    for (int i = ty; i < 32; i += 8)
        t[i][tx] = in[(size_t)(r0 + i) * cols + c0 + tx];
    __syncthreads();
    for (int i = ty; i < 32; i += 8)
        out[(size_t)(c0 + i) * rows + r0 + tx] = t[tx][i];
}

// ------------------------- gx0 -------------------------
__global__ void gx0_kernel(const float* __restrict__ x, const float* __restrict__ wih,
                           const float* __restrict__ bih, float* __restrict__ gx)
{
    __shared__ float xs[32 * D_];
    const int t = blockIdx.x;
    const int n0 = blockIdx.y * 32;
    const int g = threadIdx.x;
    for (int idx = g; idx < 32 * D_; idx += G3) {
        int r = idx / D_, d = idx - r * D_;
        xs[idx] = x[(size_t)(n0 + r) * (D_ * T_) + d * T_ + t];
    }
    float wr[D_];
#pragma unroll
    for (int d = 0; d < D_; ++d) wr[d] = wih[g * D_ + d];
    const float b = bih[g];
    __syncthreads();
    for (int r = 0; r < 32; ++r) {
        const float4* xp = (const float4*)&xs[r * D_];
        float acc = b;
#pragma unroll
        for (int q = 0; q < 5; ++q) {
            float4 v = xp[q];
            acc += v.x * wr[q * 4 + 0] + v.y * wr[q * 4 + 1] +
                   v.z * wr[q * 4 + 2] + v.w * wr[q * 4 + 3];
        }
        gx[((size_t)t * N_ + n0 + r) * G3 + g] = acc;
    }
}

// ------------------------- 128x128 f32x2 SGEMM (NT, K=128 chain GEMMs) --------
template <int EPI>
__device__ __forceinline__ float epi_apply(float v, int row, int col, int Nn,
                                           const float* e1, const float* e2)
{
    if (EPI == 1) v += e1[col];
    if (EPI == 2) { v += e1[col]; v = v > 0.f ? v : 0.01f * v; }
    if (EPI == 3) { v += e1[col]; v = e2[(size_t)row * Nn + col] - v; }
    return v;
}

template <int TR, int EPI>
__global__ __launch_bounds__(256, 2) void sgemm128(
    const float* __restrict__ A, const float* __restrict__ B, float* __restrict__ Cm,
    int M, int Nn, int K, int Ksplit,
    const float* __restrict__ e1, const float* __restrict__ e2,
    float* __restrict__ part)
{
    __shared__ __align__(16) float As[16][136];
    __shared__ __align__(16) float Bs[16][136];
    const int bm = blockIdx.y * 128, bn = blockIdx.x * 128;
    const int z = blockIdx.z;
    const int kb = z * Ksplit, ke = kb + Ksplit;
    const int tid = threadIdx.x;
    const int tx = tid & 15, ty = tid >> 4;
    u64 acc[4][8];
#pragma unroll
    for (int i = 0; i < 4; ++i)
#pragma unroll
        for (int j = 0; j < 8; ++j) acc[i][j] = 0ull;

    for (int k0 = kb; k0 < ke; k0 += 16) {
        if (TR == 2) {
            int k = tid >> 4, m = (tid & 15) << 3;
            const float* src = &A[(size_t)(k0 + k) * M + bm + m];
            *(float4*)&As[k][m]     = *(const float4*)(src);
            *(float4*)&As[k][m + 4] = *(const float4*)(src + 4);
        } else {
            int m = tid >> 1, kq = (tid & 1) << 3;
            const float* src = &A[(size_t)(bm + m) * K + k0 + kq];
            float4 v0 = *(const float4*)(src);
            float4 v1 = *(const float4*)(src + 4);
            As[kq + 0][m] = v0.x; As[kq + 1][m] = v0.y;
            As[kq + 2][m] = v0.z; As[kq + 3][m] = v0.w;
            As[kq + 4][m] = v1.x; As[kq + 5][m] = v1.y;
            As[kq + 6][m] = v1.z; As[kq + 7][m] = v1.w;
        }
        if (TR == 1) {
            int n = tid >> 1, kq = (tid & 1) << 3;
            const float* src = &B[(size_t)(bn + n) * K + k0 + kq];
            float4 v0 = *(const float4*)(src);
            float4 v1 = *(const float4*)(src + 4);
            Bs[kq + 0][n] = v0.x; Bs[kq + 1][n] = v0.y;
            Bs[kq + 2][n] = v0.z; Bs[kq + 3][n] = v0.w;
            Bs[kq + 4][n] = v1.x; Bs[kq + 5][n] = v1.y;
            Bs[kq + 6][n] = v1.z; Bs[kq + 7][n] = v1.w;
        } else {
            int k = tid >> 4, n = (tid & 15) << 3;
            const float* src = &B[(size_t)(k0 + k) * Nn + bn + n];
            *(float4*)&Bs[k][n]     = *(const float4*)(src);
            *(float4*)&Bs[k][n + 4] = *(const float4*)(src + 4);
        }
        __syncthreads();
#pragma unroll
        for (int kk = 0; kk < 16; ++kk) {
            ulonglong2 a01 = *(const ulonglong2*)&As[kk][ty << 3];
            ulonglong2 a23 = *(const ulonglong2*)&As[kk][(ty << 3) + 4];
            float4 b0 = *(const float4*)&Bs[kk][tx << 2];
            float4 b1 = *(const float4*)&Bs[kk][64 + (tx << 2)];
            u64 ar[4] = {a01.x, a01.y, a23.x, a23.y};
            u64 bd[8];
            bd[0] = pack2_(b0.x); bd[1] = pack2_(b0.y);
            bd[2] = pack2_(b0.z); bd[3] = pack2_(b0.w);
            bd[4] = pack2_(b1.x); bd[5] = pack2_(b1.y);
            bd[6] = pack2_(b1.z); bd[7] = pack2_(b1.w);
#pragma unroll
            for (int rp = 0; rp < 4; ++rp)
#pragma unroll
                for (int c = 0; c < 8; ++c) fma2_(acc[rp][c], ar[rp], bd[c]);
        }
        __syncthreads();
    }

    const bool partial = (gridDim.z > 1);
    float* obase = partial ? part + (size_t)z * M * Nn : Cm;
#pragma unroll
    for (int rp = 0; rp < 4; ++rp) {
        float lo[8], hi[8];
#pragma unroll
        for (int c = 0; c < 8; ++c) unpack2_(acc[rp][c], lo[c], hi[c]);
        int row0 = bm + (ty << 3) + rp * 2;
#pragma unroll
        for (int h = 0; h < 2; ++h) {
            int row = row0 + h;
            float* vv = h ? hi : lo;
            int colA = bn + (tx << 2);
            int colB = bn + 64 + (tx << 2);
            float4 oA, oB;
            if (!partial) {
                oA.x = epi_apply<EPI>(vv[0], row, colA + 0, Nn, e1, e2);
                oA.y = epi_apply<EPI>(vv[1], row, colA + 1, Nn, e1, e2);
                oA.z = epi_apply<EPI>(vv[2], row, colA + 2, Nn, e1, e2);
                oA.w = epi_apply<EPI>(vv[3], row, colA + 3, Nn, e1, e2);
                oB.x = epi_apply<EPI>(vv[4], row, colB + 0, Nn, e1, e2);
                oB.y = epi_apply<EPI>(vv[5], row, colB + 1, Nn, e1, e2);
                oB.z = epi_apply<EPI>(vv[6], row, colB + 2, Nn, e1, e2);
                oB.w = epi_apply<EPI>(vv[7], row, colB + 3, Nn, e1, e2);
            } else {
                oA = make_float4(vv[0], vv[1], vv[2], vv[3]);
                oB = make_float4(vv[4], vv[5], vv[6], vv[7]);
            }
            *(float4*)&obase[(size_t)row * Nn + colA] = oA;
            *(float4*)&obase[(size_t)row * Nn + colB] = oB;
        }
    }
}

// ------------------------- reductions / elementwise -------------------------
__global__ void colsum_part(const float* __restrict__ m, const float* __restrict__ w,
                            int rows, int cols, float* __restrict__ part)
{
    int c = blockIdx.x * 256 + threadIdx.x;
    int chunk = rows / gridDim.y;
    int r0 = blockIdx.y * chunk;
    float acc = 0.f;
    for (int r = r0; r < r0 + chunk; ++r)
        acc += m[(size_t)r * cols + c] * (w ? w[r] : 1.f);
    part[(size_t)blockIdx.y * cols + c] = acc;
}
__global__ void colsum_reduce(const float* __restrict__ part, int nb, int cols,
                              float* __restrict__ out)
{
    int c = blockIdx.x * 256 + threadIdx.x;
    float a = 0.f;
    for (int b = 0; b < nb; ++b) a += part[(size_t)b * cols + c];
    out[c] = a;
}

__global__ void s2c_kernel(const float* __restrict__ cm, const float* __restrict__ mv,
                           const float* __restrict__ den, float* __restrict__ s2c)
{
    int e = blockIdx.x * 256 + threadIdx.x;
    if (e >= N_ * C_) return;
    int i = e >> 9, c = e & (C_ - 1);
    float cv = cm[e];
    s2c[e] = cv * mv[i] / (den[c] * cv + 1.f);
}

__global__ void rownorm(const float* __restrict__ x, int cols,
                        float* __restrict__ nrm, float* __restrict__ vflag,
                        float* __restrict__ dg)
{
    int row = blockIdx.x * 8 + (threadIdx.x >> 5);
    int lane = threadIdx.x & 31;
    const float* p = x + (size_t)row * cols;
    float s = 0.f, q = 0.f;
    for (int c = lane; c < cols; c += 32) { float v = p[c]; s += v; q += v * v; }
#pragma unroll
    for (int o = 16; o; o >>= 1) {
        s += __shfl_xor_sync(0xffffffffu, s, o);
        q += __shfl_xor_sync(0xffffffffu, q, o);
    }
    if (lane == 0) {
        if (nrm) nrm[row] = sqrtf(q);
        if (vflag) vflag[row] = (s != 0.f) ? 1.f : 0.f;
        if (dg) { float d = sqrtf(q) * sqrtf(q); dg[row] = q / fmaxf(d, 1e-12f); }
    }
}

// 512-thread row softmax
__global__ __launch_bounds__(512, 1) void row_softmax(
    float* __restrict__ m, int width,
    const float* __restrict__ rs, const float* __restrict__ cs,
    const float* __restrict__ vm)
{
    extern __shared__ float sv[];
    __shared__ float red[16];
    __shared__ float smx, ssum;
    const int tid = threadIdx.x, lane = tid & 31, wid = tid >> 5;
    const size_t base = (size_t)blockIdx.x * width;
    const float rsv = rs ? rs[blockIdx.x] : 0.f;
    float lmax = -3.0e38f;
    for (int j = tid; j < width; j += 512) {
        float v = m[base + j];
        if (rs) v = v / fmaxf(rsv * cs[j], 1e-12f);
        if (vm && vm[j] == 0.f) v = -3.0e38f;
        sv[j] = v;
        lmax = fmaxf(lmax, v);
    }
#pragma unroll
    for (int o = 16; o; o >>= 1) lmax = fmaxf(lmax, __shfl_xor_sync(0xffffffffu, lmax, o));
    if (lane == 0) red[wid] = lmax;
    __syncthreads();
    if (tid == 0) {
        float v = red[0];
        for (int w = 1; w < 16; ++w) v = fmaxf(v, red[w]);
        smx = v;
    }
    __syncthreads();
    const float mx = smx;
    float lsum = 0.f;
    for (int j = tid; j < width; j += 512) {
        float e = __expf(sv[j] - mx);
        sv[j] = e;
        lsum += e;
    }
#pragma unroll
    for (int o = 16; o; o >>= 1) lsum += __shfl_xor_sync(0xffffffffu, lsum, o);
    if (lane == 0) red[wid] = lsum;
    __syncthreads();
    if (tid == 0) {
        float v = 0.f;
        for (int w = 0; w < 16; ++w) v += red[w];
        ssum = v;
    }
    __syncthreads();
    const float inv = 1.f / ssum;
    for (int j = tid; j < width; j += 512) {
        float o = sv[j] * inv;
        if (vm) o = (vm[j] != 0.f) ? o : 0.f;
        m[base + j] = o;
    }
}

// ------------------------- top-10 store -------------------------
__global__ __launch_bounds__(512, 1) void topk_store(
    const float* __restrict__ m, int* __restrict__ colcnt,
    int* __restrict__ kidx, float* __restrict__ kval)
{
    __shared__ float vals[N_];
    __shared__ float cval[160];
    __shared__ int cidx[160];
    __shared__ int keep[10];
    __shared__ float keepv[10];
    const int tid = threadIdx.x, lane = tid & 31, wid = tid >> 5;
    const size_t base = (size_t)blockIdx.x * N_;

    for (int j = tid; j < N_; j += 512) vals[j] = m[base + j];
    __syncthreads();

    {
        const int cbase = wid * 256 + lane * 8;
        float v[8];
#pragma unroll
        for (int i = 0; i < 8; ++i) v[i] = vals[cbase + i];
        for (int s = 0; s < 10; ++s) {
            float bv = v[0]; int bs = 0;
#pragma unroll
            for (int i = 1; i < 8; ++i)
                if (v[i] > bv) { bv = v[i]; bs = i; }
            int bi = cbase + bs;
#pragma unroll
            for (int o = 16; o; o >>= 1) {
                float ov = __shfl_down_sync(0xffffffffu, bv, o);
                int oi = __shfl_down_sync(0xffffffffu, bi, o);
                if (ov > bv || (ov == bv && oi < bi)) { bv = ov; bi = oi; }
            }
            bv = __shfl_sync(0xffffffffu, bv, 0);
            bi = __shfl_sync(0xffffffffu, bi, 0);
            if (lane == 0) { cval[wid * 10 + s] = bv; cidx[wid * 10 + s] = bi; }
            if (bi >= cbase && bi < cbase + 8) v[bi - cbase] = -3.0e38f;
        }
    }
    __syncthreads();

    if (wid == 0) {
        float v[5]; int gi[5];
#pragma unroll
        for (int i = 0; i < 5; ++i) {
            v[i] = cval[lane * 5 + i];
            gi[i] = cidx[lane * 5 + i];
        }
        for (int s = 0; s < 10; ++s) {
            float bv = v[0]; int bi = gi[0], bs = 0;
#pragma unroll
            for (int i = 1; i < 5; ++i)
                if (v[i] > bv || (v[i] == bv && gi[i] < bi)) { bv = v[i]; bi = gi[i]; bs = i; }
            int slot = lane * 5 + bs;
#pragma unroll
            for (int o = 16; o; o >>= 1) {
                float ov = __shfl_down_sync(0xffffffffu, bv, o);
                int oi = __shfl_down_sync(0xffffffffu, bi, o);
                int os = __shfl_down_sync(0xffffffffu, slot, o);
                if (ov > bv || (ov == bv && oi < bi)) { bv = ov; bi = oi; slot = os; }
            }
            bv = __shfl_sync(0xffffffffu, bv, 0);
            bi = __shfl_sync(0xffffffffu, bi, 0);
            slot = __shfl_sync(0xffffffffu, slot, 0);
            if (lane == 0) { keep[s] = bi; keepv[s] = bv; }
            if (slot >= lane * 5 && slot < lane * 5 + 5) v[slot - lane * 5] = -3.0e38f;
        }
        if (lane < 10) {
            atomicAdd(&colcnt[keep[lane]], 1);
            kidx[blockIdx.x * 10 + lane] = keep[lane];
            kval[blockIdx.x * 10 + lane] = keepv[lane];
        }
    }
}

// ------------------------- sparse hidden_h -------------------------
#define FXSCALE 1099511627776.f
#define FXINV   (1.0 / 1099511627776.0)

__global__ void scatter_hidh(const int* __restrict__ kidx, const float* __restrict__ kval,
                             const float* __restrict__ hsh, long long* __restrict__ hacc)
{
    int gid = blockIdx.x * 256 + threadIdx.x;
    if (gid >= N_ * 10 * H_) return;
    int e = gid >> 7, h = gid & 127;
    int row = e / 10;
    int col = kidx[e];
    float prod = kval[e] * hsh[row * H_ + h];
    long long q = llrintf(prod * FXSCALE);
    atomicAdd((unsigned long long*)&hacc[(size_t)col * H_ + h], (unsigned long long)q);
}

__global__ void convert_hidh(const long long* __restrict__ hacc,
                             const int* __restrict__ cnt, const float* __restrict__ dg,
                             const float* __restrict__ hsh, float* __restrict__ hidH)
{
    int i = blockIdx.x * 256 + threadIdx.x;
    if (i >= N_ * H_) return;
    int c = i >> 7;
    float v = (float)((double)hacc[i] * FXINV);
    if (cnt[c] > 0) v += dg[c] * hsh[i];
    hidH[i] = v;
}

__global__ void final_head(const float* __restrict__ a, const float* __restrict__ b,
                           const float* __restrict__ c, const float* __restrict__ w,
                           const float* __restrict__ bo, float* __restrict__ out)
{
    int row = blockIdx.x * 8 + (threadIdx.x >> 5);
    int lane = threadIdx.x & 31;
    size_t base = (size_t)row * H_;
    float acc = 0.f;
    for (int h = lane; h < H_; h += 32)
        acc += (a[base + h] + b[base + h] + c[base + h]) * w[h];
#pragma unroll
    for (int o = 16; o; o >>= 1) acc += __shfl_xor_sync(0xffffffffu, acc, o);
    if (lane == 0) out[row] = acc + bo[0];
}

// ------------------------- host side -------------------------
static float* g_kpart_ptr;

static void gemm(int TR, int EPI, const float* A, const float* B, float* Cm,
                 int M, int Nn, int K, const float* e1, const float* e2)
{
    dim3 g(Nn / 128, M / 128, 1), blk(256);
    if (TR == 1 && EPI == 1) sgemm128<1, 1><<<g, blk>>>(A, B, Cm, M, Nn, K, K, e1, e2, nullptr);
    else if (TR == 1 && EPI == 2) sgemm128<1, 2><<<g, blk>>>(A, B, Cm, M, Nn, K, K, e1, e2, nullptr);
    else if (TR == 1 && EPI == 3) sgemm128<1, 3><<<g, blk>>>(A, B, Cm, M, Nn, K, K, e1, e2, nullptr);
    else sgemm128<1, 0><<<g, blk>>>(A, B, Cm, M, Nn, K, K, e1, e2, nullptr);
}

static void mm_go(int EPI, const float* A, const float* B, float* Cm,
                  int M, int Nn, const float* e1, const float* e2)
{
    dim3 g(Nn / 128, M / 128);
    if (EPI == 0) mmagemm<0><<<g, 256, MM_SMEM>>>(A, B, Cm, M, Nn, e1, e2);
    else if (EPI == 1) mmagemm<1><<<g, 256, MM_SMEM>>>(A, B, Cm, M, Nn, e1, e2);
    else mmagemm<4><<<g, 256, MM_SMEM>>>(A, B, Cm, M, Nn, e1, e2);
}

static void mm_k(const float* A, const float* B, float* Cm, int M, int K, int S)
{
    int Kchunk = K / S;
    dim3 g(1, M / 128, S);
    mmagemm_k<<<g, 256, MM_SMEM>>>(A, B, g_kpart_ptr, M, 128, K, Kchunk);
    size_t MN = (size_t)M * 128;
    kreduce<<<(int)((MN / 4 + 255) / 256), 256>>>(g_kpart_ptr, S, MN, Cm);
}

template <typename Tp>
static float* symaddr(Tp& sym)
{
    void* p = nullptr;
    cudaGetSymbolAddress(&p, sym);
    return (float*)p;
}

extern "C" void kernel_launch(void* const* d_in, const int* in_sizes, int n_in,
                              void* d_out, int out_size)
{
    const float* x = (const float*)d_in[0];
    const float* cm = (const float*)d_in[1];
    const float* mv = (const float*)d_in[2];
    const float* wih0 = (const float*)d_in[3];
    const float* whh0 = (const float*)d_in[4];
    const float* bih0 = (const float*)d_in[5];
    const float* bhh0 = (const float*)d_in[6];
    const float* wih1 = (const float*)d_in[7];
    const float* whh1 = (const float*)d_in[8];
    const float* bih1 = (const float*)d_in[9];
    const float* bhh1 = (const float*)d_in[10];
    const float* w_ps = (const float*)d_in[11];
    const float* b_ps = (const float*)d_in[12];
    const float* w_hs = (const float*)d_in[13];
    const float* b_hs = (const float*)d_in[14];
    const float* w_ps_fore = (const float*)d_in[15];
    const float* b_ps_fore = (const float*)d_in[16];
    const float* w_hs_fore = (const float*)d_in[17];
    const float* b_hs_fore = (const float*)d_in[18];
    const float* w_ps_back = (const float*)d_in[19];
    const float* b_ps_back = (const float*)d_in[20];
    const float* w_hs_back = (const float*)d_in[21];
    const float* b_hs_back = (const float*)d_in[22];
    const float* w_indi = (const float*)d_in[23];
    const float* b_indi = (const float*)d_in[24];
    const float* w_out = (const float*)d_in[25];
    const float* b_out = (const float*)d_in[26];
    float* out = (float*)d_out;

    float* gx = symaddr(g_gx);
    __nv_bfloat16* out0hi = (__nv_bfloat16*)symaddr(g_out0hi);
    __nv_bfloat16* out0lo = (__nv_bfloat16*)symaddr(g_out0lo);
    float* xh = symaddr(g_xh);
    float* xhT = symaddr(g_xhT);
    float* den = symaddr(g_den);
    float* s2c = symaddr(g_s2c);
    float* s2cT = symaddr(g_s2cT);
    float* hidC = symaddr(g_hidC);
    float* v1 = symaddr(g_v1);
    float* logits = symaddr(g_logits);
    float* hid2 = symaddr(g_hid2);
    float* hid2T = symaddr(g_hid2T);
    float* nx = symaddr(g_nx);
    float* ny = symaddr(g_ny);
    float* c2s = symaddr(g_c2s);
    float* tmp = symaddr(g_tmp);
    float* ps = symaddr(g_ps);
    float* hsh = symaddr(g_hsh);
    float* outps = symaddr(g_outps);
    float* nh = symaddr(g_nh);
    float* dg = symaddr(g_diag);
    float* big = symaddr(g_big);
    int* colcnt = (int*)symaddr(g_colcnt);
    int* kidx = (int*)symaddr(g_kidx);
    float* kval = symaddr(g_kval);
    long long* hacc = (long long*)symaddr(g_hacc);
    float* hidH = symaddr(g_hidH);
    float* hidHT = symaddr(g_hidHT);
    float* v2 = symaddr(g_v2);
    float* nhh = symaddr(g_nhh);
    float* hsi = symaddr(g_hsi);
    float* indi = symaddr(g_indi);
    float* ouths = symaddr(g_ouths);
    float* outindi = symaddr(g_outindi);
    float* part = g_kpart_ptr = symaddr(g_kpart);

    cudaFuncSetAttribute(gru_mma, cudaFuncAttributeMaxDynamicSharedMemorySize, GRU_SMEM);
    cudaFuncSetAttribute(mmagemm<0>, cudaFuncAttributeMaxDynamicSharedMemorySize, MM_SMEM);
    cudaFuncSetAttribute(mmagemm<1>, cudaFuncAttributeMaxDynamicSharedMemorySize, MM_SMEM);
    cudaFuncSetAttribute(mmagemm<4>, cudaFuncAttributeMaxDynamicSharedMemorySize, MM_SMEM);
    cudaFuncSetAttribute(mmagemm_pre, cudaFuncAttributeMaxDynamicSharedMemorySize, MM_SMEM);
    cudaFuncSetAttribute(mmagemm_k, cudaFuncAttributeMaxDynamicSharedMemorySize, MM_SMEM);

    // ---- GRU ----
    gx0_kernel<<<dim3(T_, N_ / 32), G3>>>(x, wih0, bih0, gx);
    gru_mma<<<N_ / 32, 512, GRU_SMEM>>>(gx, whh0, bhh0, nullptr, out0hi, out0lo, 1);
    {
        dim3 g(G3 / 128, (T_ * N_) / 128);
        mmagemm_pre<<<g, 256, MM_SMEM>>>(out0hi, out0lo, wih1, gx, T_ * N_, G3, bih1);
    }
    gru_mma<<<N_ / 32, 512, GRU_SMEM>>>(gx, whh1, bhh1, xh, nullptr, nullptr, 0);

    // ---- predefined-concept branch ----
    colsum_part<<<dim3(C_ / 256, 32), 256>>>(cm, mv, N_, C_, part);
    colsum_reduce<<<C_ / 256, 256>>>(part, 32, C_, den);
    s2c_kernel<<<(N_ * C_) / 256, 256>>>(cm, mv, den, s2c);
    transpose32<<<dim3(C_ / 32, N_ / 32), dim3(32, 8)>>>(s2c, s2cT, N_, C_);
    transpose32<<<dim3(H_ / 32, N_ / 32), dim3(32, 8)>>>(xh, xhT, N_, H_);
    mm_k(s2cT, xhT, hidC, C_, N_, 32);                                  // hidden (HMMA K-loop)
    rownorm<<<C_ / 8, 256>>>(hidC, H_, nullptr, v1, nullptr);
    mm_go(0, hidC, xh, logits, C_, N_, nullptr, nullptr);
    row_softmax<<<C_, 512, N_ * 4>>>(logits, N_, nullptr, nullptr, nullptr);
    mm_k(logits, xhT, hid2, C_, N_, 32);                                // hidden2 (HMMA K-loop)
    rownorm<<<N_ / 8, 256>>>(xh, H_, nx, nullptr, nullptr);
    rownorm<<<C_ / 8, 256>>>(hid2, H_, ny, nullptr, nullptr);
    mm_go(0, xh, hid2, c2s, N_, C_, nullptr, nullptr);
    row_softmax<<<N_, 512, C_ * 4>>>(c2s, C_, nx, ny, v1);
    transpose32<<<dim3(H_ / 32, C_ / 32), dim3(32, 8)>>>(hid2, hid2T, C_, H_);
    mm_k(c2s, hid2T, tmp, N_, C_, 4);                                   // p_shared0 (HMMA K-loop)
    gemm(1, 1, tmp, w_ps, ps, N_, H_, H_, b_ps, nullptr);
    gemm(1, 3, ps, w_ps_back, hsh, N_, H_, H_, b_ps_back, xh);
    gemm(1, 2, ps, w_ps_fore, outps, N_, H_, H_, b_ps_fore, nullptr);

    // ---- hidden-concept branch ----
    rownorm<<<N_ / 8, 256>>>(hsh, H_, nh, nullptr, dg);
    mm_go(4, hsh, hsh, big, N_, N_, nh, nh);
    cudaMemsetAsync(colcnt, 0, N_ * sizeof(int));
    cudaMemsetAsync(hacc, 0, (size_t)N_ * H_ * sizeof(long long));
    topk_store<<<N_, 512>>>(big, colcnt, kidx, kval);
    scatter_hidh<<<(N_ * 10 * H_) / 256, 256>>>(kidx, kval, hsh, hacc);
    convert_hidh<<<(N_ * H_) / 256, 256>>>(hacc, colcnt, dg, hsh, hidH);
    rownorm<<<N_ / 8, 256>>>(hidH, H_, nhh, v2, nullptr);
    mm_go(0, hsh, hidH, big, N_, N_, nullptr, nullptr);
    row_softmax<<<N_, 512, N_ * 4>>>(big, N_, nh, nhh, v2);
    transpose32<<<dim3(H_ / 32, N_ / 32), dim3(32, 8)>>>(hidH, hidHT, N_, H_);
    mm_k(big, hidHT, tmp, N_, N_, 8);                                   // h_si0 (HMMA K-loop)
    gemm(1, 1, tmp, w_hs, hsi, N_, H_, H_, b_hs, nullptr);
    gemm(1, 3, hsi, w_hs_back, indi, N_, H_, H_, b_hs_back, hsh);
    gemm(1, 2, hsi, w_hs_fore, ouths, N_, H_, H_, b_hs_fore, nullptr);
    gemm(1, 2, indi, w_indi, outindi, N_, H_, H_, b_indi, nullptr);

    // ---- head ----
    final_head<<<N_ / 8, 256>>>(outps, ouths, outindi, w_out, b_out, out);
}

// round 17
// speedup vs baseline: 1.0413x; 1.0133x over previous
#include <cuda_runtime.h>
#include <cuda_bf16.h>
#include <math.h>
#include <stdint.h>

#define N_ 4096
#define C_ 512
#define H_ 128
#define T_ 64
#define D_ 20
#define G3 384

typedef unsigned long long u64;

// ------------------------- fast activations -------------------------
__device__ __forceinline__ float fsig_(float x) {
    float e, r;
    asm("ex2.approx.f32 %0, %1;" : "=f"(e) : "f"(-1.4426950408889634f * x));
    asm("rcp.approx.f32 %0, %1;" : "=f"(r) : "f"(1.f + e));
    return r;
}
__device__ __forceinline__ float ftanh_(float x) {
    float e, r;
    asm("ex2.approx.f32 %0, %1;" : "=f"(e) : "f"(2.8853900817779268f * x));
    asm("rcp.approx.f32 %0, %1;" : "=f"(r) : "f"(1.f + e));
    return fmaf(-2.f, r, 1.f);
}

// ------------------------- mma.sync helpers -------------------------
__device__ __forceinline__ uint32_t smem_u32_(const void* p) {
    uint32_t a;
    asm("{ .reg .u64 t; cvta.to.shared.u64 t, %1; cvt.u32.u64 %0, t; }" : "=r"(a) : "l"(p));
    return a;
}
__device__ __forceinline__ void ldsm4_(uint32_t* r, uint32_t a) {
    asm volatile("ldmatrix.sync.aligned.m8n8.x4.shared.b16 {%0,%1,%2,%3}, [%4];"
                 : "=r"(r[0]), "=r"(r[1]), "=r"(r[2]), "=r"(r[3]) : "r"(a));
}
__device__ __forceinline__ void ldsm2_(uint32_t* r, uint32_t a) {
    asm volatile("ldmatrix.sync.aligned.m8n8.x2.shared.b16 {%0,%1}, [%2];"
                 : "=r"(r[0]), "=r"(r[1]) : "r"(a));
}
__device__ __forceinline__ void mma_bf16_(float* d, const uint32_t* a, const uint32_t* b) {
    asm volatile(
        "mma.sync.aligned.m16n8k16.row.col.f32.bf16.bf16.f32 "
        "{%0,%1,%2,%3}, {%4,%5,%6,%7}, {%8,%9}, {%0,%1,%2,%3};"
        : "+f"(d[0]), "+f"(d[1]), "+f"(d[2]), "+f"(d[3])
        : "r"(a[0]), "r"(a[1]), "r"(a[2]), "r"(a[3]), "r"(b[0]), "r"(b[1]));
}

// ------------------------- scratch (device globals) -------------------------
__device__ float g_gx[(size_t)T_ * N_ * G3];
__device__ __nv_bfloat16 g_out0hi[(size_t)T_ * N_ * H_];
__device__ __nv_bfloat16 g_out0lo[(size_t)T_ * N_ * H_];
__device__ float g_xh[N_ * H_];
__device__ float g_xhT[H_ * N_];
__device__ float g_den[C_];
__device__ float g_s2c[(size_t)N_ * C_];
__device__ float g_s2cT[(size_t)C_ * N_];
__device__ float g_hidC[C_ * H_];
__device__ float g_v1[C_];
__device__ float g_logits[(size_t)C_ * N_];
__device__ float g_hid2[C_ * H_];
__device__ float g_hid2T[H_ * C_];
__device__ float g_nx[N_];
__device__ float g_ny[C_];
__device__ float g_c2s[(size_t)N_ * C_];
__device__ float g_tmp[N_ * H_];
__device__ float g_hsh[N_ * H_];
__device__ float g_outps[N_ * H_];
__device__ float g_nh[N_];
__device__ float g_diag[N_];
__device__ float g_big[(size_t)N_ * N_];
__device__ float g_kpart[(size_t)32 * 4096 * H_];
__device__ int   g_colcnt[N_];
__device__ int   g_kidx[N_ * 10];
__device__ float g_kval[N_ * 10];
__device__ long long g_hacc[N_ * H_];
__device__ float g_hidH[N_ * H_];
__device__ float g_hidHT[H_ * N_];
__device__ float g_v2[N_];
__device__ float g_nhh[N_];
__device__ float g_indi[N_ * H_];
__device__ float g_ouths[N_ * H_];
__device__ float g_outindi[N_ * H_];

// ==================== HMMA GRU layer (512 thr / 16 warps, double-buffered h) ====
#define GRU_W_BYTES 98304
#define GRU_HB_STRIDE 136
#define GRU_HB_BYTES (32 * GRU_HB_STRIDE * 2)
#define GRU_SMEM (2 * GRU_W_BYTES + 4 * GRU_HB_BYTES)

__global__ __launch_bounds__(512, 1) void gru_mma(
    const float* __restrict__ gx, const float* __restrict__ whh,
    const float* __restrict__ bhh, float* __restrict__ outF,
    __nv_bfloat16* __restrict__ outHi, __nv_bfloat16* __restrict__ outLo,
    int write_all)
{
    extern __shared__ __align__(16) char gsm[];
    char* Wlo = gsm + GRU_W_BYTES;
    char* Hbase = gsm + 2 * GRU_W_BYTES;
    const int tid = threadIdx.x, lane = tid & 31, wp = tid >> 5;
    const int n0 = blockIdx.x * 32;
    const int jb = wp * 8;

    for (int idx = tid; idx < 384 * 16; idx += 512) {
        int n = idx >> 4, g8 = idx & 15;
        const float* src = whh + n * 128 + g8 * 8;
        float4 v0 = *(const float4*)src;
        float4 v1 = *(const float4*)(src + 4);
        float f[8] = {v0.x, v0.y, v0.z, v0.w, v1.x, v1.y, v1.z, v1.w};
        uint32_t hw[4], lw[4];
#pragma unroll
        for (int q = 0; q < 4; ++q) {
            __nv_bfloat16 h0 = __float2bfloat16(f[2 * q]);
            __nv_bfloat16 h1 = __float2bfloat16(f[2 * q + 1]);
            __nv_bfloat162 hp = __halves2bfloat162(h0, h1);
            __nv_bfloat162 lp = __halves2bfloat162(
                __float2bfloat16(f[2 * q] - __bfloat162float(h0)),
                __float2bfloat16(f[2 * q + 1] - __bfloat162float(h1)));
            hw[q] = *(uint32_t*)&hp;
            lw[q] = *(uint32_t*)&lp;
        }
        int off = n * 256 + ((g8 ^ (n & 7)) << 4);
        *(uint4*)(gsm + off) = make_uint4(hw[0], hw[1], hw[2], hw[3]);
        *(uint4*)(Wlo + off) = make_uint4(lw[0], lw[1], lw[2], lw[3]);
    }
    for (int idx = tid; idx < (4 * GRU_HB_BYTES) / 4; idx += 512)
        ((uint32_t*)Hbase)[idx] = 0;

    const int col0 = jb + 2 * (lane & 3);
    const int rbase = lane >> 2;
    float bR0 = bhh[col0], bR1 = bhh[col0 + 1];
    float bZ0 = bhh[128 + col0], bZ1 = bhh[128 + col0 + 1];
    float bN0 = bhh[256 + col0], bN1 = bhh[256 + col0 + 1];

    const uint32_t sb = smem_u32_(gsm);
    const uint32_t hB = sb + 2 * GRU_W_BYTES;
    const uint32_t aoff = (uint32_t)((lane & 15) * (GRU_HB_STRIDE * 2) + (lane >> 4) * 16);
    const int nRZ = ((lane >> 4) ? 128 + jb : jb) + (lane & 7);
    const uint32_t bRZ_base = sb + nRZ * 256;
    const uint32_t nlowRZ = (uint32_t)(nRZ & 7);
    const int nN = 256 + jb + (lane & 7);
    const uint32_t bN_base = sb + nN * 256;
    const uint32_t nlowN = (uint32_t)(nN & 7);
    const uint32_t ghalf = (uint32_t)((lane >> 3) & 1);

    float hold[4][2];
#pragma unroll
    for (int i = 0; i < 4; ++i) { hold[i][0] = 0.f; hold[i][1] = 0.f; }

    __syncthreads();

    for (int t = 0; t < T_; ++t) {
        const int rb = t & 1;
        const uint32_t aHi = hB + (uint32_t)(rb * 2 * GRU_HB_BYTES);
        const uint32_t aLo = aHi + GRU_HB_BYTES;
        __nv_bfloat16* Whi_w = (__nv_bfloat16*)(Hbase + (rb ^ 1) * 2 * GRU_HB_BYTES);
        __nv_bfloat16* Wlo_w = (__nv_bfloat16*)((char*)Whi_w + GRU_HB_BYTES);

        const float* gbase = gx + ((size_t)t * N_ + n0) * G3;
        float2 gR[4], gZ[4], gN[4];
#pragma unroll
        for (int ridx = 0; ridx < 4; ++ridx) {
            int row = (ridx >> 1) * 16 + (ridx & 1) * 8 + rbase;
            const float* gp = gbase + row * G3 + col0;
            gR[ridx] = *(const float2*)(gp);
            gZ[ridx] = *(const float2*)(gp + 128);
            gN[ridx] = *(const float2*)(gp + 256);
        }

        float acc[2][3][4];
#pragma unroll
        for (int i = 0; i < 2; ++i)
#pragma unroll
            for (int g = 0; g < 3; ++g)
#pragma unroll
                for (int q = 0; q < 4; ++q) acc[i][g][q] = 0.f;

#pragma unroll 2
        for (int kc = 0; kc < 8; ++kc) {
            uint32_t gsw = (uint32_t)(kc * 2);
            uint32_t addrRZ = bRZ_base + (((gsw + ghalf) ^ nlowRZ) << 4);
            uint32_t addrN = bN_base + (((gsw + ghalf) ^ nlowN) << 4);
            uint32_t bhiRZ[4], bloRZ[4], bhiN[2], bloN[2];
            ldsm4_(bhiRZ, addrRZ);
            ldsm4_(bloRZ, addrRZ + GRU_W_BYTES);
            ldsm2_(bhiN, addrN);
            ldsm2_(bloN, addrN + GRU_W_BYTES);
            uint32_t ahi[2][4], alo[2][4];
#pragma unroll
            for (int i = 0; i < 2; ++i) {
                uint32_t aa = aoff + (uint32_t)(i * 16 * GRU_HB_STRIDE * 2 + kc * 32);
                ldsm4_(ahi[i], aHi + aa);
                ldsm4_(alo[i], aLo + aa);
            }
#pragma unroll
            for (int i = 0; i < 2; ++i) {
                mma_bf16_(acc[i][0], ahi[i], bhiRZ);
                mma_bf16_(acc[i][0], alo[i], bhiRZ);
                mma_bf16_(acc[i][0], ahi[i], bloRZ);
                mma_bf16_(acc[i][1], ahi[i], bhiRZ + 2);
                mma_bf16_(acc[i][1], alo[i], bhiRZ + 2);
                mma_bf16_(acc[i][1], ahi[i], bloRZ + 2);
                mma_bf16_(acc[i][2], ahi[i], bhiN);
                mma_bf16_(acc[i][2], alo[i], bhiN);
                mma_bf16_(acc[i][2], ahi[i], bloN);
            }
        }

#pragma unroll
        for (int ridx = 0; ridx < 4; ++ridx) {
            int i = ridx >> 1, q0 = (ridx & 1) * 2;
            int row = (ridx >> 1) * 16 + (ridx & 1) * 8 + rbase;
            float rr0 = fsig_(gR[ridx].x + acc[i][0][q0] + bR0);
            float rr1 = fsig_(gR[ridx].y + acc[i][0][q0 + 1] + bR1);
            float zz0 = fsig_(gZ[ridx].x + acc[i][1][q0] + bZ0);
            float zz1 = fsig_(gZ[ridx].y + acc[i][1][q0 + 1] + bZ1);
            float nc0 = ftanh_(gN[ridx].x + rr0 * (acc[i][2][q0] + bN0));
            float nc1 = ftanh_(gN[ridx].y + rr1 * (acc[i][2][q0 + 1] + bN1));
            float h0 = (1.f - zz0) * nc0 + zz0 * hold[ridx][0];
            float h1 = (1.f - zz1) * nc1 + zz1 * hold[ridx][1];
            hold[ridx][0] = h0; hold[ridx][1] = h1;
            __nv_bfloat16 hh0 = __float2bfloat16(h0);
            __nv_bfloat16 hh1 = __float2bfloat16(h1);
            __nv_bfloat162 hp = __halves2bfloat162(hh0, hh1);
            __nv_bfloat162 lp = __halves2bfloat162(
                __float2bfloat16(h0 - __bfloat162float(hh0)),
                __float2bfloat16(h1 - __bfloat162float(hh1)));
            *(__nv_bfloat162*)&Whi_w[row * GRU_HB_STRIDE + col0] = hp;
            *(__nv_bfloat162*)&Wlo_w[row * GRU_HB_STRIDE + col0] = lp;
            if (write_all) {
                size_t gb = ((size_t)t * N_ + n0 + row) * H_ + col0;
                *(__nv_bfloat162*)&outHi[gb] = hp;
                *(__nv_bfloat162*)&outLo[gb] = lp;
            }
        }
        __syncthreads();
    }
    if (!write_all) {
#pragma unroll
        for (int ridx = 0; ridx < 4; ++ridx) {
            int row = (ridx >> 1) * 16 + (ridx & 1) * 8 + rbase;
            *(float2*)&outF[(size_t)(n0 + row) * H_ + col0] =
                make_float2(hold[ridx][0], hold[ridx][1]);
        }
    }
}

// ==================== HMMA bf16-split GEMMs ====================
#define MM_PAD 136
#define MM_TILE_BYTES (128 * MM_PAD * 2)
#define MM_SMEM (4 * MM_TILE_BYTES)

__device__ __forceinline__ void cvt_split_(float4 v, uint2& hw, uint2& lw) {
    __nv_bfloat16 h0 = __float2bfloat16(v.x), h1 = __float2bfloat16(v.y);
    __nv_bfloat16 h2 = __float2bfloat16(v.z), h3 = __float2bfloat16(v.w);
    __nv_bfloat162 hp0 = __halves2bfloat162(h0, h1);
    __nv_bfloat162 hp1 = __halves2bfloat162(h2, h3);
    __nv_bfloat162 lp0 = __halves2bfloat162(
        __float2bfloat16(v.x - __bfloat162float(h0)),
        __float2bfloat16(v.y - __bfloat162float(h1)));
    __nv_bfloat162 lp1 = __halves2bfloat162(
        __float2bfloat16(v.z - __bfloat162float(h2)),
        __float2bfloat16(v.w - __bfloat162float(h3)));
    hw.x = *(uint32_t*)&hp0; hw.y = *(uint32_t*)&hp1;
    lw.x = *(uint32_t*)&lp0; lw.y = *(uint32_t*)&lp1;
}

// EPI: 0 none ; 1 +bias ; 2 +bias leaky ; 3 aux - (v+bias) ; 4 cos-scale+zdiag
template <int EPI>
__device__ __forceinline__ float mepi_(float v, int row, int col, int Nn,
                                       const float* e1, const float* e2)
{
    if (EPI == 1) v += e1[col];
    if (EPI == 2) { v += e1[col]; v = v > 0.f ? v : 0.01f * v; }
    if (EPI == 3) { v += e1[col]; v = e2[(size_t)row * Nn + col] - v; }
    if (EPI == 4) {
        v = v / fmaxf(e1[row] * e2[col], 1e-12f);
        if (row == col) v = 0.f;
    }
    return v;
}

// compute-only 3-pass mainloop from staged smem (acc[4][4][4] owned by caller)
__device__ __forceinline__ void mm_compute_(uint32_t sb, float acc[4][4][4],
                                            uint32_t aRow, uint32_t bRow)
{
#pragma unroll
    for (int i = 0; i < 4; ++i)
#pragma unroll
        for (int j = 0; j < 4; ++j)
#pragma unroll
            for (int q = 0; q < 4; ++q) acc[i][j][q] = 0.f;
#pragma unroll
    for (int p = 0; p < 3; ++p) {
        const uint32_t aB = sb + (p == 1 ? MM_TILE_BYTES : 0) + aRow;
        const uint32_t bB = sb + 2 * MM_TILE_BYTES + (p == 2 ? MM_TILE_BYTES : 0) + bRow;
#pragma unroll
        for (int k0 = 0; k0 < 128; k0 += 16) {
            uint32_t af[4][4], bf[4][2];
#pragma unroll
            for (int i = 0; i < 4; ++i) ldsm4_(af[i], aB + i * 16 * MM_PAD * 2 + k0 * 2);
#pragma unroll
            for (int j = 0; j < 4; ++j) ldsm2_(bf[j], bB + j * 8 * MM_PAD * 2 + k0 * 2);
#pragma unroll
            for (int i = 0; i < 4; ++i)
#pragma unroll
                for (int j = 0; j < 4; ++j) mma_bf16_(acc[i][j], af[i], bf[j]);
        }
    }
}

template <int EPI>
__device__ __forceinline__ void mm_epilogue_(float acc[4][4][4], float* __restrict__ Cm,
                                             int bm, int bn, int Nn, int m0, int n0,
                                             int lane, const float* e1, const float* e2)
{
    const int tr = lane >> 2, tc = (lane & 3) * 2;
#pragma unroll
    for (int i = 0; i < 4; ++i) {
#pragma unroll
        for (int j = 0; j < 4; ++j) {
            int row = bm + m0 + i * 16 + tr;
            int col = bn + n0 + j * 8 + tc;
            float2 v0, v1;
            v0.x = mepi_<EPI>(acc[i][j][0], row, col, Nn, e1, e2);
            v0.y = mepi_<EPI>(acc[i][j][1], row, col + 1, Nn, e1, e2);
            v1.x = mepi_<EPI>(acc[i][j][2], row + 8, col, Nn, e1, e2);
            v1.y = mepi_<EPI>(acc[i][j][3], row + 8, col + 1, Nn, e1, e2);
            *(float2*)&Cm[(size_t)row * Nn + col] = v0;
            *(float2*)&Cm[(size_t)(row + 8) * Nn + col] = v1;
        }
    }
}

template <int EPI>
__global__ __launch_bounds__(256, 1) void mmagemm(
    const float* __restrict__ A, const float* __restrict__ B, float* __restrict__ Cm,
    int M, int Nn, const float* __restrict__ e1, const float* __restrict__ e2)
{
    extern __shared__ __align__(16) char msm[];
    __nv_bfloat16* Ah = (__nv_bfloat16*)msm;
    __nv_bfloat16* Al = (__nv_bfloat16*)(msm + MM_TILE_BYTES);
    __nv_bfloat16* Bh = (__nv_bfloat16*)(msm + 2 * MM_TILE_BYTES);
    __nv_bfloat16* Bl = (__nv_bfloat16*)(msm + 3 * MM_TILE_BYTES);
    const int tid = threadIdx.x, lane = tid & 31, wid = tid >> 5;
    const int bm = blockIdx.y * 128, bn = blockIdx.x * 128;

    {
        const float* Ab = A + (size_t)bm * 128;
        const float* Bb = B + (size_t)bn * 128;
        for (int idx = tid; idx < 128 * 32; idx += 256) {
            int row = idx >> 5, q = (idx & 31) << 2;
            uint2 hw, lw;
            cvt_split_(*(const float4*)&Ab[row * 128 + q], hw, lw);
            *(uint2*)&Ah[row * MM_PAD + q] = hw;
            *(uint2*)&Al[row * MM_PAD + q] = lw;
            cvt_split_(*(const float4*)&Bb[row * 128 + q], hw, lw);
            *(uint2*)&Bh[row * MM_PAD + q] = hw;
            *(uint2*)&Bl[row * MM_PAD + q] = lw;
        }
    }
    __syncthreads();
    const uint32_t sb = smem_u32_(msm);
    const int m0 = (wid >> 2) * 64, n0 = (wid & 3) * 32;
    const uint32_t aRow = (uint32_t)((m0 + (lane & 15)) * MM_PAD * 2 + (lane >> 4) * 16);
    const uint32_t bRow = (uint32_t)((n0 + (lane & 7)) * MM_PAD * 2 + ((lane >> 3) & 1) * 16);
    float acc[4][4][4];
    mm_compute_(sb, acc, aRow, bRow);
    mm_epilogue_<EPI>(acc, Cm, bm, bn, Nn, m0, n0, lane, e1, e2);
}

// variant: A pre-split (bf16 hi/lo planes), B fp32
__global__ __launch_bounds__(256, 1) void mmagemm_pre(
    const __nv_bfloat16* __restrict__ Ahi_g, const __nv_bfloat16* __restrict__ Alo_g,
    const float* __restrict__ B, float* __restrict__ Cm,
    int M, int Nn, const float* __restrict__ e1)
{
    extern __shared__ __align__(16) char msm[];
    __nv_bfloat16* Ah = (__nv_bfloat16*)msm;
    __nv_bfloat16* Al = (__nv_bfloat16*)(msm + MM_TILE_BYTES);
    __nv_bfloat16* Bh = (__nv_bfloat16*)(msm + 2 * MM_TILE_BYTES);
    __nv_bfloat16* Bl = (__nv_bfloat16*)(msm + 3 * MM_TILE_BYTES);
    const int tid = threadIdx.x, lane = tid & 31, wid = tid >> 5;
    const int bm = blockIdx.y * 128, bn = blockIdx.x * 128;

    for (int idx = tid; idx < 128 * 16; idx += 256) {
        int row = idx >> 4, q = (idx & 15) << 3;
        *(uint4*)&Ah[row * MM_PAD + q] = *(const uint4*)&Ahi_g[((size_t)bm + row) * 128 + q];
        *(uint4*)&Al[row * MM_PAD + q] = *(const uint4*)&Alo_g[((size_t)bm + row) * 128 + q];
    }
    {
        const float* Bb = B + (size_t)bn * 128;
        for (int idx = tid; idx < 128 * 32; idx += 256) {
            int row = idx >> 5, q = (idx & 31) << 2;
            uint2 hw, lw;
            cvt_split_(*(const float4*)&Bb[row * 128 + q], hw, lw);
            *(uint2*)&Bh[row * MM_PAD + q] = hw;
            *(uint2*)&Bl[row * MM_PAD + q] = lw;
        }
    }
    __syncthreads();
    const uint32_t sb = smem_u32_(msm);
    const int m0 = (wid >> 2) * 64, n0 = (wid & 3) * 32;
    const uint32_t aRow = (uint32_t)((m0 + (lane & 15)) * MM_PAD * 2 + (lane >> 4) * 16);
    const uint32_t bRow = (uint32_t)((n0 + (lane & 7)) * MM_PAD * 2 + ((lane >> 3) & 1) * 16);
    float acc[4][4][4];
    mm_compute_(sb, acc, aRow, bRow);
    mm_epilogue_<1>(acc, Cm, bm, bn, Nn, m0, n0, lane, e1, nullptr);
}

// K-loop split-K HMMA NT GEMM
__global__ __launch_bounds__(256, 1) void mmagemm_k(
    const float* __restrict__ A, const float* __restrict__ B, float* __restrict__ part,
    int M, int Nn, int K, int Kchunk)
{
    extern __shared__ __align__(16) char msm[];
    __nv_bfloat16* Ah = (__nv_bfloat16*)msm;
    __nv_bfloat16* Al = (__nv_bfloat16*)(msm + MM_TILE_BYTES);
    __nv_bfloat16* Bh = (__nv_bfloat16*)(msm + 2 * MM_TILE_BYTES);
    __nv_bfloat16* Bl = (__nv_bfloat16*)(msm + 3 * MM_TILE_BYTES);
    const int tid = threadIdx.x, lane = tid & 31, wid = tid >> 5;
    const int bm = blockIdx.y * 128, bn = blockIdx.x * 128;
    const int kb = blockIdx.z * Kchunk;

    const uint32_t sb = smem_u32_(msm);
    const int m0 = (wid >> 2) * 64, n0 = (wid & 3) * 32;
    const uint32_t aRow = (uint32_t)((m0 + (lane & 15)) * MM_PAD * 2 + (lane >> 4) * 16);
    const uint32_t bRow = (uint32_t)((n0 + (lane & 7)) * MM_PAD * 2 + ((lane >> 3) & 1) * 16);

    float acc[4][4][4];
#pragma unroll
    for (int i = 0; i < 4; ++i)
#pragma unroll
        for (int j = 0; j < 4; ++j)
#pragma unroll
            for (int q = 0; q < 4; ++q) acc[i][j][q] = 0.f;

    for (int kc = kb; kc < kb + Kchunk; kc += 128) {
        for (int idx = tid; idx < 128 * 32; idx += 256) {
            int row = idx >> 5, q = (idx & 31) << 2;
            uint2 hw, lw;
            cvt_split_(*(const float4*)&A[(size_t)(bm + row) * K + kc + q], hw, lw);
            *(uint2*)&Ah[row * MM_PAD + q] = hw;
            *(uint2*)&Al[row * MM_PAD + q] = lw;
            cvt_split_(*(const float4*)&B[(size_t)(bn + row) * K + kc + q], hw, lw);
            *(uint2*)&Bh[row * MM_PAD + q] = hw;
            *(uint2*)&Bl[row * MM_PAD + q] = lw;
        }
        __syncthreads();
#pragma unroll
        for (int p = 0; p < 3; ++p) {
            const uint32_t aB = sb + (p == 1 ? MM_TILE_BYTES : 0) + aRow;
            const uint32_t bB = sb + 2 * MM_TILE_BYTES + (p == 2 ? MM_TILE_BYTES : 0) + bRow;
#pragma unroll
            for (int k0 = 0; k0 < 128; k0 += 16) {
                uint32_t af[4][4], bf[4][2];
#pragma unroll
                for (int i = 0; i < 4; ++i) ldsm4_(af[i], aB + i * 16 * MM_PAD * 2 + k0 * 2);
#pragma unroll
                for (int j = 0; j < 4; ++j) ldsm2_(bf[j], bB + j * 8 * MM_PAD * 2 + k0 * 2);
#pragma unroll
                for (int i = 0; i < 4; ++i)
#pragma unroll
                    for (int j = 0; j < 4; ++j) mma_bf16_(acc[i][j], af[i], bf[j]);
            }
        }
        __syncthreads();
    }

    float* obase = part + (size_t)blockIdx.z * M * Nn;
    mm_epilogue_<0>(acc, obase, bm, bn, Nn, m0, n0, lane, nullptr, nullptr);
}

// ---- chain3: C1 = A@W1^T + b1 (kept in smem); out1 = aux - (C1@W2^T + b2);
//              out2 = leaky(C1@W3^T + b3). M rows, N=K=128.
__global__ __launch_bounds__(256, 1) void chain3(
    const float* __restrict__ A,
    const float* __restrict__ W1, const float* __restrict__ b1,
    const float* __restrict__ W2, const float* __restrict__ b2,
    const float* __restrict__ aux, float* __restrict__ out1,
    const float* __restrict__ W3, const float* __restrict__ b3,
    float* __restrict__ out2)
{
    extern __shared__ __align__(16) char msm[];
    __nv_bfloat16* Ah = (__nv_bfloat16*)msm;
    __nv_bfloat16* Al = (__nv_bfloat16*)(msm + MM_TILE_BYTES);
    __nv_bfloat16* Bh = (__nv_bfloat16*)(msm + 2 * MM_TILE_BYTES);
    __nv_bfloat16* Bl = (__nv_bfloat16*)(msm + 3 * MM_TILE_BYTES);
    const int tid = threadIdx.x, lane = tid & 31, wid = tid >> 5;
    const int bm = blockIdx.x * 128;

    // stage A tile + W1
    {
        const float* Ab = A + (size_t)bm * 128;
        for (int idx = tid; idx < 128 * 32; idx += 256) {
            int row = idx >> 5, q = (idx & 31) << 2;
            uint2 hw, lw;
            cvt_split_(*(const float4*)&Ab[row * 128 + q], hw, lw);
            *(uint2*)&Ah[row * MM_PAD + q] = hw;
            *(uint2*)&Al[row * MM_PAD + q] = lw;
            cvt_split_(*(const float4*)&W1[row * 128 + q], hw, lw);
            *(uint2*)&Bh[row * MM_PAD + q] = hw;
            *(uint2*)&Bl[row * MM_PAD + q] = lw;
        }
    }
    __syncthreads();
    const uint32_t sb = smem_u32_(msm);
    const int m0 = (wid >> 2) * 64, n0 = (wid & 3) * 32;
    const uint32_t aRow = (uint32_t)((m0 + (lane & 15)) * MM_PAD * 2 + (lane >> 4) * 16);
    const uint32_t bRow = (uint32_t)((n0 + (lane & 7)) * MM_PAD * 2 + ((lane >> 3) & 1) * 16);
    const int tr = lane >> 2, tc = (lane & 3) * 2;

    float acc[4][4][4];
    mm_compute_(sb, acc, aRow, bRow);
    __syncthreads();   // all reads of Ah/Al done

    // store C1 = acc + b1 into Ah/Al (split), stage W2 into Bh/Bl
#pragma unroll
    for (int i = 0; i < 4; ++i) {
#pragma unroll
        for (int j = 0; j < 4; ++j) {
            int rl = m0 + i * 16 + tr;
            int col = n0 + j * 8 + tc;
#pragma unroll
            for (int h = 0; h < 2; ++h) {
                int row = rl + h * 8;
                float v0 = acc[i][j][h * 2] + b1[col];
                float v1 = acc[i][j][h * 2 + 1] + b1[col + 1];
                __nv_bfloat16 h0 = __float2bfloat16(v0);
                __nv_bfloat16 h1 = __float2bfloat16(v1);
                __nv_bfloat162 hp = __halves2bfloat162(h0, h1);
                __nv_bfloat162 lp = __halves2bfloat162(
                    __float2bfloat16(v0 - __bfloat162float(h0)),
                    __float2bfloat16(v1 - __bfloat162float(h1)));
                *(__nv_bfloat162*)&Ah[row * MM_PAD + col] = hp;
                *(__nv_bfloat162*)&Al[row * MM_PAD + col] = lp;
            }
        }
    }
    for (int idx = tid; idx < 128 * 32; idx += 256) {
        int row = idx >> 5, q = (idx & 31) << 2;
        uint2 hw, lw;
        cvt_split_(*(const float4*)&W2[row * 128 + q], hw, lw);
        *(uint2*)&Bh[row * MM_PAD + q] = hw;
        *(uint2*)&Bl[row * MM_PAD + q] = lw;
    }
    __syncthreads();

    mm_compute_(sb, acc, aRow, bRow);
    mm_epilogue_<3>(acc, out1, bm, 0, 128, m0, n0, lane, b2, aux);
    __syncthreads();   // Bh/Bl reads done

    for (int idx = tid; idx < 128 * 32; idx += 256) {
        int row = idx >> 5, q = (idx & 31) << 2;
        uint2 hw, lw;
        cvt_split_(*(const float4*)&W3[row * 128 + q], hw, lw);
        *(uint2*)&Bh[row * MM_PAD + q] = hw;
        *(uint2*)&Bl[row * MM_PAD + q] = lw;
    }
    __syncthreads();

    mm_compute_(sb, acc, aRow, bRow);
    mm_epilogue_<2>(acc, out2, bm, 0, 128, m0, n0, lane, b3, nullptr);
}

__global__ void kreduce(const float* __restrict__ part, int S, size_t MN,
                        float* __restrict__ out)
{
    size_t i4 = ((size_t)blockIdx.x * 256 + threadIdx.x) * 4;
    if (i4 >= MN) return;
    float4 s = *(const float4*)&part[i4];
    for (int z = 1; z < S; ++z) {
        float4 v = *(const float4*)&part[(size_t)z * MN + i4];
        s.x += v.x; s.y += v.y; s.z += v.z; s.w += v.w;
    }
    *(float4*)&out[i4] = s;
}

// ------------------------- tiled transpose -------------------------
__global__ void transpose32(const float* __restrict__ in, float* __restrict__ out,
                            int rows, int cols)
{
    __shared__ float t[32][33];
    int c0 = blockIdx.x * 32, r0 = blockIdx.y * 32;
    int tx = threadIdx.x, ty = threadIdx.y;
    for (int i = ty; i < 32; i += 8)
        t[i][tx] = in[(size_t)(r0 + i) * cols + c0 + tx];
    __syncthreads();
    for (int i = ty; i < 32; i += 8)
        out[(size_t)(c0 + i) * rows + r0 + tx] = t[tx][i];
}

// ------------------------- gx0 -------------------------
__global__ void gx0_kernel(const float* __restrict__ x, const float* __restrict__ wih,
                           const float* __restrict__ bih, float* __restrict__ gx)
{
    __shared__ float xs[32 * D_];
    const int t = blockIdx.x;
    const int n0 = blockIdx.y * 32;
    const int g = threadIdx.x;
    for (int idx = g; idx < 32 * D_; idx += G3) {
        int r = idx / D_, d = idx - r * D_;
        xs[idx] = x[(size_t)(n0 + r) * (D_ * T_) + d * T_ + t];
    }
    float wr[D_];
#pragma unroll
    for (int d = 0; d < D_; ++d) wr[d] = wih[g * D_ + d];
    const float b = bih[g];
    __syncthreads();
    for (int r = 0; r < 32; ++r) {
        const float4* xp = (const float4*)&xs[r * D_];
        float acc = b;
#pragma unroll
        for (int q = 0; q < 5; ++q) {
            float4 v = xp[q];
            acc += v.x * wr[q * 4 + 0] + v.y * wr[q * 4 + 1] +
                   v.z * wr[q * 4 + 2] + v.w * wr[q * 4 + 3];
        }
        gx[((size_t)t * N_ + n0 + r) * G3 + g] = acc;
    }
}

// ------------------------- reductions / elementwise -------------------------
__global__ void colsum_part(const float* __restrict__ m, const float* __restrict__ w,
                            int rows, int cols, float* __restrict__ part)
{
    int c = blockIdx.x * 256 + threadIdx.x;
    int chunk = rows / gridDim.y;
    int r0 = blockIdx.y * chunk;
    float acc = 0.f;
    for (int r = r0; r < r0 + chunk; ++r)
        acc += m[(size_t)r * cols + c] * (w ? w[r] : 1.f);
    part[(size_t)blockIdx.y * cols + c] = acc;
}
__global__ void colsum_reduce(const float* __restrict__ part, int nb, int cols,
                              float* __restrict__ out)
{
    int c = blockIdx.x * 256 + threadIdx.x;
    float a = 0.f;
    for (int b = 0; b < nb; ++b) a += part[(size_t)b * cols + c];
    out[c] = a;
}

__global__ void s2c_kernel(const float* __restrict__ cm, const float* __restrict__ mv,
                           const float* __restrict__ den, float* __restrict__ s2c)
{
    int e = blockIdx.x * 256 + threadIdx.x;
    if (e >= N_ * C_) return;
    int i = e >> 9, c = e & (C_ - 1);
    float cv = cm[e];
    s2c[e] = cv * mv[i] / (den[c] * cv + 1.f);
}

__global__ void rownorm(const float* __restrict__ x, int cols,
                        float* __restrict__ nrm, float* __restrict__ vflag,
                        float* __restrict__ dg)
{
    int row = blockIdx.x * 8 + (threadIdx.x >> 5);
    int lane = threadIdx.x & 31;
    const float* p = x + (size_t)row * cols;
    float s = 0.f, q = 0.f;
    for (int c = lane; c < cols; c += 32) { float v = p[c]; s += v; q += v * v; }
#pragma unroll
    for (int o = 16; o; o >>= 1) {
        s += __shfl_xor_sync(0xffffffffu, s, o);
        q += __shfl_xor_sync(0xffffffffu, q, o);
    }
    if (lane == 0) {
        if (nrm) nrm[row] = sqrtf(q);
        if (vflag) vflag[row] = (s != 0.f) ? 1.f : 0.f;
        if (dg) { float d = sqrtf(q) * sqrtf(q); dg[row] = q / fmaxf(d, 1e-12f); }
    }
}

// 512-thread row softmax
__global__ __launch_bounds__(512, 1) void row_softmax(
    float* __restrict__ m, int width,
    const float* __restrict__ rs, const float* __restrict__ cs,
    const float* __restrict__ vm)
{
    extern __shared__ float sv[];
    __shared__ float red[16];
    __shared__ float smx, ssum;
    const int tid = threadIdx.x, lane = tid & 31, wid = tid >> 5;
    const size_t base = (size_t)blockIdx.x * width;
    const float rsv = rs ? rs[blockIdx.x] : 0.f;
    float lmax = -3.0e38f;
    for (int j = tid; j < width; j += 512) {
        float v = m[base + j];
        if (rs) v = v / fmaxf(rsv * cs[j], 1e-12f);
        if (vm && vm[j] == 0.f) v = -3.0e38f;
        sv[j] = v;
        lmax = fmaxf(lmax, v);
    }
#pragma unroll
    for (int o = 16; o; o >>= 1) lmax = fmaxf(lmax, __shfl_xor_sync(0xffffffffu, lmax, o));
    if (lane == 0) red[wid] = lmax;
    __syncthreads();
    if (tid == 0) {
        float v = red[0];
        for (int w = 1; w < 16; ++w) v = fmaxf(v, red[w]);
        smx = v;
    }
    __syncthreads();
    const float mx = smx;
    float lsum = 0.f;
    for (int j = tid; j < width; j += 512) {
        float e = __expf(sv[j] - mx);
        sv[j] = e;
        lsum += e;
    }
#pragma unroll
    for (int o = 16; o; o >>= 1) lsum += __shfl_xor_sync(0xffffffffu, lsum, o);
    if (lane == 0) red[wid] = lsum;
    __syncthreads();
    if (tid == 0) {
        float v = 0.f;
        for (int w = 0; w < 16; ++w) v += red[w];
        ssum = v;
    }
    __syncthreads();
    const float inv = 1.f / ssum;
    for (int j = tid; j < width; j += 512) {
        float o = sv[j] * inv;
        if (vm) o = (vm[j] != 0.f) ? o : 0.f;
        m[base + j] = o;
    }
}

// ------------------------- top-10 store -------------------------
__global__ __launch_bounds__(512, 1) void topk_store(
    const float* __restrict__ m, int* __restrict__ colcnt,
    int* __restrict__ kidx, float* __restrict__ kval)
{
    __shared__ float vals[N_];
    __shared__ float cval[160];
    __shared__ int cidx[160];
    __shared__ int keep[10];
    __shared__ float keepv[10];
    const int tid = threadIdx.x, lane = tid & 31, wid = tid >> 5;
    const size_t base = (size_t)blockIdx.x * N_;

    for (int j = tid; j < N_; j += 512) vals[j] = m[base + j];
    __syncthreads();

    {
        const int cbase = wid * 256 + lane * 8;
        float v[8];
#pragma unroll
        for (int i = 0; i < 8; ++i) v[i] = vals[cbase + i];
        for (int s = 0; s < 10; ++s) {
            float bv = v[0]; int bs = 0;
#pragma unroll
            for (int i = 1; i < 8; ++i)
                if (v[i] > bv) { bv = v[i]; bs = i; }
            int bi = cbase + bs;
#pragma unroll
            for (int o = 16; o; o >>= 1) {
                float ov = __shfl_down_sync(0xffffffffu, bv, o);
                int oi = __shfl_down_sync(0xffffffffu, bi, o);
                if (ov > bv || (ov == bv && oi < bi)) { bv = ov; bi = oi; }
            }
            bv = __shfl_sync(0xffffffffu, bv, 0);
            bi = __shfl_sync(0xffffffffu, bi, 0);
            if (lane == 0) { cval[wid * 10 + s] = bv; cidx[wid * 10 + s] = bi; }
            if (bi >= cbase && bi < cbase + 8) v[bi - cbase] = -3.0e38f;
        }
    }
    __syncthreads();

    if (wid == 0) {
        float v[5]; int gi[5];
#pragma unroll
        for (int i = 0; i < 5; ++i) {
            v[i] = cval[lane * 5 + i];
            gi[i] = cidx[lane * 5 + i];
        }
        for (int s = 0; s < 10; ++s) {
            float bv = v[0]; int bi = gi[0], bs = 0;
#pragma unroll
            for (int i = 1; i < 5; ++i)
                if (v[i] > bv || (v[i] == bv && gi[i] < bi)) { bv = v[i]; bi = gi[i]; bs = i; }
            int slot = lane * 5 + bs;
#pragma unroll
            for (int o = 16; o; o >>= 1) {
                float ov = __shfl_down_sync(0xffffffffu, bv, o);
                int oi = __shfl_down_sync(0xffffffffu, bi, o);
                int os = __shfl_down_sync(0xffffffffu, slot, o);
                if (ov > bv || (ov == bv && oi < bi)) { bv = ov; bi = oi; slot = os; }
            }
            bv = __shfl_sync(0xffffffffu, bv, 0);
            bi = __shfl_sync(0xffffffffu, bi, 0);
            slot = __shfl_sync(0xffffffffu, slot, 0);
            if (lane == 0) { keep[s] = bi; keepv[s] = bv; }
            if (slot >= lane * 5 && slot < lane * 5 + 5) v[slot - lane * 5] = -3.0e38f;
        }
        if (lane < 10) {
            atomicAdd(&colcnt[keep[lane]], 1);
            kidx[blockIdx.x * 10 + lane] = keep[lane];
            kval[blockIdx.x * 10 + lane] = keepv[lane];
        }
    }
}

// ------------------------- sparse hidden_h -------------------------
#define FXSCALE 1099511627776.f
#define FXINV   (1.0 / 1099511627776.0)

__global__ void scatter_hidh(const int* __restrict__ kidx, const float* __restrict__ kval,
                             const float* __restrict__ hsh, long long* __restrict__ hacc)
{
    int gid = blockIdx.x * 256 + threadIdx.x;
    if (gid >= N_ * 10 * H_) return;
    int e = gid >> 7, h = gid & 127;
    int row = e / 10;
    int col = kidx[e];
    float prod = kval[e] * hsh[row * H_ + h];
    long long q = llrintf(prod * FXSCALE);
    atomicAdd((unsigned long long*)&hacc[(size_t)col * H_ + h], (unsigned long long)q);
}

__global__ void convert_hidh(const long long* __restrict__ hacc,
                             const int* __restrict__ cnt, const float* __restrict__ dg,
                             const float* __restrict__ hsh, float* __restrict__ hidH)
{
    int i = blockIdx.x * 256 + threadIdx.x;
    if (i >= N_ * H_) return;
    int c = i >> 7;
    float v = (float)((double)hacc[i] * FXINV);
    if (cnt[c] > 0) v += dg[c] * hsh[i];
    hidH[i] = v;
}

__global__ void final_head(const float* __restrict__ a, const float* __restrict__ b,
                           const float* __restrict__ c, const float* __restrict__ w,
                           const float* __restrict__ bo, float* __restrict__ out)
{
    int row = blockIdx.x * 8 + (threadIdx.x >> 5);
    int lane = threadIdx.x & 31;
    size_t base = (size_t)row * H_;
    float acc = 0.f;
    for (int h = lane; h < H_; h += 32)
        acc += (a[base + h] + b[base + h] + c[base + h]) * w[h];
#pragma unroll
    for (int o = 16; o; o >>= 1) acc += __shfl_xor_sync(0xffffffffu, acc, o);
    if (lane == 0) out[row] = acc + bo[0];
}

// ------------------------- host side -------------------------
static float* g_kpart_ptr;

static void mm_go(int EPI, const float* A, const float* B, float* Cm,
                  int M, int Nn, const float* e1, const float* e2)
{
    dim3 g(Nn / 128, M / 128);
    if (EPI == 0) mmagemm<0><<<g, 256, MM_SMEM>>>(A, B, Cm, M, Nn, e1, e2);
    else if (EPI == 1) mmagemm<1><<<g, 256, MM_SMEM>>>(A, B, Cm, M, Nn, e1, e2);
    else if (EPI == 2) mmagemm<2><<<g, 256, MM_SMEM>>>(A, B, Cm, M, Nn, e1, e2);
    else mmagemm<4><<<g, 256, MM_SMEM>>>(A, B, Cm, M, Nn, e1, e2);
}

static void mm_k(const float* A, const float* B, float* Cm, int M, int K, int S)
{
    int Kchunk = K / S;
    dim3 g(1, M / 128, S);
    mmagemm_k<<<g, 256, MM_SMEM>>>(A, B, g_kpart_ptr, M, 128, K, Kchunk);
    size_t MN = (size_t)M * 128;
    kreduce<<<(int)((MN / 4 + 255) / 256), 256>>>(g_kpart_ptr, S, MN, Cm);
}

template <typename Tp>
static float* symaddr(Tp& sym)
{
    void* p = nullptr;
    cudaGetSymbolAddress(&p, sym);
    return (float*)p;
}

extern "C" void kernel_launch(void* const* d_in, const int* in_sizes, int n_in,
                              void* d_out, int out_size)
{
    const float* x = (const float*)d_in[0];
    const float* cm = (const float*)d_in[1];
    const float* mv = (const float*)d_in[2];
    const float* wih0 = (const float*)d_in[3];
    const float* whh0 = (const float*)d_in[4];
    const float* bih0 = (const float*)d_in[5];
    const float* bhh0 = (const float*)d_in[6];
    const float* wih1 = (const float*)d_in[7];
    const float* whh1 = (const float*)d_in[8];
    const float* bih1 = (const float*)d_in[9];
    const float* bhh1 = (const float*)d_in[10];
    const float* w_ps = (const float*)d_in[11];
    const float* b_ps = (const float*)d_in[12];
    const float* w_hs = (const float*)d_in[13];
    const float* b_hs = (const float*)d_in[14];
    const float* w_ps_fore = (const float*)d_in[15];
    const float* b_ps_fore = (const float*)d_in[16];
    const float* w_hs_fore = (const float*)d_in[17];
    const float* b_hs_fore = (const float*)d_in[18];
    const float* w_ps_back = (const float*)d_in[19];
    const float* b_ps_back = (const float*)d_in[20];
    const float* w_hs_back = (const float*)d_in[21];
    const float* b_hs_back = (const float*)d_in[22];
    const float* w_indi = (const float*)d_in[23];
    const float* b_indi = (const float*)d_in[24];
    const float* w_out = (const float*)d_in[25];
    const float* b_out = (const float*)d_in[26];
    float* out = (float*)d_out;

    float* gx = symaddr(g_gx);
    __nv_bfloat16* out0hi = (__nv_bfloat16*)symaddr(g_out0hi);
    __nv_bfloat16* out0lo = (__nv_bfloat16*)symaddr(g_out0lo);
    float* xh = symaddr(g_xh);
    float* xhT = symaddr(g_xhT);
    float* den = symaddr(g_den);
    float* s2c = symaddr(g_s2c);
    float* s2cT = symaddr(g_s2cT);
    float* hidC = symaddr(g_hidC);
    float* v1 = symaddr(g_v1);
    float* logits = symaddr(g_logits);
    float* hid2 = symaddr(g_hid2);
    float* hid2T = symaddr(g_hid2T);
    float* nx = symaddr(g_nx);
    float* ny = symaddr(g_ny);
    float* c2s = symaddr(g_c2s);
    float* tmp = symaddr(g_tmp);
    float* hsh = symaddr(g_hsh);
    float* outps = symaddr(g_outps);
    float* nh = symaddr(g_nh);
    float* dg = symaddr(g_diag);
    float* big = symaddr(g_big);
    int* colcnt = (int*)symaddr(g_colcnt);
    int* kidx = (int*)symaddr(g_kidx);
    float* kval = symaddr(g_kval);
    long long* hacc = (long long*)symaddr(g_hacc);
    float* hidH = symaddr(g_hidH);
    float* hidHT = symaddr(g_hidHT);
    float* v2 = symaddr(g_v2);
    float* nhh = symaddr(g_nhh);
    float* indi = symaddr(g_indi);
    float* ouths = symaddr(g_ouths);
    float* outindi = symaddr(g_outindi);
    float* part = g_kpart_ptr = symaddr(g_kpart);

    cudaFuncSetAttribute(gru_mma, cudaFuncAttributeMaxDynamicSharedMemorySize, GRU_SMEM);
    cudaFuncSetAttribute(mmagemm<0>, cudaFuncAttributeMaxDynamicSharedMemorySize, MM_SMEM);
    cudaFuncSetAttribute(mmagemm<1>, cudaFuncAttributeMaxDynamicSharedMemorySize, MM_SMEM);
    cudaFuncSetAttribute(mmagemm<2>, cudaFuncAttributeMaxDynamicSharedMemorySize, MM_SMEM);
    cudaFuncSetAttribute(mmagemm<4>, cudaFuncAttributeMaxDynamicSharedMemorySize, MM_SMEM);
    cudaFuncSetAttribute(mmagemm_pre, cudaFuncAttributeMaxDynamicSharedMemorySize, MM_SMEM);
    cudaFuncSetAttribute(mmagemm_k, cudaFuncAttributeMaxDynamicSharedMemorySize, MM_SMEM);
    cudaFuncSetAttribute(chain3, cudaFuncAttributeMaxDynamicSharedMemorySize, MM_SMEM);

    // ---- GRU ----
    gx0_kernel<<<dim3(T_, N_ / 32), G3>>>(x, wih0, bih0, gx);
    gru_mma<<<N_ / 32, 512, GRU_SMEM>>>(gx, whh0, bhh0, nullptr, out0hi, out0lo, 1);
    {
        dim3 g(G3 / 128, (T_ * N_) / 128);
        mmagemm_pre<<<g, 256, MM_SMEM>>>(out0hi, out0lo, wih1, gx, T_ * N_, G3, bih1);
    }
    gru_mma<<<N_ / 32, 512, GRU_SMEM>>>(gx, whh1, bhh1, xh, nullptr, nullptr, 0);

    // ---- predefined-concept branch ----
    colsum_part<<<dim3(C_ / 256, 32), 256>>>(cm, mv, N_, C_, part);
    colsum_reduce<<<C_ / 256, 256>>>(part, 32, C_, den);
    s2c_kernel<<<(N_ * C_) / 256, 256>>>(cm, mv, den, s2c);
    transpose32<<<dim3(C_ / 32, N_ / 32), dim3(32, 8)>>>(s2c, s2cT, N_, C_);
    transpose32<<<dim3(H_ / 32, N_ / 32), dim3(32, 8)>>>(xh, xhT, N_, H_);
    mm_k(s2cT, xhT, hidC, C_, N_, 32);
    rownorm<<<C_ / 8, 256>>>(hidC, H_, nullptr, v1, nullptr);
    mm_go(0, hidC, xh, logits, C_, N_, nullptr, nullptr);
    row_softmax<<<C_, 512, N_ * 4>>>(logits, N_, nullptr, nullptr, nullptr);
    mm_k(logits, xhT, hid2, C_, N_, 32);
    rownorm<<<N_ / 8, 256>>>(xh, H_, nx, nullptr, nullptr);
    rownorm<<<C_ / 8, 256>>>(hid2, H_, ny, nullptr, nullptr);
    mm_go(0, xh, hid2, c2s, N_, C_, nullptr, nullptr);
    row_softmax<<<N_, 512, C_ * 4>>>(c2s, C_, nx, ny, v1);
    transpose32<<<dim3(H_ / 32, C_ / 32), dim3(32, 8)>>>(hid2, hid2T, C_, H_);
    mm_k(c2s, hid2T, tmp, N_, C_, 4);
    // ps-chain: ps = tmp@w_ps^T+b_ps (in smem); hsh = xh - (ps@w_ps_back^T+b);
    // outps = leaky(ps@w_ps_fore^T+b)
    chain3<<<N_ / 128, 256, MM_SMEM>>>(tmp, w_ps, b_ps,
                                       w_ps_back, b_ps_back, xh, hsh,
                                       w_ps_fore, b_ps_fore, outps);

    // ---- hidden-concept branch ----
    rownorm<<<N_ / 8, 256>>>(hsh, H_, nh, nullptr, dg);
    mm_go(4, hsh, hsh, big, N_, N_, nh, nh);
    cudaMemsetAsync(colcnt, 0, N_ * sizeof(int));
    cudaMemsetAsync(hacc, 0, (size_t)N_ * H_ * sizeof(long long));
    topk_store<<<N_, 512>>>(big, colcnt, kidx, kval);
    scatter_hidh<<<(N_ * 10 * H_) / 256, 256>>>(kidx, kval, hsh, hacc);
    convert_hidh<<<(N_ * H_) / 256, 256>>>(hacc, colcnt, dg, hsh, hidH);
    rownorm<<<N_ / 8, 256>>>(hidH, H_, nhh, v2, nullptr);
    mm_go(0, hsh, hidH, big, N_, N_, nullptr, nullptr);
    row_softmax<<<N_, 512, N_ * 4>>>(big, N_, nh, nhh, v2);
    transpose32<<<dim3(H_ / 32, N_ / 32), dim3(32, 8)>>>(hidH, hidHT, N_, H_);
    mm_k(big, hidHT, tmp, N_, N_, 8);
    // hs-chain: hsi = tmp@w_hs^T+b_hs (smem); indi = hsh - (hsi@w_hs_back^T+b);
    // ouths = leaky(hsi@w_hs_fore^T+b)
    chain3<<<N_ / 128, 256, MM_SMEM>>>(tmp, w_hs, b_hs,
                                       w_hs_back, b_hs_back, hsh, indi,
                                       w_hs_fore, b_hs_fore, ouths);
    mm_go(2, indi, w_indi, outindi, N_, H_, b_indi, nullptr);

    // ---- head ----
    final_head<<<N_ / 8, 256>>>(outps, ouths, outindi, w_out, b_out, out);
}